// round 7
// baseline (speedup 1.0000x reference)
#include <cuda_runtime.h>
#include <cuda_bf16.h>
#include <math.h>
#include <stdint.h>

// Problem constants
#define BB 4096
#define CC 1000
#define PP 10
#define DD 256
#define NN 10000     // CC*PP
#define EE 160000
#define MARGIN_F (-0.1f)
#define LW_F (0.1f)

// bf16-split GEMM geometry
#define KTOT 768          // [hi | hi | lo] x [hi | lo | hi]
#define LDN 10112         // N padded to 79*128
#define MPAD 10112        // NN padded to 79*128

// HMMA tiling
#define BKK 32
#define LDK 40            // padded row stride in bf16 (80B)
#define KITERS (KTOT / BKK)   // 24
#define STG 3
#define STAGE_BYTES 20480     // A(10240) + B(10240) per stage
#define SMEM_BYTES (STG * STAGE_BYTES)  // 61440

// ---------------- scratch (device globals; no runtime allocation) ----------------
__device__ float g_bufA[MPAD * DD];             // xw scratch (padded rows written, ignored)
__device__ float g_bufB[NN * DD];               // aggregated / x
__device__ __nv_bfloat16 g_xs[MPAD * KTOT];     // GCN input split (pad rows stay 0)
__device__ __nv_bfloat16 g_ws[DD * KTOT];       // weight split
__device__ __nv_bfloat16 g_Abf[BB * KTOT];      // hidden_norm split
__device__ __nv_bfloat16 g_Bbf[LDN * KTOT];     // proto_norm split (pad rows stay 0)
__device__ unsigned long long g_pack[(size_t)BB * CC]; // packed (max, idx)
__device__ unsigned char g_argp[BB * CC];
__device__ float g_disqrt[NN];
__device__ int   g_deg[NN];
__device__ int   g_rowptr[NN + 1];
__device__ int   g_col[EE];
__device__ int   g_cursor[NN];
__device__ float g_s[DD];
__device__ float g_ce_sum;
__device__ int   g_cnt;

// ---------------- helpers ----------------
__device__ __forceinline__ uint32_t smem_to_u32(const void* p) {
    uint32_t a;
    asm("{ .reg .u64 t; cvta.to.shared.u64 t, %1; cvt.u32.u64 %0, t; }" : "=r"(a) : "l"(p));
    return a;
}
__device__ __forceinline__ void cp_async16(uint32_t dst, const void* src) {
    asm volatile("cp.async.cg.shared.global [%0], [%1], 16;" :: "r"(dst), "l"(src) : "memory");
}
__device__ __forceinline__ void cp_commit() {
    asm volatile("cp.async.commit_group;" ::: "memory");
}
__device__ __forceinline__ void cp_wait1() {
    asm volatile("cp.async.wait_group 1;" ::: "memory");
}
__device__ __forceinline__ void ldm_x4(uint32_t& r0, uint32_t& r1, uint32_t& r2, uint32_t& r3,
                                       uint32_t addr) {
    asm volatile("ldmatrix.sync.aligned.m8n8.x4.shared.b16 {%0,%1,%2,%3}, [%4];"
                 : "=r"(r0), "=r"(r1), "=r"(r2), "=r"(r3) : "r"(addr));
}
__device__ __forceinline__ void mma16816(float* d, const uint32_t* a, const uint32_t* b) {
    asm volatile(
        "mma.sync.aligned.m16n8k16.row.col.f32.bf16.bf16.f32 "
        "{%0,%1,%2,%3}, {%4,%5,%6,%7}, {%8,%9}, {%0,%1,%2,%3};"
        : "+f"(d[0]), "+f"(d[1]), "+f"(d[2]), "+f"(d[3])
        : "r"(a[0]), "r"(a[1]), "r"(a[2]), "r"(a[3]), "r"(b[0]), "r"(b[1]));
}
__device__ __forceinline__ unsigned int f2sortable(float f) {
    unsigned int b = __float_as_uint(f);
    return (b & 0x80000000u) ? ~b : (b | 0x80000000u);
}
__device__ __forceinline__ float sortable2f(unsigned int e) {
    unsigned int b = (e & 0x80000000u) ? (e ^ 0x80000000u) : ~e;
    return __uint_as_float(b);
}

// ---------------- init ----------------
__global__ void init_kernel(float* out_tail) {
    int i = blockIdx.x * blockDim.x + threadIdx.x;
    if (i < NN) { g_deg[i] = 0; g_cursor[i] = 0; }
    if (i < DD) g_s[i] = 0.0f;
    if (i == 0) { g_ce_sum = 0.0f; g_cnt = 0; }
    if (i < 1 + 2 * NN) out_tail[i] = 0.0f;
    if (i < BB * CC) g_pack[i] = 0ull;
}

// ---------------- degree ----------------
__global__ void deg_kernel(const int* __restrict__ ei) {
    int e = blockIdx.x * blockDim.x + threadIdx.x;
    if (e < EE) atomicAdd(&g_deg[ei[EE + e]], 1);
}

__global__ void disqrt_kernel() {
    int n = blockIdx.x * blockDim.x + threadIdx.x;
    if (n < NN) {
        float x = (float)(g_deg[n] + 1);
        float r = rsqrtf(x);
        r = r * (1.5f - 0.5f * x * r * r);
        g_disqrt[n] = r;
    }
}

// ---------------- exclusive scan ----------------
__global__ void scan_kernel() {
    const int T = 1024;
    const int CH = (NN + T - 1) / T;
    __shared__ int part[T];
    int t = threadIdx.x;
    int base = t * CH;
    int s = 0;
    for (int i = 0; i < CH; i++) {
        int idx = base + i;
        if (idx < NN) s += g_deg[idx];
    }
    part[t] = s;
    __syncthreads();
    for (int off = 1; off < T; off <<= 1) {
        int add = (t >= off) ? part[t - off] : 0;
        __syncthreads();
        part[t] += add;
        __syncthreads();
    }
    if (t == 0) g_rowptr[NN] = part[T - 1];
    int prefix = (t > 0) ? part[t - 1] : 0;
    for (int i = 0; i < CH; i++) {
        int idx = base + i;
        if (idx < NN) { g_rowptr[idx] = prefix; prefix += g_deg[idx]; }
    }
}

__global__ void scatter_kernel(const int* __restrict__ ei) {
    int e = blockIdx.x * blockDim.x + threadIdx.x;
    if (e < EE) {
        int d = ei[EE + e];
        int pos = g_rowptr[d] + atomicAdd(&g_cursor[d], 1);
        g_col[pos] = ei[e];
    }
}

__global__ void sort_kernel() {
    int n = blockIdx.x * blockDim.x + threadIdx.x;
    if (n >= NN) return;
    int beg = g_rowptr[n], end = g_rowptr[n + 1];
    for (int i = beg + 1; i < end; i++) {
        int key = g_col[i];
        int j = i - 1;
        while (j >= beg && g_col[j] > key) { g_col[j + 1] = g_col[j]; j--; }
        g_col[j + 1] = key;
    }
}

// ---------------- bf16 split kernels ----------------
// x split: [hi | hi | lo], one block per row
__global__ void split_x_kernel(const float* __restrict__ in, __nv_bfloat16* __restrict__ outp) {
    int r = blockIdx.x;
    int t = threadIdx.x;
    float v = in[(size_t)r * DD + t];
    __nv_bfloat16 hi = __float2bfloat16(v);
    __nv_bfloat16 lo = __float2bfloat16(v - __bfloat162float(hi));
    size_t base = (size_t)r * KTOT;
    outp[base + t] = hi;
    outp[base + DD + t] = hi;
    outp[base + 2 * DD + t] = lo;
}

// w split (with transpose): B rows = output columns n; [hi | lo | hi]
__global__ void split_w_kernel(const float* __restrict__ w, __nv_bfloat16* __restrict__ outp) {
    int n = blockIdx.x;   // output col
    int k = threadIdx.x;  // input dim
    float v = w[(size_t)k * DD + n];
    __nv_bfloat16 hi = __float2bfloat16(v);
    __nv_bfloat16 lo = __float2bfloat16(v - __bfloat162float(hi));
    size_t base = (size_t)n * KTOT;
    outp[base + k] = hi;
    outp[base + DD + k] = lo;
    outp[base + 2 * DD + k] = hi;
}

// ---------------- row L2 normalize + bf16 split ----------------
__global__ void norm_split_kernel(const float* __restrict__ in,
                                  __nv_bfloat16* __restrict__ outp,
                                  int hi2_off, int lo_off, int accum_s) {
    int r = blockIdx.x;
    int t = threadIdx.x;
    float v = in[(size_t)r * DD + t];
    __shared__ float sh[DD];
    sh[t] = v * v;
    __syncthreads();
    for (int off = 128; off > 0; off >>= 1) {
        if (t < off) sh[t] += sh[t + off];
        __syncthreads();
    }
    float nrm = sqrtf(sh[0]);
    float val = v / fmaxf(nrm, 1e-12f);
    __nv_bfloat16 hi = __float2bfloat16(val);
    __nv_bfloat16 lo = __float2bfloat16(val - __bfloat162float(hi));
    size_t base = (size_t)r * KTOT;
    outp[base + t] = hi;
    outp[base + hi2_off + t] = hi;
    outp[base + lo_off + t] = lo;
    if (accum_s) atomicAdd(&g_s[t], val);
}

// ---------------- bf16 HMMA NT GEMM, K=768, CTA tile 128x128, 3-stage pipeline ------
// MODE 0: store fp32 C (ldc), MODE 1: fused per-class(10) max -> packed uint64
template <int MODE>
__global__ __launch_bounds__(256) void hmma_nt(const __nv_bfloat16* __restrict__ A,
                                               const __nv_bfloat16* __restrict__ B,
                                               float* __restrict__ C,
                                               unsigned long long* __restrict__ pack,
                                               int ldc) {
    extern __shared__ char smem[];
    const uint32_t smem_base = smem_to_u32(smem);

    const int tid = threadIdx.x;
    const int wid = tid >> 5;
    const int lane = tid & 31;
    const int bm = blockIdx.y * 128;
    const int bn = blockIdx.x * 128;

    const int wm = (wid & 3) * 32;   // warp m offset
    const int wn = (wid >> 2) * 64;  // warp n offset

    // copy indices: 512 16B-chunks per matrix tile, 2 per thread
    const int r0c = tid >> 2;        // 0..63
    const int c0c = (tid & 3) * 8;   // bf16 col offset (0,8,16,24)

    float acc[2][8][4];
#pragma unroll
    for (int mt = 0; mt < 2; mt++)
#pragma unroll
        for (int nt = 0; nt < 8; nt++)
#pragma unroll
            for (int e = 0; e < 4; e++) acc[mt][nt][e] = 0.0f;

    // stage load helper (issued inline)
#define ISSUE_STAGE(slot, kb_idx) do {                                              \
        uint32_t aB = smem_base + (slot) * STAGE_BYTES;                             \
        uint32_t bB = aB + 10240;                                                   \
        int k0 = (kb_idx) * BKK;                                                    \
        _Pragma("unroll")                                                           \
        for (int q = 0; q < 2; q++) {                                               \
            int row = r0c + q * 64;                                                 \
            cp_async16(aB + (uint32_t)(row * LDK + c0c) * 2,                        \
                       &A[(size_t)(bm + row) * KTOT + k0 + c0c]);                   \
            cp_async16(bB + (uint32_t)(row * LDK + c0c) * 2,                        \
                       &B[(size_t)(bn + row) * KTOT + k0 + c0c]);                   \
        }                                                                           \
    } while (0)

    // preload stages 0..STG-2
#pragma unroll
    for (int s = 0; s < STG - 1; s++) {
        ISSUE_STAGE(s, s);
        cp_commit();
    }

    for (int kb = 0; kb < KITERS; kb++) {
        if (kb + STG - 1 < KITERS) {
            ISSUE_STAGE((kb + STG - 1) % STG, kb + STG - 1);
        }
        cp_commit();         // exactly one group per iteration (maybe empty)
        cp_wait1();          // stage kb resident
        __syncthreads();

        uint32_t aBase = smem_base + (kb % STG) * STAGE_BYTES;
        uint32_t bBase = aBase + 10240;
#pragma unroll
        for (int ks = 0; ks < BKK; ks += 16) {
            uint32_t afr[2][4];
#pragma unroll
            for (int mt = 0; mt < 2; mt++) {
                int r = wm + mt * 16 + (lane & 15);
                int c = ks + 8 * (lane >> 4);
                ldm_x4(afr[mt][0], afr[mt][1], afr[mt][2], afr[mt][3],
                       aBase + (uint32_t)(r * LDK + c) * 2);
            }
            uint32_t bfr[8][2];
#pragma unroll
            for (int bt = 0; bt < 4; bt++) {
                int r = wn + bt * 16 + ((lane >> 4) & 1) * 8 + (lane & 7);
                int c = ks + ((lane >> 3) & 1) * 8;
                ldm_x4(bfr[bt * 2][0], bfr[bt * 2][1], bfr[bt * 2 + 1][0], bfr[bt * 2 + 1][1],
                       bBase + (uint32_t)(r * LDK + c) * 2);
            }
#pragma unroll
            for (int mt = 0; mt < 2; mt++)
#pragma unroll
                for (int nt = 0; nt < 8; nt++)
                    mma16816(acc[mt][nt], afr[mt], bfr[nt]);
        }
        __syncthreads();
    }
#undef ISSUE_STAGE

    if (MODE == 0) {
        // plain fp32 store
#pragma unroll
        for (int mt = 0; mt < 2; mt++) {
            int row0 = bm + wm + mt * 16 + (lane >> 2);
#pragma unroll
            for (int nt = 0; nt < 8; nt++) {
                int col = bn + wn + nt * 8 + 2 * (lane & 3);
                *(float2*)&C[(size_t)row0 * ldc + col] =
                    make_float2(acc[mt][nt][0], acc[mt][nt][1]);
                *(float2*)&C[(size_t)(row0 + 8) * ldc + col] =
                    make_float2(acc[mt][nt][2], acc[mt][nt][3]);
            }
        }
    } else {
        // fused per-class (groups of 10 cols) max + argmax -> packed uint64
        float* sst = (float*)smem;   // 64 x 132 floats staging
        const int lwm = wm & 63;
        int c_lo = bn / PP;
        int c_hi = (bn + 127) / PP;
        if (c_hi > CC - 1) c_hi = CC - 1;
        const int nc = c_hi - c_lo + 1;
#pragma unroll
        for (int half = 0; half < 2; half++) {
            __syncthreads();
            if ((wm < 64) == (half == 0)) {
#pragma unroll
                for (int mt = 0; mt < 2; mt++) {
                    int r0 = lwm + mt * 16 + (lane >> 2);
#pragma unroll
                    for (int nt = 0; nt < 8; nt++) {
                        int col = wn + nt * 8 + 2 * (lane & 3);
                        sst[r0 * 132 + col] = acc[mt][nt][0];
                        sst[r0 * 132 + col + 1] = acc[mt][nt][1];
                        sst[(r0 + 8) * 132 + col] = acc[mt][nt][2];
                        sst[(r0 + 8) * 132 + col + 1] = acc[mt][nt][3];
                    }
                }
            }
            __syncthreads();
            for (int w = tid; w < 64 * nc; w += 256) {
                int r = w / nc;
                int c = c_lo + (w % nc);
                int col0 = c * PP - bn;
                int lo = col0 > 0 ? col0 : 0;
                int hi = col0 + PP < 128 ? col0 + PP : 128;
                float best = -3.402823466e+38f;
                int bj = 0;
                for (int x = lo; x < hi; x++) {
                    float v = sst[r * 132 + x];
                    if (v > best) { best = v; bj = x - col0; }
                }
                unsigned long long pk =
                    ((unsigned long long)f2sortable(best) << 32) | (unsigned int)(15 - bj);
                unsigned long long* dst = &pack[(size_t)(bm + half * 64 + r) * CC + c];
                if (col0 >= 0 && col0 + PP <= 128) *dst = pk;   // interior: exclusive writer
                else atomicMax(dst, pk);                         // straddles tile boundary
            }
        }
    }
}

// ---------------- GCN aggregation + bias + relu ----------------
__global__ void agg_kernel(const float* __restrict__ xw,
                           float* __restrict__ outp,
                           const float* __restrict__ bias) {
    int n = blockIdx.x;
    int d = threadIdx.x;
    float dn = g_disqrt[n];
    float acc = dn * dn * xw[(size_t)n * DD + d];
    int beg = g_rowptr[n], end = g_rowptr[n + 1];
    for (int j = beg; j < end; j++) {
        int s = g_col[j];
        acc += dn * g_disqrt[s] * xw[(size_t)s * DD + d];
    }
    outp[(size_t)n * DD + d] = fmaxf(acc + bias[d], 0.0f);
}

// ---------------- decode packed -> output + argp ----------------
__global__ void decode_kernel(float* __restrict__ out) {
    int i = blockIdx.x * blockDim.x + threadIdx.x;
    if (i >= BB * CC) return;
    unsigned long long pk = g_pack[i];
    float best = sortable2f((unsigned int)(pk >> 32));
    out[i] = 0.5f * (1.0f + best);
    g_argp[i] = (unsigned char)(15u - (unsigned int)(pk & 0xFFFFFFFFull));
}

// ---------------- per-row CE + usage scatter ----------------
__global__ void ce_kernel(const float* __restrict__ out,
                          const int* __restrict__ labels,
                          float* __restrict__ usage_pos,
                          float* __restrict__ usage_neg) {
    int b = blockIdx.x;
    const float* row = out + (size_t)b * CC;
    int t = threadIdx.x;
    __shared__ float smax[256];
    __shared__ int simax[256];
    float bm = -1e30f;
    int bi = 0x7fffffff;
    for (int c = t; c < CC; c += 256) {
        float v = row[c];
        if (v > bm) { bm = v; bi = c; }
    }
    smax[t] = bm; simax[t] = bi;
    __syncthreads();
    for (int off = 128; off > 0; off >>= 1) {
        if (t < off) {
            float v2 = smax[t + off];
            int i2 = simax[t + off];
            if (v2 > smax[t] || (v2 == smax[t] && i2 < simax[t])) {
                smax[t] = v2; simax[t] = i2;
            }
        }
        __syncthreads();
    }
    float rowmax = smax[0];
    int pred = simax[0];
    __shared__ float ssum[256];
    float s = 0.0f;
    for (int c = t; c < CC; c += 256) s += expf(row[c] - rowmax);
    ssum[t] = s;
    __syncthreads();
    for (int off = 128; off > 0; off >>= 1) {
        if (t < off) ssum[t] += ssum[t + off];
        __syncthreads();
    }
    if (t == 0) {
        int lab = labels[b];
        float x_lab = row[lab];
        float lse = rowmax + logf(ssum[0]);
        if ((x_lab - rowmax) > MARGIN_F) {
            atomicAdd(&g_ce_sum, lse - x_lab);
            atomicAdd(&g_cnt, 1);
        }
        atomicAdd(&usage_pos[lab * PP + (int)g_argp[b * CC + lab]], 1.0f);
        if (pred != lab)
            atomicAdd(&usage_neg[pred * PP + (int)g_argp[b * CC + pred]], 1.0f);
    }
}

// ---------------- finalize loss ----------------
__global__ void finalize_kernel(float* __restrict__ out_loss) {
    __shared__ float sh[DD];
    int t = threadIdx.x;
    float v = g_s[t];
    sh[t] = v * v;
    __syncthreads();
    for (int off = 128; off > 0; off >>= 1) {
        if (t < off) sh[t] += sh[t + off];
        __syncthreads();
    }
    if (t == 0) {
        float disp = -sh[0] / ((float)NN * (float)NN);
        int cnt = g_cnt;
        float loss = (cnt == 0) ? 0.0f
                                : (g_ce_sum / (float)(cnt > 1 ? cnt : 1) + LW_F * disp);
        out_loss[0] = loss;
    }
}

// ---------------- launch ----------------
extern "C" void kernel_launch(void* const* d_in, const int* in_sizes, int n_in,
                              void* d_out, int out_size) {
    const float* hidden = (const float*)d_in[0];
    const int* labels = (const int*)d_in[1];
    const int* edge_index = (const int*)d_in[2];
    const float* node_features = (const float*)d_in[3];
    const float* w1 = (const float*)d_in[4];
    const float* b1 = (const float*)d_in[5];
    const float* w2 = (const float*)d_in[6];
    const float* b2 = (const float*)d_in[7];
    float* out = (float*)d_out;

    float* out_loss = out + (size_t)BB * CC;
    float* out_pos = out_loss + 1;
    float* out_neg = out_pos + NN;

    float *p_bufA = 0, *p_bufB = 0;
    __nv_bfloat16 *p_xs = 0, *p_ws = 0, *p_Abf = 0, *p_Bbf = 0;
    unsigned long long* p_pack = 0;
    cudaGetSymbolAddress((void**)&p_bufA, g_bufA);
    cudaGetSymbolAddress((void**)&p_bufB, g_bufB);
    cudaGetSymbolAddress((void**)&p_xs,   g_xs);
    cudaGetSymbolAddress((void**)&p_ws,   g_ws);
    cudaGetSymbolAddress((void**)&p_Abf,  g_Abf);
    cudaGetSymbolAddress((void**)&p_Bbf,  g_Bbf);
    cudaGetSymbolAddress((void**)&p_pack, g_pack);

    cudaFuncSetAttribute(hmma_nt<0>, cudaFuncAttributeMaxDynamicSharedMemorySize, SMEM_BYTES);
    cudaFuncSetAttribute(hmma_nt<1>, cudaFuncAttributeMaxDynamicSharedMemorySize, SMEM_BYTES);

    // graph build + pack init
    init_kernel<<<(BB * CC + 255) / 256, 256>>>(out_loss);
    deg_kernel<<<(EE + 255) / 256, 256>>>(edge_index);
    disqrt_kernel<<<(NN + 255) / 256, 256>>>();
    scan_kernel<<<1, 1024>>>();
    scatter_kernel<<<(EE + 255) / 256, 256>>>(edge_index);
    sort_kernel<<<(NN + 255) / 256, 256>>>();

    // GCN layer 1: xw = x @ w1 (bf16-split HMMA), aggregate + bias + relu
    split_x_kernel<<<NN, DD>>>(node_features, p_xs);
    split_w_kernel<<<DD, DD>>>(w1, p_ws);
    {
        dim3 grid(DD / 128, MPAD / 128);
        hmma_nt<0><<<grid, 256, SMEM_BYTES>>>(p_xs, p_ws, p_bufA, p_pack, DD);
    }
    agg_kernel<<<NN, DD>>>(p_bufA, p_bufB, b1);

    // GCN layer 2
    split_x_kernel<<<NN, DD>>>(p_bufB, p_xs);
    split_w_kernel<<<DD, DD>>>(w2, p_ws);
    {
        dim3 grid(DD / 128, MPAD / 128);
        hmma_nt<0><<<grid, 256, SMEM_BYTES>>>(p_xs, p_ws, p_bufA, p_pack, DD);
    }
    agg_kernel<<<NN, DD>>>(p_bufA, p_bufB, b2);

    // normalize + bf16 split:
    //   protos (B'): [hi | lo | hi]  -> hi2_off=512, lo_off=256 ; accumulate g_s
    //   hidden (A'): [hi | hi | lo]  -> hi2_off=256, lo_off=512
    norm_split_kernel<<<NN, DD>>>(p_bufB, p_Bbf, 512, 256, 1);
    norm_split_kernel<<<BB, DD>>>(hidden, p_Abf, 256, 512, 0);

    // sim GEMM with fused per-class max/argmax
    {
        dim3 grid(LDN / 128, BB / 128);
        hmma_nt<1><<<grid, 256, SMEM_BYTES>>>(p_Abf, p_Bbf, (float*)0, p_pack, 0);
    }

    // decode packed -> output scores + argmax idx
    decode_kernel<<<(BB * CC + 255) / 256, 256>>>(out);

    // CE + usage
    ce_kernel<<<BB, 256>>>(out, labels, out_pos, out_neg);

    // loss
    finalize_kernel<<<1, DD>>>(out_loss);
}

// round 9
// speedup vs baseline: 1.4063x; 1.4063x over previous
#include <cuda_runtime.h>
#include <cuda_bf16.h>
#include <math.h>
#include <stdint.h>

// Problem constants
#define BB 4096
#define CC 1000
#define PP 10
#define DD 256
#define NN 10000     // CC*PP
#define EE 160000
#define MARGIN_F (-0.1f)
#define LW_F (0.1f)

// bf16-split GEMM geometry
#define KTOT 768          // [hi | hi | lo] x [hi | lo | hi]
#define LDN 10112         // N padded to 79*128
#define MPAD 10112        // NN padded to 79*128

// ---------------- scratch (device globals; no runtime allocation) ----------------
__device__ float g_bufA[MPAD * DD];             // xw scratch (padded rows written, ignored)
__device__ float g_bufB[NN * DD];               // aggregated / x
__device__ __nv_bfloat16 g_xs[MPAD * KTOT];     // GCN input split (pad rows stay 0)
__device__ __nv_bfloat16 g_ws[DD * KTOT];       // weight split (transposed)
__device__ __nv_bfloat16 g_Abf[BB * KTOT];      // hidden_norm split
__device__ __nv_bfloat16 g_Bbf[LDN * KTOT];     // proto_norm split (pad rows stay 0)
__device__ float g_sim[(size_t)BB * LDN];       // raw dot products
__device__ unsigned char g_argp[BB * CC];
__device__ float g_disqrt[NN];
__device__ int   g_deg[NN];
__device__ int   g_rowptr[NN + 1];
__device__ int   g_col[EE];
__device__ int   g_cursor[NN];
__device__ float g_s[DD];
__device__ float g_ce_sum;
__device__ int   g_cnt;

// ---------------- helpers ----------------
__device__ __forceinline__ uint32_t smem_to_u32(const void* p) {
    uint32_t a;
    asm("{ .reg .u64 t; cvta.to.shared.u64 t, %1; cvt.u32.u64 %0, t; }" : "=r"(a) : "l"(p));
    return a;
}
__device__ __forceinline__ void cp_async16(uint32_t dst, const void* src) {
    asm volatile("cp.async.cg.shared.global [%0], [%1], 16;" :: "r"(dst), "l"(src) : "memory");
}
__device__ __forceinline__ void cp_commit() {
    asm volatile("cp.async.commit_group;" ::: "memory");
}
__device__ __forceinline__ void cp_wait0() {
    asm volatile("cp.async.wait_group 0;" ::: "memory");
}
__device__ __forceinline__ void ldm_x4(uint32_t& r0, uint32_t& r1, uint32_t& r2, uint32_t& r3,
                                       uint32_t addr) {
    asm volatile("ldmatrix.sync.aligned.m8n8.x4.shared.b16 {%0,%1,%2,%3}, [%4];"
                 : "=r"(r0), "=r"(r1), "=r"(r2), "=r"(r3) : "r"(addr));
}
__device__ __forceinline__ void mma16816(float* d, const uint32_t* a, const uint32_t* b) {
    asm volatile(
        "mma.sync.aligned.m16n8k16.row.col.f32.bf16.bf16.f32 "
        "{%0,%1,%2,%3}, {%4,%5,%6,%7}, {%8,%9}, {%0,%1,%2,%3};"
        : "+f"(d[0]), "+f"(d[1]), "+f"(d[2]), "+f"(d[3])
        : "r"(a[0]), "r"(a[1]), "r"(a[2]), "r"(a[3]), "r"(b[0]), "r"(b[1]));
}

// ---------------- init ----------------
__global__ void init_kernel(float* out_tail) {
    int i = blockIdx.x * blockDim.x + threadIdx.x;
    if (i < NN) { g_deg[i] = 0; g_cursor[i] = 0; }
    if (i < DD) g_s[i] = 0.0f;
    if (i == 0) { g_ce_sum = 0.0f; g_cnt = 0; }
    if (i < 1 + 2 * NN) out_tail[i] = 0.0f;
}

// ---------------- degree ----------------
__global__ void deg_kernel(const int* __restrict__ ei) {
    int e = blockIdx.x * blockDim.x + threadIdx.x;
    if (e < EE) atomicAdd(&g_deg[ei[EE + e]], 1);
}

__global__ void disqrt_kernel() {
    int n = blockIdx.x * blockDim.x + threadIdx.x;
    if (n < NN) {
        float x = (float)(g_deg[n] + 1);
        float r = rsqrtf(x);
        r = r * (1.5f - 0.5f * x * r * r);
        g_disqrt[n] = r;
    }
}

// ---------------- exclusive scan ----------------
__global__ void scan_kernel() {
    const int T = 1024;
    const int CH = (NN + T - 1) / T;
    __shared__ int part[T];
    int t = threadIdx.x;
    int base = t * CH;
    int s = 0;
    for (int i = 0; i < CH; i++) {
        int idx = base + i;
        if (idx < NN) s += g_deg[idx];
    }
    part[t] = s;
    __syncthreads();
    for (int off = 1; off < T; off <<= 1) {
        int add = (t >= off) ? part[t - off] : 0;
        __syncthreads();
        part[t] += add;
        __syncthreads();
    }
    if (t == 0) g_rowptr[NN] = part[T - 1];
    int prefix = (t > 0) ? part[t - 1] : 0;
    for (int i = 0; i < CH; i++) {
        int idx = base + i;
        if (idx < NN) { g_rowptr[idx] = prefix; prefix += g_deg[idx]; }
    }
}

__global__ void scatter_kernel(const int* __restrict__ ei) {
    int e = blockIdx.x * blockDim.x + threadIdx.x;
    if (e < EE) {
        int d = ei[EE + e];
        int pos = g_rowptr[d] + atomicAdd(&g_cursor[d], 1);
        g_col[pos] = ei[e];
    }
}

__global__ void sort_kernel() {
    int n = blockIdx.x * blockDim.x + threadIdx.x;
    if (n >= NN) return;
    int beg = g_rowptr[n], end = g_rowptr[n + 1];
    for (int i = beg + 1; i < end; i++) {
        int key = g_col[i];
        int j = i - 1;
        while (j >= beg && g_col[j] > key) { g_col[j + 1] = g_col[j]; j--; }
        g_col[j + 1] = key;
    }
}

// ---------------- bf16 split kernels ----------------
// x split: [hi | hi | lo], one block per row
__global__ void split_x_kernel(const float* __restrict__ in, __nv_bfloat16* __restrict__ outp) {
    int r = blockIdx.x;
    int t = threadIdx.x;
    float v = in[(size_t)r * DD + t];
    __nv_bfloat16 hi = __float2bfloat16(v);
    __nv_bfloat16 lo = __float2bfloat16(v - __bfloat162float(hi));
    size_t base = (size_t)r * KTOT;
    outp[base + t] = hi;
    outp[base + DD + t] = hi;
    outp[base + 2 * DD + t] = lo;
}

// w split (with transpose): B rows = output columns n; [hi | lo | hi]
__global__ void split_w_kernel(const float* __restrict__ w, __nv_bfloat16* __restrict__ outp) {
    int n = blockIdx.x;   // output col
    int k = threadIdx.x;  // input dim
    float v = w[(size_t)k * DD + n];
    __nv_bfloat16 hi = __float2bfloat16(v);
    __nv_bfloat16 lo = __float2bfloat16(v - __bfloat162float(hi));
    size_t base = (size_t)n * KTOT;
    outp[base + k] = hi;
    outp[base + DD + k] = lo;
    outp[base + 2 * DD + k] = hi;
}

// ---------------- row L2 normalize + bf16 split ----------------
__global__ void norm_split_kernel(const float* __restrict__ in,
                                  __nv_bfloat16* __restrict__ outp,
                                  int hi2_off, int lo_off, int accum_s) {
    int r = blockIdx.x;
    int t = threadIdx.x;
    float v = in[(size_t)r * DD + t];
    __shared__ float sh[DD];
    sh[t] = v * v;
    __syncthreads();
    for (int off = 128; off > 0; off >>= 1) {
        if (t < off) sh[t] += sh[t + off];
        __syncthreads();
    }
    float nrm = sqrtf(sh[0]);
    float val = v / fmaxf(nrm, 1e-12f);
    __nv_bfloat16 hi = __float2bfloat16(val);
    __nv_bfloat16 lo = __float2bfloat16(val - __bfloat162float(hi));
    size_t base = (size_t)r * KTOT;
    outp[base + t] = hi;
    outp[base + hi2_off + t] = hi;
    outp[base + lo_off + t] = lo;
    if (accum_s) atomicAdd(&g_s[t], val);
}

// ---------------- bf16 HMMA sim GEMM (round-6 proven): C[B, LDN] ----------------
#define BKK 32
#define LDK 40   // padded row stride in bf16 (80B) -> conflict-free ldmatrix
#define KITERS (KTOT / BKK)   // 24

__global__ __launch_bounds__(256) void sim_hmma_kernel(const __nv_bfloat16* __restrict__ Abf,
                                                       const __nv_bfloat16* __restrict__ Bbf,
                                                       float* __restrict__ simout) {
    __shared__ __nv_bfloat16 sA[2][128 * LDK];
    __shared__ __nv_bfloat16 sB[2][128 * LDK];

    const int tid = threadIdx.x;
    const int wid = tid >> 5;
    const int lane = tid & 31;
    const int bm = blockIdx.y * 128;
    const int bn = blockIdx.x * 128;

    const int wm = (wid & 3) * 32;   // warp m offset
    const int wn = (wid >> 2) * 64;  // warp n offset

    const uint32_t sA0 = smem_to_u32(&sA[0][0]);
    const uint32_t sA1 = smem_to_u32(&sA[1][0]);
    const uint32_t sB0 = smem_to_u32(&sB[0][0]);
    const uint32_t sB1 = smem_to_u32(&sB[1][0]);

    const int r0c = tid >> 2;          // chunk row (0..63)
    const int c0c = tid & 3;           // chunk col

    float acc[2][8][4];
#pragma unroll
    for (int mt = 0; mt < 2; mt++)
#pragma unroll
        for (int nt = 0; nt < 8; nt++)
#pragma unroll
            for (int e = 0; e < 4; e++) acc[mt][nt][e] = 0.0f;

    {
        const int k0 = 0;
#pragma unroll
        for (int q = 0; q < 2; q++) {
            int row = r0c + q * 64;
            int col = c0c * 8;
            cp_async16(sA0 + (uint32_t)(row * LDK + col) * 2,
                       &Abf[(size_t)(bm + row) * KTOT + k0 + col]);
            cp_async16(sB0 + (uint32_t)(row * LDK + col) * 2,
                       &Bbf[(size_t)(bn + row) * KTOT + k0 + col]);
        }
        cp_commit();
    }

    for (int kb = 0; kb < KITERS; kb++) {
        cp_wait0();
        __syncthreads();
        if (kb + 1 < KITERS) {
            const int k0 = (kb + 1) * BKK;
            uint32_t dA = ((kb + 1) & 1) ? sA1 : sA0;
            uint32_t dB = ((kb + 1) & 1) ? sB1 : sB0;
#pragma unroll
            for (int q = 0; q < 2; q++) {
                int row = r0c + q * 64;
                int col = c0c * 8;
                cp_async16(dA + (uint32_t)(row * LDK + col) * 2,
                           &Abf[(size_t)(bm + row) * KTOT + k0 + col]);
                cp_async16(dB + (uint32_t)(row * LDK + col) * 2,
                           &Bbf[(size_t)(bn + row) * KTOT + k0 + col]);
            }
            cp_commit();
        }
        uint32_t aBase = (kb & 1) ? sA1 : sA0;
        uint32_t bBase = (kb & 1) ? sB1 : sB0;
#pragma unroll
        for (int ks = 0; ks < BKK; ks += 16) {
            uint32_t afr[2][4];
#pragma unroll
            for (int mt = 0; mt < 2; mt++) {
                int r = wm + mt * 16 + (lane & 15);
                int c = ks + 8 * (lane >> 4);
                ldm_x4(afr[mt][0], afr[mt][1], afr[mt][2], afr[mt][3],
                       aBase + (uint32_t)(r * LDK + c) * 2);
            }
            uint32_t bfr[8][2];
#pragma unroll
            for (int bt = 0; bt < 4; bt++) {
                int r = wn + bt * 16 + ((lane >> 4) & 1) * 8 + (lane & 7);
                int c = ks + ((lane >> 3) & 1) * 8;
                ldm_x4(bfr[bt * 2][0], bfr[bt * 2][1], bfr[bt * 2 + 1][0], bfr[bt * 2 + 1][1],
                       bBase + (uint32_t)(r * LDK + c) * 2);
            }
#pragma unroll
            for (int mt = 0; mt < 2; mt++)
#pragma unroll
                for (int nt = 0; nt < 8; nt++)
                    mma16816(acc[mt][nt], afr[mt], bfr[nt]);
        }
        __syncthreads();
    }

#pragma unroll
    for (int mt = 0; mt < 2; mt++) {
        int row0 = bm + wm + mt * 16 + (lane >> 2);
#pragma unroll
        for (int nt = 0; nt < 8; nt++) {
            int col = bn + wn + nt * 8 + 2 * (lane & 3);
            *(float2*)&simout[(size_t)row0 * LDN + col] =
                make_float2(acc[mt][nt][0], acc[mt][nt][1]);
            *(float2*)&simout[(size_t)(row0 + 8) * LDN + col] =
                make_float2(acc[mt][nt][2], acc[mt][nt][3]);
        }
    }
}

// ---------------- GCN HMMA GEMM: C[MPAD, DD] = Xs @ Ws^T (K=768), ldc=DD ----------
__global__ __launch_bounds__(256) void gcn_hmma_kernel(const __nv_bfloat16* __restrict__ Abf,
                                                       const __nv_bfloat16* __restrict__ Bbf,
                                                       float* __restrict__ Cout) {
    __shared__ __nv_bfloat16 sA[2][128 * LDK];
    __shared__ __nv_bfloat16 sB[2][128 * LDK];

    const int tid = threadIdx.x;
    const int wid = tid >> 5;
    const int lane = tid & 31;
    const int bm = blockIdx.y * 128;
    const int bn = blockIdx.x * 128;

    const int wm = (wid & 3) * 32;
    const int wn = (wid >> 2) * 64;

    const uint32_t sA0 = smem_to_u32(&sA[0][0]);
    const uint32_t sA1 = smem_to_u32(&sA[1][0]);
    const uint32_t sB0 = smem_to_u32(&sB[0][0]);
    const uint32_t sB1 = smem_to_u32(&sB[1][0]);

    const int r0c = tid >> 2;
    const int c0c = tid & 3;

    float acc[2][8][4];
#pragma unroll
    for (int mt = 0; mt < 2; mt++)
#pragma unroll
        for (int nt = 0; nt < 8; nt++)
#pragma unroll
            for (int e = 0; e < 4; e++) acc[mt][nt][e] = 0.0f;

    {
#pragma unroll
        for (int q = 0; q < 2; q++) {
            int row = r0c + q * 64;
            int col = c0c * 8;
            cp_async16(sA0 + (uint32_t)(row * LDK + col) * 2,
                       &Abf[(size_t)(bm + row) * KTOT + col]);
            cp_async16(sB0 + (uint32_t)(row * LDK + col) * 2,
                       &Bbf[(size_t)(bn + row) * KTOT + col]);
        }
        cp_commit();
    }

    for (int kb = 0; kb < KITERS; kb++) {
        cp_wait0();
        __syncthreads();
        if (kb + 1 < KITERS) {
            const int k0 = (kb + 1) * BKK;
            uint32_t dA = ((kb + 1) & 1) ? sA1 : sA0;
            uint32_t dB = ((kb + 1) & 1) ? sB1 : sB0;
#pragma unroll
            for (int q = 0; q < 2; q++) {
                int row = r0c + q * 64;
                int col = c0c * 8;
                cp_async16(dA + (uint32_t)(row * LDK + col) * 2,
                           &Abf[(size_t)(bm + row) * KTOT + k0 + col]);
                cp_async16(dB + (uint32_t)(row * LDK + col) * 2,
                           &Bbf[(size_t)(bn + row) * KTOT + k0 + col]);
            }
            cp_commit();
        }
        uint32_t aBase = (kb & 1) ? sA1 : sA0;
        uint32_t bBase = (kb & 1) ? sB1 : sB0;
#pragma unroll
        for (int ks = 0; ks < BKK; ks += 16) {
            uint32_t afr[2][4];
#pragma unroll
            for (int mt = 0; mt < 2; mt++) {
                int r = wm + mt * 16 + (lane & 15);
                int c = ks + 8 * (lane >> 4);
                ldm_x4(afr[mt][0], afr[mt][1], afr[mt][2], afr[mt][3],
                       aBase + (uint32_t)(r * LDK + c) * 2);
            }
            uint32_t bfr[8][2];
#pragma unroll
            for (int bt = 0; bt < 4; bt++) {
                int r = wn + bt * 16 + ((lane >> 4) & 1) * 8 + (lane & 7);
                int c = ks + ((lane >> 3) & 1) * 8;
                ldm_x4(bfr[bt * 2][0], bfr[bt * 2][1], bfr[bt * 2 + 1][0], bfr[bt * 2 + 1][1],
                       bBase + (uint32_t)(r * LDK + c) * 2);
            }
#pragma unroll
            for (int mt = 0; mt < 2; mt++)
#pragma unroll
                for (int nt = 0; nt < 8; nt++)
                    mma16816(acc[mt][nt], afr[mt], bfr[nt]);
        }
        __syncthreads();
    }

#pragma unroll
    for (int mt = 0; mt < 2; mt++) {
        int row0 = bm + wm + mt * 16 + (lane >> 2);
#pragma unroll
        for (int nt = 0; nt < 8; nt++) {
            int col = bn + wn + nt * 8 + 2 * (lane & 3);
            *(float2*)&Cout[(size_t)row0 * DD + col] =
                make_float2(acc[mt][nt][0], acc[mt][nt][1]);
            *(float2*)&Cout[(size_t)(row0 + 8) * DD + col] =
                make_float2(acc[mt][nt][2], acc[mt][nt][3]);
        }
    }
}

// ---------------- GCN aggregation + bias + relu ----------------
__global__ void agg_kernel(const float* __restrict__ xw,
                           float* __restrict__ outp,
                           const float* __restrict__ bias) {
    int n = blockIdx.x;
    int d = threadIdx.x;
    float dn = g_disqrt[n];
    float acc = dn * dn * xw[(size_t)n * DD + d];
    int beg = g_rowptr[n], end = g_rowptr[n + 1];
    for (int j = beg; j < end; j++) {
        int s = g_col[j];
        acc += dn * g_disqrt[s] * xw[(size_t)s * DD + d];
    }
    outp[(size_t)n * DD + d] = fmaxf(acc + bias[d], 0.0f);
}

// ---------------- per-class max over 10 prototypes ----------------
__global__ void reduce_max_kernel(float* __restrict__ out) {
    int i = blockIdx.x * blockDim.x + threadIdx.x;
    if (i >= BB * CC) return;
    int b = i / CC, c = i % CC;
    const float* p = &g_sim[(size_t)b * LDN + c * PP];
    float best = -1e30f;
    int bi = 0;
#pragma unroll
    for (int j = 0; j < PP; j++) {
        float v = p[j];
        if (v > best) { best = v; bi = j; }
    }
    out[i] = 0.5f * (1.0f + best);
    g_argp[i] = (unsigned char)bi;
}

// ---------------- per-row CE + usage scatter ----------------
__global__ void ce_kernel(const float* __restrict__ out,
                          const int* __restrict__ labels,
                          float* __restrict__ usage_pos,
                          float* __restrict__ usage_neg) {
    int b = blockIdx.x;
    const float* row = out + (size_t)b * CC;
    int t = threadIdx.x;
    __shared__ float smax[256];
    __shared__ int simax[256];
    float bm = -1e30f;
    int bi = 0x7fffffff;
    for (int c = t; c < CC; c += 256) {
        float v = row[c];
        if (v > bm) { bm = v; bi = c; }
    }
    smax[t] = bm; simax[t] = bi;
    __syncthreads();
    for (int off = 128; off > 0; off >>= 1) {
        if (t < off) {
            float v2 = smax[t + off];
            int i2 = simax[t + off];
            if (v2 > smax[t] || (v2 == smax[t] && i2 < simax[t])) {
                smax[t] = v2; simax[t] = i2;
            }
        }
        __syncthreads();
    }
    float rowmax = smax[0];
    int pred = simax[0];
    __shared__ float ssum[256];
    float s = 0.0f;
    for (int c = t; c < CC; c += 256) s += expf(row[c] - rowmax);
    ssum[t] = s;
    __syncthreads();
    for (int off = 128; off > 0; off >>= 1) {
        if (t < off) ssum[t] += ssum[t + off];
        __syncthreads();
    }
    if (t == 0) {
        int lab = labels[b];
        float x_lab = row[lab];
        float lse = rowmax + logf(ssum[0]);
        if ((x_lab - rowmax) > MARGIN_F) {
            atomicAdd(&g_ce_sum, lse - x_lab);
            atomicAdd(&g_cnt, 1);
        }
        atomicAdd(&usage_pos[lab * PP + (int)g_argp[b * CC + lab]], 1.0f);
        if (pred != lab)
            atomicAdd(&usage_neg[pred * PP + (int)g_argp[b * CC + pred]], 1.0f);
    }
}

// ---------------- finalize loss ----------------
__global__ void finalize_kernel(float* __restrict__ out_loss) {
    __shared__ float sh[DD];
    int t = threadIdx.x;
    float v = g_s[t];
    sh[t] = v * v;
    __syncthreads();
    for (int off = 128; off > 0; off >>= 1) {
        if (t < off) sh[t] += sh[t + off];
        __syncthreads();
    }
    if (t == 0) {
        float disp = -sh[0] / ((float)NN * (float)NN);
        int cnt = g_cnt;
        float loss = (cnt == 0) ? 0.0f
                                : (g_ce_sum / (float)(cnt > 1 ? cnt : 1) + LW_F * disp);
        out_loss[0] = loss;
    }
}

// ---------------- launch ----------------
extern "C" void kernel_launch(void* const* d_in, const int* in_sizes, int n_in,
                              void* d_out, int out_size) {
    const float* hidden = (const float*)d_in[0];
    const int* labels = (const int*)d_in[1];
    const int* edge_index = (const int*)d_in[2];
    const float* node_features = (const float*)d_in[3];
    const float* w1 = (const float*)d_in[4];
    const float* b1 = (const float*)d_in[5];
    const float* w2 = (const float*)d_in[6];
    const float* b2 = (const float*)d_in[7];
    float* out = (float*)d_out;

    float* out_loss = out + (size_t)BB * CC;
    float* out_pos = out_loss + 1;
    float* out_neg = out_pos + NN;

    float *p_bufA = 0, *p_bufB = 0, *p_sim = 0;
    __nv_bfloat16 *p_xs = 0, *p_ws = 0, *p_Abf = 0, *p_Bbf = 0;
    cudaGetSymbolAddress((void**)&p_bufA, g_bufA);
    cudaGetSymbolAddress((void**)&p_bufB, g_bufB);
    cudaGetSymbolAddress((void**)&p_sim,  g_sim);
    cudaGetSymbolAddress((void**)&p_xs,   g_xs);
    cudaGetSymbolAddress((void**)&p_ws,   g_ws);
    cudaGetSymbolAddress((void**)&p_Abf,  g_Abf);
    cudaGetSymbolAddress((void**)&p_Bbf,  g_Bbf);

    // graph build
    init_kernel<<<(1 + 2 * NN + 255) / 256, 256>>>(out_loss);
    deg_kernel<<<(EE + 255) / 256, 256>>>(edge_index);
    disqrt_kernel<<<(NN + 255) / 256, 256>>>();
    scan_kernel<<<1, 1024>>>();
    scatter_kernel<<<(EE + 255) / 256, 256>>>(edge_index);
    sort_kernel<<<(NN + 255) / 256, 256>>>();

    // GCN layer 1: xw = x @ w1 (bf16-split HMMA), aggregate + bias + relu
    split_x_kernel<<<NN, DD>>>(node_features, p_xs);
    split_w_kernel<<<DD, DD>>>(w1, p_ws);
    {
        dim3 grid(DD / 128, MPAD / 128);
        gcn_hmma_kernel<<<grid, 256>>>(p_xs, p_ws, p_bufA);
    }
    agg_kernel<<<NN, DD>>>(p_bufA, p_bufB, b1);

    // GCN layer 2
    split_x_kernel<<<NN, DD>>>(p_bufB, p_xs);
    split_w_kernel<<<DD, DD>>>(w2, p_ws);
    {
        dim3 grid(DD / 128, MPAD / 128);
        gcn_hmma_kernel<<<grid, 256>>>(p_xs, p_ws, p_bufA);
    }
    agg_kernel<<<NN, DD>>>(p_bufA, p_bufB, b2);

    // normalize + bf16 split:
    //   protos (B'): [hi | lo | hi]  -> hi2_off=512, lo_off=256 ; accumulate g_s
    //   hidden (A'): [hi | hi | lo]  -> hi2_off=256, lo_off=512
    norm_split_kernel<<<NN, DD>>>(p_bufB, p_Bbf, 512, 256, 1);
    norm_split_kernel<<<BB, DD>>>(hidden, p_Abf, 256, 512, 0);

    // tensor-core (HMMA) sim GEMM: g_sim[4096, 10112] = A' @ B'^T
    {
        dim3 grid(LDN / 128, BB / 128);
        sim_hmma_kernel<<<grid, 256>>>(p_Abf, p_Bbf, p_sim);
    }

    // per-class max + argmax
    reduce_max_kernel<<<(BB * CC + 255) / 256, 256>>>(out);

    // CE + usage
    ce_kernel<<<BB, 256>>>(out, labels, out_pos, out_neg);

    // loss
    finalize_kernel<<<1, DD>>>(out_loss);
}

// round 10
// speedup vs baseline: 1.4961x; 1.0638x over previous
#include <cuda_runtime.h>
#include <cuda_bf16.h>
#include <math.h>
#include <stdint.h>

// Problem constants
#define BB 4096
#define CC 1000
#define PP 10
#define DD 256
#define NN 10000     // CC*PP
#define EE 160000
#define MARGIN_F (-0.1f)
#define LW_F (0.1f)

// bf16-split GEMM geometry
#define KTOT 768          // [hi | hi | lo] x [hi | lo | hi]
#define LDN 10112         // N padded to 79*128
#define MPAD 10112        // NN padded to 79*128

// ---------------- scratch (device globals; no runtime allocation) ----------------
__device__ float g_bufA[MPAD * DD];             // xw scratch (padded rows written, ignored)
__device__ float g_bufB[NN * DD];               // aggregated / x
__device__ __nv_bfloat16 g_xs[MPAD * KTOT];     // GCN input split (pad rows stay 0)
__device__ __nv_bfloat16 g_ws[DD * KTOT];       // weight split (transposed)
__device__ __nv_bfloat16 g_Abf[BB * KTOT];      // hidden_norm split
__device__ __nv_bfloat16 g_Bbf[LDN * KTOT];     // proto_norm split (pad rows stay 0)
__device__ unsigned long long g_pack[(size_t)BB * CC]; // packed (sortable max, 15-idx)
__device__ float g_disqrt[NN];
__device__ int   g_deg[NN];
__device__ int   g_rowptr[NN + 1];
__device__ int   g_col[EE];
__device__ int   g_cursor[NN];
__device__ float g_s[DD];
__device__ float g_ce_sum;
__device__ int   g_cnt;

// ---------------- helpers ----------------
__device__ __forceinline__ uint32_t smem_to_u32(const void* p) {
    uint32_t a;
    asm("{ .reg .u64 t; cvta.to.shared.u64 t, %1; cvt.u32.u64 %0, t; }" : "=r"(a) : "l"(p));
    return a;
}
__device__ __forceinline__ void cp_async16(uint32_t dst, const void* src) {
    asm volatile("cp.async.cg.shared.global [%0], [%1], 16;" :: "r"(dst), "l"(src) : "memory");
}
__device__ __forceinline__ void cp_commit() {
    asm volatile("cp.async.commit_group;" ::: "memory");
}
__device__ __forceinline__ void cp_wait0() {
    asm volatile("cp.async.wait_group 0;" ::: "memory");
}
__device__ __forceinline__ void ldm_x4(uint32_t& r0, uint32_t& r1, uint32_t& r2, uint32_t& r3,
                                       uint32_t addr) {
    asm volatile("ldmatrix.sync.aligned.m8n8.x4.shared.b16 {%0,%1,%2,%3}, [%4];"
                 : "=r"(r0), "=r"(r1), "=r"(r2), "=r"(r3) : "r"(addr));
}
__device__ __forceinline__ void mma16816(float* d, const uint32_t* a, const uint32_t* b) {
    asm volatile(
        "mma.sync.aligned.m16n8k16.row.col.f32.bf16.bf16.f32 "
        "{%0,%1,%2,%3}, {%4,%5,%6,%7}, {%8,%9}, {%0,%1,%2,%3};"
        : "+f"(d[0]), "+f"(d[1]), "+f"(d[2]), "+f"(d[3])
        : "r"(a[0]), "r"(a[1]), "r"(a[2]), "r"(a[3]), "r"(b[0]), "r"(b[1]));
}
__device__ __forceinline__ unsigned int f2sortable(float f) {
    unsigned int b = __float_as_uint(f);
    return (b & 0x80000000u) ? ~b : (b | 0x80000000u);
}
__device__ __forceinline__ float sortable2f(unsigned int e) {
    unsigned int b = (e & 0x80000000u) ? (e ^ 0x80000000u) : ~e;
    return __uint_as_float(b);
}

// ---------------- init ----------------
__global__ void init_kernel(float* out_tail) {
    int i = blockIdx.x * blockDim.x + threadIdx.x;
    if (i < NN) { g_deg[i] = 0; g_cursor[i] = 0; }
    if (i < DD) g_s[i] = 0.0f;
    if (i == 0) { g_ce_sum = 0.0f; g_cnt = 0; }
    if (i < 1 + 2 * NN) out_tail[i] = 0.0f;
    if (i < BB * CC) g_pack[i] = 0ull;   // boundary-class atomicMax needs per-call reset
}

// ---------------- degree ----------------
__global__ void deg_kernel(const int* __restrict__ ei) {
    int e = blockIdx.x * blockDim.x + threadIdx.x;
    if (e < EE) atomicAdd(&g_deg[ei[EE + e]], 1);
}

__global__ void disqrt_kernel() {
    int n = blockIdx.x * blockDim.x + threadIdx.x;
    if (n < NN) {
        float x = (float)(g_deg[n] + 1);
        float r = rsqrtf(x);
        r = r * (1.5f - 0.5f * x * r * r);
        g_disqrt[n] = r;
    }
}

// ---------------- exclusive scan ----------------
__global__ void scan_kernel() {
    const int T = 1024;
    const int CH = (NN + T - 1) / T;
    __shared__ int part[T];
    int t = threadIdx.x;
    int base = t * CH;
    int s = 0;
    for (int i = 0; i < CH; i++) {
        int idx = base + i;
        if (idx < NN) s += g_deg[idx];
    }
    part[t] = s;
    __syncthreads();
    for (int off = 1; off < T; off <<= 1) {
        int add = (t >= off) ? part[t - off] : 0;
        __syncthreads();
        part[t] += add;
        __syncthreads();
    }
    if (t == 0) g_rowptr[NN] = part[T - 1];
    int prefix = (t > 0) ? part[t - 1] : 0;
    for (int i = 0; i < CH; i++) {
        int idx = base + i;
        if (idx < NN) { g_rowptr[idx] = prefix; prefix += g_deg[idx]; }
    }
}

__global__ void scatter_kernel(const int* __restrict__ ei) {
    int e = blockIdx.x * blockDim.x + threadIdx.x;
    if (e < EE) {
        int d = ei[EE + e];
        int pos = g_rowptr[d] + atomicAdd(&g_cursor[d], 1);
        g_col[pos] = ei[e];
    }
}

__global__ void sort_kernel() {
    int n = blockIdx.x * blockDim.x + threadIdx.x;
    if (n >= NN) return;
    int beg = g_rowptr[n], end = g_rowptr[n + 1];
    for (int i = beg + 1; i < end; i++) {
        int key = g_col[i];
        int j = i - 1;
        while (j >= beg && g_col[j] > key) { g_col[j + 1] = g_col[j]; j--; }
        g_col[j + 1] = key;
    }
}

// ---------------- bf16 split kernels ----------------
__global__ void split_x_kernel(const float* __restrict__ in, __nv_bfloat16* __restrict__ outp) {
    int r = blockIdx.x;
    int t = threadIdx.x;
    float v = in[(size_t)r * DD + t];
    __nv_bfloat16 hi = __float2bfloat16(v);
    __nv_bfloat16 lo = __float2bfloat16(v - __bfloat162float(hi));
    size_t base = (size_t)r * KTOT;
    outp[base + t] = hi;
    outp[base + DD + t] = hi;
    outp[base + 2 * DD + t] = lo;
}

__global__ void split_w_kernel(const float* __restrict__ w, __nv_bfloat16* __restrict__ outp) {
    int n = blockIdx.x;   // output col
    int k = threadIdx.x;  // input dim
    float v = w[(size_t)k * DD + n];
    __nv_bfloat16 hi = __float2bfloat16(v);
    __nv_bfloat16 lo = __float2bfloat16(v - __bfloat162float(hi));
    size_t base = (size_t)n * KTOT;
    outp[base + k] = hi;
    outp[base + DD + k] = lo;
    outp[base + 2 * DD + k] = hi;
}

// ---------------- row L2 normalize + bf16 split ----------------
__global__ void norm_split_kernel(const float* __restrict__ in,
                                  __nv_bfloat16* __restrict__ outp,
                                  int hi2_off, int lo_off, int accum_s) {
    int r = blockIdx.x;
    int t = threadIdx.x;
    float v = in[(size_t)r * DD + t];
    __shared__ float sh[DD];
    sh[t] = v * v;
    __syncthreads();
    for (int off = 128; off > 0; off >>= 1) {
        if (t < off) sh[t] += sh[t + off];
        __syncthreads();
    }
    float nrm = sqrtf(sh[0]);
    float val = v / fmaxf(nrm, 1e-12f);
    __nv_bfloat16 hi = __float2bfloat16(val);
    __nv_bfloat16 lo = __float2bfloat16(val - __bfloat162float(hi));
    size_t base = (size_t)r * KTOT;
    outp[base + t] = hi;
    outp[base + hi2_off + t] = hi;
    outp[base + lo_off + t] = lo;
    if (accum_s) atomicAdd(&g_s[t], val);
}

// ---------------- bf16 HMMA sim GEMM + fused per-class max -------------------
#define BKK 32
#define LDK 40   // padded row stride in bf16 (80B) -> conflict-free ldmatrix
#define KITERS (KTOT / BKK)   // 24
#define BUF_B 10240           // one 128xLDK bf16 buffer

__global__ __launch_bounds__(256) void sim_hmma_kernel(const __nv_bfloat16* __restrict__ Abf,
                                                       const __nv_bfloat16* __restrict__ Bbf,
                                                       unsigned long long* __restrict__ pack) {
    __shared__ __align__(16) char smem_raw[4 * BUF_B];  // 40960B: 2xA + 2xB; aliased by epilogue

    const int tid = threadIdx.x;
    const int wid = tid >> 5;
    const int lane = tid & 31;
    const int bm = blockIdx.y * 128;
    const int bn = blockIdx.x * 128;

    const int wm = (wid & 3) * 32;   // warp m offset
    const int wn = (wid >> 2) * 64;  // warp n offset

    const uint32_t sA0 = smem_to_u32(smem_raw);
    const uint32_t sA1 = sA0 + BUF_B;
    const uint32_t sB0 = sA0 + 2 * BUF_B;
    const uint32_t sB1 = sA0 + 3 * BUF_B;

    const int r0c = tid >> 2;          // chunk row (0..63)
    const int c0c = tid & 3;           // chunk col

    float acc[2][8][4];
#pragma unroll
    for (int mt = 0; mt < 2; mt++)
#pragma unroll
        for (int nt = 0; nt < 8; nt++)
#pragma unroll
            for (int e = 0; e < 4; e++) acc[mt][nt][e] = 0.0f;

    {
        const int k0 = 0;
#pragma unroll
        for (int q = 0; q < 2; q++) {
            int row = r0c + q * 64;
            int col = c0c * 8;
            cp_async16(sA0 + (uint32_t)(row * LDK + col) * 2,
                       &Abf[(size_t)(bm + row) * KTOT + k0 + col]);
            cp_async16(sB0 + (uint32_t)(row * LDK + col) * 2,
                       &Bbf[(size_t)(bn + row) * KTOT + k0 + col]);
        }
        cp_commit();
    }

    for (int kb = 0; kb < KITERS; kb++) {
        cp_wait0();
        __syncthreads();
        if (kb + 1 < KITERS) {
            const int k0 = (kb + 1) * BKK;
            uint32_t dA = ((kb + 1) & 1) ? sA1 : sA0;
            uint32_t dB = ((kb + 1) & 1) ? sB1 : sB0;
#pragma unroll
            for (int q = 0; q < 2; q++) {
                int row = r0c + q * 64;
                int col = c0c * 8;
                cp_async16(dA + (uint32_t)(row * LDK + col) * 2,
                           &Abf[(size_t)(bm + row) * KTOT + k0 + col]);
                cp_async16(dB + (uint32_t)(row * LDK + col) * 2,
                           &Bbf[(size_t)(bn + row) * KTOT + k0 + col]);
            }
            cp_commit();
        }
        uint32_t aBase = (kb & 1) ? sA1 : sA0;
        uint32_t bBase = (kb & 1) ? sB1 : sB0;
#pragma unroll
        for (int ks = 0; ks < BKK; ks += 16) {
            uint32_t afr[2][4];
#pragma unroll
            for (int mt = 0; mt < 2; mt++) {
                int r = wm + mt * 16 + (lane & 15);
                int c = ks + 8 * (lane >> 4);
                ldm_x4(afr[mt][0], afr[mt][1], afr[mt][2], afr[mt][3],
                       aBase + (uint32_t)(r * LDK + c) * 2);
            }
            uint32_t bfr[8][2];
#pragma unroll
            for (int bt = 0; bt < 4; bt++) {
                int r = wn + bt * 16 + ((lane >> 4) & 1) * 8 + (lane & 7);
                int c = ks + ((lane >> 3) & 1) * 8;
                ldm_x4(bfr[bt * 2][0], bfr[bt * 2][1], bfr[bt * 2 + 1][0], bfr[bt * 2 + 1][1],
                       bBase + (uint32_t)(r * LDK + c) * 2);
            }
#pragma unroll
            for (int mt = 0; mt < 2; mt++)
#pragma unroll
                for (int nt = 0; nt < 8; nt++)
                    mma16816(acc[mt][nt], afr[mt], bfr[nt]);
        }
        __syncthreads();
    }

    // -------- fused epilogue: per-class (groups of PP cols) max + argmax --------
    {
        float* sst = (float*)smem_raw;   // 64 x 132 floats = 33792B staging
        const int lwm = wm & 63;
        int c_lo = bn / PP;
        int c_hi = (bn + 127) / PP;
        if (c_hi > CC - 1) c_hi = CC - 1;
        const int r = tid >> 2;          // 0..63
        const int cstep0 = tid & 3;
#pragma unroll
        for (int half = 0; half < 2; half++) {
            __syncthreads();
            if ((wm < 64) == (half == 0)) {
#pragma unroll
                for (int mt = 0; mt < 2; mt++) {
                    int r0 = lwm + mt * 16 + (lane >> 2);
#pragma unroll
                    for (int nt = 0; nt < 8; nt++) {
                        int col = wn + nt * 8 + 2 * (lane & 3);
                        sst[r0 * 132 + col] = acc[mt][nt][0];
                        sst[r0 * 132 + col + 1] = acc[mt][nt][1];
                        sst[(r0 + 8) * 132 + col] = acc[mt][nt][2];
                        sst[(r0 + 8) * 132 + col + 1] = acc[mt][nt][3];
                    }
                }
            }
            __syncthreads();
            for (int c = c_lo + cstep0; c <= c_hi; c += 4) {
                int col0 = c * PP - bn;
                int lo = col0 > 0 ? col0 : 0;
                int hi = col0 + PP < 128 ? col0 + PP : 128;
                float best = -3.402823466e+38f;
                int bj = 0;
                for (int x = lo; x < hi; x++) {
                    float v = sst[r * 132 + x];
                    if (v > best) { best = v; bj = x - col0; }
                }
                unsigned long long pk =
                    ((unsigned long long)f2sortable(best) << 32) | (unsigned int)(15 - bj);
                unsigned long long* dst = &pack[(size_t)(bm + half * 64 + r) * CC + c];
                if (col0 >= 0 && col0 + PP <= 128) *dst = pk;   // interior: exclusive writer
                else atomicMax(dst, pk);                         // straddles tile boundary
            }
        }
    }
}

// ---------------- GCN HMMA GEMM: C[MPAD, DD] = Xs @ Ws^T (K=768), ldc=DD ----------
__global__ __launch_bounds__(256) void gcn_hmma_kernel(const __nv_bfloat16* __restrict__ Abf,
                                                       const __nv_bfloat16* __restrict__ Bbf,
                                                       float* __restrict__ Cout) {
    __shared__ __nv_bfloat16 sA[2][128 * LDK];
    __shared__ __nv_bfloat16 sB[2][128 * LDK];

    const int tid = threadIdx.x;
    const int wid = tid >> 5;
    const int lane = tid & 31;
    const int bm = blockIdx.y * 128;
    const int bn = blockIdx.x * 128;

    const int wm = (wid & 3) * 32;
    const int wn = (wid >> 2) * 64;

    const uint32_t sA0 = smem_to_u32(&sA[0][0]);
    const uint32_t sA1 = smem_to_u32(&sA[1][0]);
    const uint32_t sB0 = smem_to_u32(&sB[0][0]);
    const uint32_t sB1 = smem_to_u32(&sB[1][0]);

    const int r0c = tid >> 2;
    const int c0c = tid & 3;

    float acc[2][8][4];
#pragma unroll
    for (int mt = 0; mt < 2; mt++)
#pragma unroll
        for (int nt = 0; nt < 8; nt++)
#pragma unroll
            for (int e = 0; e < 4; e++) acc[mt][nt][e] = 0.0f;

    {
#pragma unroll
        for (int q = 0; q < 2; q++) {
            int row = r0c + q * 64;
            int col = c0c * 8;
            cp_async16(sA0 + (uint32_t)(row * LDK + col) * 2,
                       &Abf[(size_t)(bm + row) * KTOT + col]);
            cp_async16(sB0 + (uint32_t)(row * LDK + col) * 2,
                       &Bbf[(size_t)(bn + row) * KTOT + col]);
        }
        cp_commit();
    }

    for (int kb = 0; kb < KITERS; kb++) {
        cp_wait0();
        __syncthreads();
        if (kb + 1 < KITERS) {
            const int k0 = (kb + 1) * BKK;
            uint32_t dA = ((kb + 1) & 1) ? sA1 : sA0;
            uint32_t dB = ((kb + 1) & 1) ? sB1 : sB0;
#pragma unroll
            for (int q = 0; q < 2; q++) {
                int row = r0c + q * 64;
                int col = c0c * 8;
                cp_async16(dA + (uint32_t)(row * LDK + col) * 2,
                           &Abf[(size_t)(bm + row) * KTOT + k0 + col]);
                cp_async16(dB + (uint32_t)(row * LDK + col) * 2,
                           &Bbf[(size_t)(bn + row) * KTOT + k0 + col]);
            }
            cp_commit();
        }
        uint32_t aBase = (kb & 1) ? sA1 : sA0;
        uint32_t bBase = (kb & 1) ? sB1 : sB0;
#pragma unroll
        for (int ks = 0; ks < BKK; ks += 16) {
            uint32_t afr[2][4];
#pragma unroll
            for (int mt = 0; mt < 2; mt++) {
                int r = wm + mt * 16 + (lane & 15);
                int c = ks + 8 * (lane >> 4);
                ldm_x4(afr[mt][0], afr[mt][1], afr[mt][2], afr[mt][3],
                       aBase + (uint32_t)(r * LDK + c) * 2);
            }
            uint32_t bfr[8][2];
#pragma unroll
            for (int bt = 0; bt < 4; bt++) {
                int r = wn + bt * 16 + ((lane >> 4) & 1) * 8 + (lane & 7);
                int c = ks + ((lane >> 3) & 1) * 8;
                ldm_x4(bfr[bt * 2][0], bfr[bt * 2][1], bfr[bt * 2 + 1][0], bfr[bt * 2 + 1][1],
                       bBase + (uint32_t)(r * LDK + c) * 2);
            }
#pragma unroll
            for (int mt = 0; mt < 2; mt++)
#pragma unroll
                for (int nt = 0; nt < 8; nt++)
                    mma16816(acc[mt][nt], afr[mt], bfr[nt]);
        }
        __syncthreads();
    }

#pragma unroll
    for (int mt = 0; mt < 2; mt++) {
        int row0 = bm + wm + mt * 16 + (lane >> 2);
#pragma unroll
        for (int nt = 0; nt < 8; nt++) {
            int col = bn + wn + nt * 8 + 2 * (lane & 3);
            *(float2*)&Cout[(size_t)row0 * DD + col] =
                make_float2(acc[mt][nt][0], acc[mt][nt][1]);
            *(float2*)&Cout[(size_t)(row0 + 8) * DD + col] =
                make_float2(acc[mt][nt][2], acc[mt][nt][3]);
        }
    }
}

// ---------------- GCN aggregation + bias + relu ----------------
__global__ void agg_kernel(const float* __restrict__ xw,
                           float* __restrict__ outp,
                           const float* __restrict__ bias) {
    int n = blockIdx.x;
    int d = threadIdx.x;
    float dn = g_disqrt[n];
    float acc = dn * dn * xw[(size_t)n * DD + d];
    int beg = g_rowptr[n], end = g_rowptr[n + 1];
    for (int j = beg; j < end; j++) {
        int s = g_col[j];
        acc += dn * g_disqrt[s] * xw[(size_t)s * DD + d];
    }
    outp[(size_t)n * DD + d] = fmaxf(acc + bias[d], 0.0f);
}

// ---------------- per-row CE + usage scatter (consumes packed) ----------------
__global__ void ce_kernel(const unsigned long long* __restrict__ pack,
                          float* __restrict__ out,
                          const int* __restrict__ labels,
                          float* __restrict__ usage_pos,
                          float* __restrict__ usage_neg) {
    int b = blockIdx.x;
    const unsigned long long* prow = pack + (size_t)b * CC;
    float* orow = out + (size_t)b * CC;
    int t = threadIdx.x;
    __shared__ float smax[256];
    __shared__ int simax[256];
    float bm = -1e30f;
    int bi = 0x7fffffff;
    for (int c = t; c < CC; c += 256) {
        unsigned long long pk = prow[c];
        float v = 0.5f * (1.0f + sortable2f((unsigned int)(pk >> 32)));
        orow[c] = v;
        if (v > bm) { bm = v; bi = c; }
    }
    smax[t] = bm; simax[t] = bi;
    __syncthreads();
    for (int off = 128; off > 0; off >>= 1) {
        if (t < off) {
            float v2 = smax[t + off];
            int i2 = simax[t + off];
            if (v2 > smax[t] || (v2 == smax[t] && i2 < simax[t])) {
                smax[t] = v2; simax[t] = i2;
            }
        }
        __syncthreads();
    }
    float rowmax = smax[0];
    int pred = simax[0];
    __shared__ float ssum[256];
    float s = 0.0f;
    for (int c = t; c < CC; c += 256) s += expf(orow[c] - rowmax);
    ssum[t] = s;
    __syncthreads();
    for (int off = 128; off > 0; off >>= 1) {
        if (t < off) ssum[t] += ssum[t + off];
        __syncthreads();
    }
    if (t == 0) {
        int lab = labels[b];
        float x_lab = orow[lab];
        float lse = rowmax + logf(ssum[0]);
        if ((x_lab - rowmax) > MARGIN_F) {
            atomicAdd(&g_ce_sum, lse - x_lab);
            atomicAdd(&g_cnt, 1);
        }
        int jl = 15 - (int)(unsigned int)(prow[lab] & 0xFFFFFFFFull);
        atomicAdd(&usage_pos[lab * PP + jl], 1.0f);
        if (pred != lab) {
            int jp = 15 - (int)(unsigned int)(prow[pred] & 0xFFFFFFFFull);
            atomicAdd(&usage_neg[pred * PP + jp], 1.0f);
        }
    }
}

// ---------------- finalize loss ----------------
__global__ void finalize_kernel(float* __restrict__ out_loss) {
    __shared__ float sh[DD];
    int t = threadIdx.x;
    float v = g_s[t];
    sh[t] = v * v;
    __syncthreads();
    for (int off = 128; off > 0; off >>= 1) {
        if (t < off) sh[t] += sh[t + off];
        __syncthreads();
    }
    if (t == 0) {
        float disp = -sh[0] / ((float)NN * (float)NN);
        int cnt = g_cnt;
        float loss = (cnt == 0) ? 0.0f
                                : (g_ce_sum / (float)(cnt > 1 ? cnt : 1) + LW_F * disp);
        out_loss[0] = loss;
    }
}

// ---------------- launch ----------------
extern "C" void kernel_launch(void* const* d_in, const int* in_sizes, int n_in,
                              void* d_out, int out_size) {
    const float* hidden = (const float*)d_in[0];
    const int* labels = (const int*)d_in[1];
    const int* edge_index = (const int*)d_in[2];
    const float* node_features = (const float*)d_in[3];
    const float* w1 = (const float*)d_in[4];
    const float* b1 = (const float*)d_in[5];
    const float* w2 = (const float*)d_in[6];
    const float* b2 = (const float*)d_in[7];
    float* out = (float*)d_out;

    float* out_loss = out + (size_t)BB * CC;
    float* out_pos = out_loss + 1;
    float* out_neg = out_pos + NN;

    float *p_bufA = 0, *p_bufB = 0;
    __nv_bfloat16 *p_xs = 0, *p_ws = 0, *p_Abf = 0, *p_Bbf = 0;
    unsigned long long* p_pack = 0;
    cudaGetSymbolAddress((void**)&p_bufA, g_bufA);
    cudaGetSymbolAddress((void**)&p_bufB, g_bufB);
    cudaGetSymbolAddress((void**)&p_xs,   g_xs);
    cudaGetSymbolAddress((void**)&p_ws,   g_ws);
    cudaGetSymbolAddress((void**)&p_Abf,  g_Abf);
    cudaGetSymbolAddress((void**)&p_Bbf,  g_Bbf);
    cudaGetSymbolAddress((void**)&p_pack, g_pack);

    // graph build + pack reset
    init_kernel<<<(BB * CC + 255) / 256, 256>>>(out_loss);
    deg_kernel<<<(EE + 255) / 256, 256>>>(edge_index);
    disqrt_kernel<<<(NN + 255) / 256, 256>>>();
    scan_kernel<<<1, 1024>>>();
    scatter_kernel<<<(EE + 255) / 256, 256>>>(edge_index);
    sort_kernel<<<(NN + 255) / 256, 256>>>();

    // GCN layer 1: xw = x @ w1 (bf16-split HMMA), aggregate + bias + relu
    split_x_kernel<<<NN, DD>>>(node_features, p_xs);
    split_w_kernel<<<DD, DD>>>(w1, p_ws);
    {
        dim3 grid(DD / 128, MPAD / 128);
        gcn_hmma_kernel<<<grid, 256>>>(p_xs, p_ws, p_bufA);
    }
    agg_kernel<<<NN, DD>>>(p_bufA, p_bufB, b1);

    // GCN layer 2
    split_x_kernel<<<NN, DD>>>(p_bufB, p_xs);
    split_w_kernel<<<DD, DD>>>(w2, p_ws);
    {
        dim3 grid(DD / 128, MPAD / 128);
        gcn_hmma_kernel<<<grid, 256>>>(p_xs, p_ws, p_bufA);
    }
    agg_kernel<<<NN, DD>>>(p_bufA, p_bufB, b2);

    // normalize + bf16 split:
    //   protos (B'): [hi | lo | hi]  -> hi2_off=512, lo_off=256 ; accumulate g_s
    //   hidden (A'): [hi | hi | lo]  -> hi2_off=256, lo_off=512
    norm_split_kernel<<<NN, DD>>>(p_bufB, p_Bbf, 512, 256, 1);
    norm_split_kernel<<<BB, DD>>>(hidden, p_Abf, 256, 512, 0);

    // sim GEMM with fused per-class max/argmax -> packed
    {
        dim3 grid(LDN / 128, BB / 128);
        sim_hmma_kernel<<<grid, 256>>>(p_Abf, p_Bbf, p_pack);
    }

    // CE + usage (decodes packed, writes output scores)
    ce_kernel<<<BB, 256>>>(p_pack, out, labels, out_pos, out_neg);

    // loss
    finalize_kernel<<<1, DD>>>(out_loss);
}

// round 13
// speedup vs baseline: 1.5657x; 1.0465x over previous
#include <cuda_runtime.h>
#include <cuda_bf16.h>
#include <math.h>
#include <stdint.h>

// Problem constants
#define BB 4096
#define CC 1000
#define PP 10
#define DD 256
#define NN 10000     // CC*PP
#define EE 160000
#define MARGIN_F (-0.1f)
#define LW_F (0.1f)

// bf16-split GEMM geometry
#define KTOT 768          // [hi | hi | lo] x [hi | lo | hi]
#define LDN 10112         // N padded to 79*128
#define MPAD 10112        // NN padded to 79*128

// ---------------- scratch (device globals; no runtime allocation) ----------------
__device__ float g_bufA[MPAD * DD];             // xw scratch (padded rows written, ignored)
__device__ float g_bufB[NN * DD];               // aggregated / x
__device__ __nv_bfloat16 g_xs[MPAD * KTOT];     // GCN input split (pad rows stay 0)
__device__ __nv_bfloat16 g_ws[DD * KTOT];       // weight split (transposed)
__device__ __nv_bfloat16 g_Abf[BB * KTOT];      // hidden_norm split
__device__ __nv_bfloat16 g_Bbf[LDN * KTOT];     // proto_norm split (pad rows stay 0)
__device__ unsigned long long g_pack[(size_t)BB * CC]; // packed (sortable max, 15-idx)
__device__ float g_disqrt[NN];
__device__ int   g_deg[NN];
__device__ int   g_rowptr[NN + 1];
__device__ int   g_col[EE];
__device__ int   g_cursor[NN];
__device__ float g_s[DD];
__device__ float g_ce_sum;
__device__ int   g_cnt;

// ---------------- helpers ----------------
__device__ __forceinline__ uint32_t smem_to_u32(const void* p) {
    uint32_t a;
    asm("{ .reg .u64 t; cvta.to.shared.u64 t, %1; cvt.u32.u64 %0, t; }" : "=r"(a) : "l"(p));
    return a;
}
__device__ __forceinline__ void cp_async16(uint32_t dst, const void* src) {
    asm volatile("cp.async.cg.shared.global [%0], [%1], 16;" :: "r"(dst), "l"(src) : "memory");
}
__device__ __forceinline__ void cp_commit() {
    asm volatile("cp.async.commit_group;" ::: "memory");
}
__device__ __forceinline__ void cp_wait0() {
    asm volatile("cp.async.wait_group 0;" ::: "memory");
}
__device__ __forceinline__ void ldm_x4(uint32_t& r0, uint32_t& r1, uint32_t& r2, uint32_t& r3,
                                       uint32_t addr) {
    asm volatile("ldmatrix.sync.aligned.m8n8.x4.shared.b16 {%0,%1,%2,%3}, [%4];"
                 : "=r"(r0), "=r"(r1), "=r"(r2), "=r"(r3) : "r"(addr));
}
__device__ __forceinline__ void mma16816(float* d, const uint32_t* a, const uint32_t* b) {
    asm volatile(
        "mma.sync.aligned.m16n8k16.row.col.f32.bf16.bf16.f32 "
        "{%0,%1,%2,%3}, {%4,%5,%6,%7}, {%8,%9}, {%0,%1,%2,%3};"
        : "+f"(d[0]), "+f"(d[1]), "+f"(d[2]), "+f"(d[3])
        : "r"(a[0]), "r"(a[1]), "r"(a[2]), "r"(a[3]), "r"(b[0]), "r"(b[1]));
}
__device__ __forceinline__ unsigned int f2sortable(float f) {
    unsigned int b = __float_as_uint(f);
    return (b & 0x80000000u) ? ~b : (b | 0x80000000u);
}
__device__ __forceinline__ float sortable2f(unsigned int e) {
    unsigned int b = (e & 0x80000000u) ? (e ^ 0x80000000u) : ~e;
    return __uint_as_float(b);
}

// ---------------- init ----------------
__global__ void init_kernel(float* out_tail) {
    int i = blockIdx.x * blockDim.x + threadIdx.x;
    if (i < NN) { g_deg[i] = 0; g_cursor[i] = 0; }
    if (i < DD) g_s[i] = 0.0f;
    if (i == 0) { g_ce_sum = 0.0f; g_cnt = 0; }
    if (i < 1 + 2 * NN) out_tail[i] = 0.0f;
    // only boundary-straddling classes are combined via atomicMax; reset just those
    if (i < BB * CC) {
        int c = i % CC;
        if (((c * PP) & 127) >= 119) g_pack[i] = 0ull;
    }
}

// ---------------- degree ----------------
__global__ void deg_kernel(const int* __restrict__ ei) {
    int e = blockIdx.x * blockDim.x + threadIdx.x;
    if (e < EE) atomicAdd(&g_deg[ei[EE + e]], 1);
}

__global__ void disqrt_kernel() {
    int n = blockIdx.x * blockDim.x + threadIdx.x;
    if (n < NN) {
        float x = (float)(g_deg[n] + 1);
        float r = rsqrtf(x);
        r = r * (1.5f - 0.5f * x * r * r);
        g_disqrt[n] = r;
    }
}

// ---------------- exclusive scan ----------------
__global__ void scan_kernel() {
    const int T = 1024;
    const int CH = (NN + T - 1) / T;
    __shared__ int part[T];
    int t = threadIdx.x;
    int base = t * CH;
    int s = 0;
    for (int i = 0; i < CH; i++) {
        int idx = base + i;
        if (idx < NN) s += g_deg[idx];
    }
    part[t] = s;
    __syncthreads();
    for (int off = 1; off < T; off <<= 1) {
        int add = (t >= off) ? part[t - off] : 0;
        __syncthreads();
        part[t] += add;
        __syncthreads();
    }
    if (t == 0) g_rowptr[NN] = part[T - 1];
    int prefix = (t > 0) ? part[t - 1] : 0;
    for (int i = 0; i < CH; i++) {
        int idx = base + i;
        if (idx < NN) { g_rowptr[idx] = prefix; prefix += g_deg[idx]; }
    }
}

__global__ void scatter_kernel(const int* __restrict__ ei) {
    int e = blockIdx.x * blockDim.x + threadIdx.x;
    if (e < EE) {
        int d = ei[EE + e];
        int pos = g_rowptr[d] + atomicAdd(&g_cursor[d], 1);
        g_col[pos] = ei[e];
    }
}

__global__ void sort_kernel() {
    int n = blockIdx.x * blockDim.x + threadIdx.x;
    if (n >= NN) return;
    int beg = g_rowptr[n], end = g_rowptr[n + 1];
    for (int i = beg + 1; i < end; i++) {
        int key = g_col[i];
        int j = i - 1;
        while (j >= beg && g_col[j] > key) { g_col[j + 1] = g_col[j]; j--; }
        g_col[j + 1] = key;
    }
}

// ---------------- bf16 split kernels ----------------
__global__ void split_x_kernel(const float* __restrict__ in, __nv_bfloat16* __restrict__ outp) {
    int r = blockIdx.x;
    int t = threadIdx.x;
    float v = in[(size_t)r * DD + t];
    __nv_bfloat16 hi = __float2bfloat16(v);
    __nv_bfloat16 lo = __float2bfloat16(v - __bfloat162float(hi));
    size_t base = (size_t)r * KTOT;
    outp[base + t] = hi;
    outp[base + DD + t] = hi;
    outp[base + 2 * DD + t] = lo;
}

__global__ void split_w_kernel(const float* __restrict__ w, __nv_bfloat16* __restrict__ outp) {
    int n = blockIdx.x;   // output col
    int k = threadIdx.x;  // input dim
    float v = w[(size_t)k * DD + n];
    __nv_bfloat16 hi = __float2bfloat16(v);
    __nv_bfloat16 lo = __float2bfloat16(v - __bfloat162float(hi));
    size_t base = (size_t)n * KTOT;
    outp[base + k] = hi;
    outp[base + DD + k] = lo;
    outp[base + 2 * DD + k] = hi;
}

// ---------------- row L2 normalize + bf16 split ----------------
__global__ void norm_split_kernel(const float* __restrict__ in,
                                  __nv_bfloat16* __restrict__ outp,
                                  int hi2_off, int lo_off, int accum_s) {
    int r = blockIdx.x;
    int t = threadIdx.x;
    float v = in[(size_t)r * DD + t];
    __shared__ float sh[DD];
    sh[t] = v * v;
    __syncthreads();
    for (int off = 128; off > 0; off >>= 1) {
        if (t < off) sh[t] += sh[t + off];
        __syncthreads();
    }
    float nrm = sqrtf(sh[0]);
    float val = v / fmaxf(nrm, 1e-12f);
    __nv_bfloat16 hi = __float2bfloat16(val);
    __nv_bfloat16 lo = __float2bfloat16(val - __bfloat162float(hi));
    size_t base = (size_t)r * KTOT;
    outp[base + t] = hi;
    outp[base + hi2_off + t] = hi;
    outp[base + lo_off + t] = lo;
    if (accum_s) atomicAdd(&g_s[t], val);
}

// ---------------- bf16 HMMA sim GEMM + fused per-class max -------------------
// BKK=64 K-chunk (12 iterations): half the barriers/waits of the BKK=32 version.
#define BKK 64
#define LDK 72            // 144B row stride: 8-row ldmatrix phase covers all 32 banks
#define KITERS (KTOT / BKK)   // 12
#define BUF_B (128 * LDK * 2) // 18432 per matrix per stage
#define SIM_SMEM (4 * BUF_B)  // 73728: 2 stages x (A,B)

__global__ __launch_bounds__(256) void sim_hmma_kernel(const __nv_bfloat16* __restrict__ Abf,
                                                       const __nv_bfloat16* __restrict__ Bbf,
                                                       unsigned long long* __restrict__ pack) {
    extern __shared__ __align__(16) char smem_raw[];

    const int tid = threadIdx.x;
    const int wid = tid >> 5;
    const int lane = tid & 31;
    const int bm = blockIdx.y * 128;
    const int bn = blockIdx.x * 128;

    const int wm = (wid & 3) * 32;   // warp m offset
    const int wn = (wid >> 2) * 64;  // warp n offset

    const uint32_t sA0 = smem_to_u32(smem_raw);
    const uint32_t sA1 = sA0 + BUF_B;
    const uint32_t sB0 = sA0 + 2 * BUF_B;
    const uint32_t sB1 = sA0 + 3 * BUF_B;

    float acc[2][8][4];
#pragma unroll
    for (int mt = 0; mt < 2; mt++)
#pragma unroll
        for (int nt = 0; nt < 8; nt++)
#pragma unroll
            for (int e = 0; e < 4; e++) acc[mt][nt][e] = 0.0f;

#define SIM_LOAD(dstA, dstB, k0) do {                                              \
        _Pragma("unroll")                                                          \
        for (int q = 0; q < 4; q++) {                                              \
            int chunk = tid + q * 256;                                             \
            int row = chunk >> 3;                                                  \
            int cs = chunk & 7;                                                    \
            uint32_t off = (uint32_t)(row * (LDK * 2) + cs * 16);                  \
            cp_async16((dstA) + off, &Abf[(size_t)(bm + row) * KTOT + (k0) + cs * 8]); \
            cp_async16((dstB) + off, &Bbf[(size_t)(bn + row) * KTOT + (k0) + cs * 8]); \
        }                                                                          \
    } while (0)

    SIM_LOAD(sA0, sB0, 0);
    cp_commit();

    for (int kb = 0; kb < KITERS; kb++) {
        cp_wait0();
        __syncthreads();
        if (kb + 1 < KITERS) {
            uint32_t dA = ((kb + 1) & 1) ? sA1 : sA0;
            uint32_t dB = ((kb + 1) & 1) ? sB1 : sB0;
            SIM_LOAD(dA, dB, (kb + 1) * BKK);
            cp_commit();
        }
        uint32_t aBase = (kb & 1) ? sA1 : sA0;
        uint32_t bBase = (kb & 1) ? sB1 : sB0;
#pragma unroll
        for (int ks = 0; ks < BKK; ks += 16) {
            uint32_t afr[2][4];
#pragma unroll
            for (int mt = 0; mt < 2; mt++) {
                int r = wm + mt * 16 + (lane & 15);
                int c = ks + 8 * (lane >> 4);
                ldm_x4(afr[mt][0], afr[mt][1], afr[mt][2], afr[mt][3],
                       aBase + (uint32_t)(r * LDK + c) * 2);
            }
            uint32_t bfr[8][2];
#pragma unroll
            for (int bt = 0; bt < 4; bt++) {
                int r = wn + bt * 16 + ((lane >> 4) & 1) * 8 + (lane & 7);
                int c = ks + ((lane >> 3) & 1) * 8;
                ldm_x4(bfr[bt * 2][0], bfr[bt * 2][1], bfr[bt * 2 + 1][0], bfr[bt * 2 + 1][1],
                       bBase + (uint32_t)(r * LDK + c) * 2);
            }
#pragma unroll
            for (int mt = 0; mt < 2; mt++)
#pragma unroll
                for (int nt = 0; nt < 8; nt++)
                    mma16816(acc[mt][nt], afr[mt], bfr[nt]);
        }
        __syncthreads();
    }
#undef SIM_LOAD

    // -------- fused epilogue: per-class (groups of PP cols) max + argmax --------
    {
        float* sst = (float*)smem_raw;   // 64 x 132 floats = 33792B staging (fits)
        const int lwm = wm & 63;
        int c_lo = bn / PP;
        int c_hi = (bn + 127) / PP;
        if (c_hi > CC - 1) c_hi = CC - 1;
        const int r = tid >> 2;          // 0..63
        const int cstep0 = tid & 3;
#pragma unroll
        for (int half = 0; half < 2; half++) {
            __syncthreads();
            if ((wm < 64) == (half == 0)) {
#pragma unroll
                for (int mt = 0; mt < 2; mt++) {
                    int r0 = lwm + mt * 16 + (lane >> 2);
#pragma unroll
                    for (int nt = 0; nt < 8; nt++) {
                        int col = wn + nt * 8 + 2 * (lane & 3);
                        sst[r0 * 132 + col] = acc[mt][nt][0];
                        sst[r0 * 132 + col + 1] = acc[mt][nt][1];
                        sst[(r0 + 8) * 132 + col] = acc[mt][nt][2];
                        sst[(r0 + 8) * 132 + col + 1] = acc[mt][nt][3];
                    }
                }
            }
            __syncthreads();
            for (int c = c_lo + cstep0; c <= c_hi; c += 4) {
                int col0 = c * PP - bn;
                int lo = col0 > 0 ? col0 : 0;
                int hi = col0 + PP < 128 ? col0 + PP : 128;
                float best = -3.402823466e+38f;
                int bj = 0;
                for (int x = lo; x < hi; x++) {
                    float v = sst[r * 132 + x];
                    if (v > best) { best = v; bj = x - col0; }
                }
                unsigned long long pk =
                    ((unsigned long long)f2sortable(best) << 32) | (unsigned int)(15 - bj);
                unsigned long long* dst = &pack[(size_t)(bm + half * 64 + r) * CC + c];
                if (col0 >= 0 && col0 + PP <= 128) *dst = pk;   // interior: exclusive writer
                else atomicMax(dst, pk);                         // straddles tile boundary
            }
        }
    }
}

// ---------------- GCN HMMA GEMM (unchanged proven BKK=32): C[MPAD, DD] ----------
#define GBKK 32
#define GLDK 40
#define GKITERS (KTOT / GBKK)   // 24

__global__ __launch_bounds__(256) void gcn_hmma_kernel(const __nv_bfloat16* __restrict__ Abf,
                                                       const __nv_bfloat16* __restrict__ Bbf,
                                                       float* __restrict__ Cout) {
    __shared__ __nv_bfloat16 sA[2][128 * GLDK];
    __shared__ __nv_bfloat16 sB[2][128 * GLDK];

    const int tid = threadIdx.x;
    const int wid = tid >> 5;
    const int lane = tid & 31;
    const int bm = blockIdx.y * 128;
    const int bn = blockIdx.x * 128;

    const int wm = (wid & 3) * 32;
    const int wn = (wid >> 2) * 64;

    const uint32_t sA0 = smem_to_u32(&sA[0][0]);
    const uint32_t sA1 = smem_to_u32(&sA[1][0]);
    const uint32_t sB0 = smem_to_u32(&sB[0][0]);
    const uint32_t sB1 = smem_to_u32(&sB[1][0]);

    const int r0c = tid >> 2;
    const int c0c = tid & 3;

    float acc[2][8][4];
#pragma unroll
    for (int mt = 0; mt < 2; mt++)
#pragma unroll
        for (int nt = 0; nt < 8; nt++)
#pragma unroll
            for (int e = 0; e < 4; e++) acc[mt][nt][e] = 0.0f;

    {
#pragma unroll
        for (int q = 0; q < 2; q++) {
            int row = r0c + q * 64;
            int col = c0c * 8;
            cp_async16(sA0 + (uint32_t)(row * GLDK + col) * 2,
                       &Abf[(size_t)(bm + row) * KTOT + col]);
            cp_async16(sB0 + (uint32_t)(row * GLDK + col) * 2,
                       &Bbf[(size_t)(bn + row) * KTOT + col]);
        }
        cp_commit();
    }

    for (int kb = 0; kb < GKITERS; kb++) {
        cp_wait0();
        __syncthreads();
        if (kb + 1 < GKITERS) {
            const int k0 = (kb + 1) * GBKK;
            uint32_t dA = ((kb + 1) & 1) ? sA1 : sA0;
            uint32_t dB = ((kb + 1) & 1) ? sB1 : sB0;
#pragma unroll
            for (int q = 0; q < 2; q++) {
                int row = r0c + q * 64;
                int col = c0c * 8;
                cp_async16(dA + (uint32_t)(row * GLDK + col) * 2,
                           &Abf[(size_t)(bm + row) * KTOT + k0 + col]);
                cp_async16(dB + (uint32_t)(row * GLDK + col) * 2,
                           &Bbf[(size_t)(bn + row) * KTOT + k0 + col]);
            }
            cp_commit();
        }
        uint32_t aBase = (kb & 1) ? sA1 : sA0;
        uint32_t bBase = (kb & 1) ? sB1 : sB0;
#pragma unroll
        for (int ks = 0; ks < GBKK; ks += 16) {
            uint32_t afr[2][4];
#pragma unroll
            for (int mt = 0; mt < 2; mt++) {
                int r = wm + mt * 16 + (lane & 15);
                int c = ks + 8 * (lane >> 4);
                ldm_x4(afr[mt][0], afr[mt][1], afr[mt][2], afr[mt][3],
                       aBase + (uint32_t)(r * GLDK + c) * 2);
            }
            uint32_t bfr[8][2];
#pragma unroll
            for (int bt = 0; bt < 4; bt++) {
                int r = wn + bt * 16 + ((lane >> 4) & 1) * 8 + (lane & 7);
                int c = ks + ((lane >> 3) & 1) * 8;
                ldm_x4(bfr[bt * 2][0], bfr[bt * 2][1], bfr[bt * 2 + 1][0], bfr[bt * 2 + 1][1],
                       bBase + (uint32_t)(r * GLDK + c) * 2);
            }
#pragma unroll
            for (int mt = 0; mt < 2; mt++)
#pragma unroll
                for (int nt = 0; nt < 8; nt++)
                    mma16816(acc[mt][nt], afr[mt], bfr[nt]);
        }
        __syncthreads();
    }

#pragma unroll
    for (int mt = 0; mt < 2; mt++) {
        int row0 = bm + wm + mt * 16 + (lane >> 2);
#pragma unroll
        for (int nt = 0; nt < 8; nt++) {
            int col = bn + wn + nt * 8 + 2 * (lane & 3);
            *(float2*)&Cout[(size_t)row0 * DD + col] =
                make_float2(acc[mt][nt][0], acc[mt][nt][1]);
            *(float2*)&Cout[(size_t)(row0 + 8) * DD + col] =
                make_float2(acc[mt][nt][2], acc[mt][nt][3]);
        }
    }
}

// ---------------- GCN aggregation + bias + relu ----------------
__global__ void agg_kernel(const float* __restrict__ xw,
                           float* __restrict__ outp,
                           const float* __restrict__ bias) {
    int n = blockIdx.x;
    int d = threadIdx.x;
    float dn = g_disqrt[n];
    float acc = dn * dn * xw[(size_t)n * DD + d];
    int beg = g_rowptr[n], end = g_rowptr[n + 1];
    for (int j = beg; j < end; j++) {
        int s = g_col[j];
        acc += dn * g_disqrt[s] * xw[(size_t)s * DD + d];
    }
    outp[(size_t)n * DD + d] = fmaxf(acc + bias[d], 0.0f);
}

// ---------------- per-row CE + usage scatter (consumes packed) ----------------
__global__ void ce_kernel(const unsigned long long* __restrict__ pack,
                          float* __restrict__ out,
                          const int* __restrict__ labels,
                          float* __restrict__ usage_pos,
                          float* __restrict__ usage_neg) {
    int b = blockIdx.x;
    const unsigned long long* prow = pack + (size_t)b * CC;
    float* orow = out + (size_t)b * CC;
    int t = threadIdx.x;
    __shared__ float smax[256];
    __shared__ int simax[256];
    float bm = -1e30f;
    int bi = 0x7fffffff;
    for (int c = t; c < CC; c += 256) {
        unsigned long long pk = prow[c];
        float v = 0.5f * (1.0f + sortable2f((unsigned int)(pk >> 32)));
        orow[c] = v;
        if (v > bm) { bm = v; bi = c; }
    }
    smax[t] = bm; simax[t] = bi;
    __syncthreads();
    for (int off = 128; off > 0; off >>= 1) {
        if (t < off) {
            float v2 = smax[t + off];
            int i2 = simax[t + off];
            if (v2 > smax[t] || (v2 == smax[t] && i2 < simax[t])) {
                smax[t] = v2; simax[t] = i2;
            }
        }
        __syncthreads();
    }
    float rowmax = smax[0];
    int pred = simax[0];
    __shared__ float ssum[256];
    float s = 0.0f;
    for (int c = t; c < CC; c += 256) s += expf(orow[c] - rowmax);
    ssum[t] = s;
    __syncthreads();
    for (int off = 128; off > 0; off >>= 1) {
        if (t < off) ssum[t] += ssum[t + off];
        __syncthreads();
    }
    if (t == 0) {
        int lab = labels[b];
        float x_lab = orow[lab];
        float lse = rowmax + logf(ssum[0]);
        if ((x_lab - rowmax) > MARGIN_F) {
            atomicAdd(&g_ce_sum, lse - x_lab);
            atomicAdd(&g_cnt, 1);
        }
        int jl = 15 - (int)(unsigned int)(prow[lab] & 0xFFFFFFFFull);
        atomicAdd(&usage_pos[lab * PP + jl], 1.0f);
        if (pred != lab) {
            int jp = 15 - (int)(unsigned int)(prow[pred] & 0xFFFFFFFFull);
            atomicAdd(&usage_neg[pred * PP + jp], 1.0f);
        }
    }
}

// ---------------- finalize loss ----------------
__global__ void finalize_kernel(float* __restrict__ out_loss) {
    __shared__ float sh[DD];
    int t = threadIdx.x;
    float v = g_s[t];
    sh[t] = v * v;
    __syncthreads();
    for (int off = 128; off > 0; off >>= 1) {
        if (t < off) sh[t] += sh[t + off];
        __syncthreads();
    }
    if (t == 0) {
        float disp = -sh[0] / ((float)NN * (float)NN);
        int cnt = g_cnt;
        float loss = (cnt == 0) ? 0.0f
                                : (g_ce_sum / (float)(cnt > 1 ? cnt : 1) + LW_F * disp);
        out_loss[0] = loss;
    }
}

// ---------------- launch ----------------
extern "C" void kernel_launch(void* const* d_in, const int* in_sizes, int n_in,
                              void* d_out, int out_size) {
    const float* hidden = (const float*)d_in[0];
    const int* labels = (const int*)d_in[1];
    const int* edge_index = (const int*)d_in[2];
    const float* node_features = (const float*)d_in[3];
    const float* w1 = (const float*)d_in[4];
    const float* b1 = (const float*)d_in[5];
    const float* w2 = (const float*)d_in[6];
    const float* b2 = (const float*)d_in[7];
    float* out = (float*)d_out;

    float* out_loss = out + (size_t)BB * CC;
    float* out_pos = out_loss + 1;
    float* out_neg = out_pos + NN;

    float *p_bufA = 0, *p_bufB = 0;
    __nv_bfloat16 *p_xs = 0, *p_ws = 0, *p_Abf = 0, *p_Bbf = 0;
    unsigned long long* p_pack = 0;
    cudaGetSymbolAddress((void**)&p_bufA, g_bufA);
    cudaGetSymbolAddress((void**)&p_bufB, g_bufB);
    cudaGetSymbolAddress((void**)&p_xs,   g_xs);
    cudaGetSymbolAddress((void**)&p_ws,   g_ws);
    cudaGetSymbolAddress((void**)&p_Abf,  g_Abf);
    cudaGetSymbolAddress((void**)&p_Bbf,  g_Bbf);
    cudaGetSymbolAddress((void**)&p_pack, g_pack);

    cudaFuncSetAttribute(sim_hmma_kernel, cudaFuncAttributeMaxDynamicSharedMemorySize, SIM_SMEM);

    // graph build + boundary pack reset
    init_kernel<<<(BB * CC + 255) / 256, 256>>>(out_loss);
    deg_kernel<<<(EE + 255) / 256, 256>>>(edge_index);
    disqrt_kernel<<<(NN + 255) / 256, 256>>>();
    scan_kernel<<<1, 1024>>>();
    scatter_kernel<<<(EE + 255) / 256, 256>>>(edge_index);
    sort_kernel<<<(NN + 255) / 256, 256>>>();

    // GCN layer 1: xw = x @ w1 (bf16-split HMMA), aggregate + bias + relu
    split_x_kernel<<<NN, DD>>>(node_features, p_xs);
    split_w_kernel<<<DD, DD>>>(w1, p_ws);
    {
        dim3 grid(DD / 128, MPAD / 128);
        gcn_hmma_kernel<<<grid, 256>>>(p_xs, p_ws, p_bufA);
    }
    agg_kernel<<<NN, DD>>>(p_bufA, p_bufB, b1);

    // GCN layer 2
    split_x_kernel<<<NN, DD>>>(p_bufB, p_xs);
    split_w_kernel<<<DD, DD>>>(w2, p_ws);
    {
        dim3 grid(DD / 128, MPAD / 128);
        gcn_hmma_kernel<<<grid, 256>>>(p_xs, p_ws, p_bufA);
    }
    agg_kernel<<<NN, DD>>>(p_bufA, p_bufB, b2);

    // normalize + bf16 split:
    //   protos (B'): [hi | lo | hi]  -> hi2_off=512, lo_off=256 ; accumulate g_s
    //   hidden (A'): [hi | hi | lo]  -> hi2_off=256, lo_off=512
    norm_split_kernel<<<NN, DD>>>(p_bufB, p_Bbf, 512, 256, 1);
    norm_split_kernel<<<BB, DD>>>(hidden, p_Abf, 256, 512, 0);

    // sim GEMM (BKK=64, dynamic smem) with fused per-class max/argmax -> packed
    {
        dim3 grid(LDN / 128, BB / 128);
        sim_hmma_kernel<<<grid, 256, SIM_SMEM>>>(p_Abf, p_Bbf, p_pack);
    }

    // CE + usage (decodes packed, writes output scores)
    ce_kernel<<<BB, 256>>>(p_pack, out, labels, out_pos, out_neg);

    // loss
    finalize_kernel<<<1, DD>>>(out_loss);
}

// round 14
// speedup vs baseline: 1.6098x; 1.0282x over previous
#include <cuda_runtime.h>
#include <cuda_bf16.h>
#include <math.h>
#include <stdint.h>

// Problem constants
#define BB 4096
#define CC 1000
#define PP 10
#define DD 256
#define NN 10000     // CC*PP
#define EE 160000
#define MARGIN_F (-0.1f)
#define LW_F (0.1f)

// bf16-split GEMM geometry
#define KTOT 768          // [hi | hi | lo] x [hi | lo | hi]
#define LDN 10112         // N padded to 79*128
#define MPAD 10112        // NN padded to 79*128

// ---------------- scratch (device globals; no runtime allocation) ----------------
__device__ float g_bufA[MPAD * DD];             // xw scratch (padded rows written, ignored)
__device__ float g_bufB[NN * DD];               // aggregated / x
__device__ __nv_bfloat16 g_xs[MPAD * KTOT];     // GCN input split (pad rows stay 0)
__device__ __nv_bfloat16 g_ws[DD * KTOT];       // weight split (transposed)
__device__ __nv_bfloat16 g_Abf[BB * KTOT];      // hidden_norm split
__device__ __nv_bfloat16 g_Bbf[LDN * KTOT];     // proto_norm split (pad rows stay 0)
__device__ unsigned long long g_pack[(size_t)BB * CC]; // packed (sortable max, 15-idx)
__device__ float g_disqrt[NN];
__device__ int   g_deg[NN];
__device__ int   g_rowptr[NN + 1];
__device__ int   g_col[EE];
__device__ int   g_cursor[NN];
__device__ float g_s[DD];
__device__ float g_ce_sum;
__device__ int   g_cnt;

// ---------------- helpers ----------------
__device__ __forceinline__ uint32_t smem_to_u32(const void* p) {
    uint32_t a;
    asm("{ .reg .u64 t; cvta.to.shared.u64 t, %1; cvt.u32.u64 %0, t; }" : "=r"(a) : "l"(p));
    return a;
}
__device__ __forceinline__ void cp_async16(uint32_t dst, const void* src) {
    asm volatile("cp.async.cg.shared.global [%0], [%1], 16;" :: "r"(dst), "l"(src) : "memory");
}
__device__ __forceinline__ void cp_commit() {
    asm volatile("cp.async.commit_group;" ::: "memory");
}
__device__ __forceinline__ void cp_wait0() {
    asm volatile("cp.async.wait_group 0;" ::: "memory");
}
__device__ __forceinline__ void ldm_x4(uint32_t& r0, uint32_t& r1, uint32_t& r2, uint32_t& r3,
                                       uint32_t addr) {
    asm volatile("ldmatrix.sync.aligned.m8n8.x4.shared.b16 {%0,%1,%2,%3}, [%4];"
                 : "=r"(r0), "=r"(r1), "=r"(r2), "=r"(r3) : "r"(addr));
}
__device__ __forceinline__ void mma16816(float* d, const uint32_t* a, const uint32_t* b) {
    asm volatile(
        "mma.sync.aligned.m16n8k16.row.col.f32.bf16.bf16.f32 "
        "{%0,%1,%2,%3}, {%4,%5,%6,%7}, {%8,%9}, {%0,%1,%2,%3};"
        : "+f"(d[0]), "+f"(d[1]), "+f"(d[2]), "+f"(d[3])
        : "r"(a[0]), "r"(a[1]), "r"(a[2]), "r"(a[3]), "r"(b[0]), "r"(b[1]));
}
__device__ __forceinline__ unsigned int f2sortable(float f) {
    unsigned int b = __float_as_uint(f);
    return (b & 0x80000000u) ? ~b : (b | 0x80000000u);
}
__device__ __forceinline__ float sortable2f(unsigned int e) {
    unsigned int b = (e & 0x80000000u) ? (e ^ 0x80000000u) : ~e;
    return __uint_as_float(b);
}

// ---------------- init ----------------
__global__ void init_kernel(float* out_tail) {
    int i = blockIdx.x * blockDim.x + threadIdx.x;
    if (i < NN) { g_deg[i] = 0; g_cursor[i] = 0; }
    if (i < DD) g_s[i] = 0.0f;
    if (i == 0) { g_ce_sum = 0.0f; g_cnt = 0; }
    if (i < 1 + 2 * NN) out_tail[i] = 0.0f;
    // only boundary-straddling classes are combined via atomicMax; reset just those
    if (i < BB * CC) {
        int c = i % CC;
        if (((c * PP) & 127) >= 119) g_pack[i] = 0ull;
    }
}

// ---------------- degree ----------------
__global__ void deg_kernel(const int* __restrict__ ei) {
    int e = blockIdx.x * blockDim.x + threadIdx.x;
    if (e < EE) atomicAdd(&g_deg[ei[EE + e]], 1);
}

// ---------------- exclusive scan (shfl-based) + fused disqrt ----------------
__global__ void scan_kernel() {
    const int T = 1024;
    const int CH = (NN + T - 1) / T;   // 10
    __shared__ int wsum[32];
    int t = threadIdx.x;
    int lane = t & 31, w = t >> 5;
    int base = t * CH;
    int local[CH];
    int s = 0;
#pragma unroll
    for (int i = 0; i < CH; i++) {
        int idx = base + i;
        local[i] = (idx < NN) ? g_deg[idx] : 0;
        s += local[i];
    }
    // warp inclusive scan of s
    int v = s;
#pragma unroll
    for (int off = 1; off < 32; off <<= 1) {
        int u = __shfl_up_sync(0xFFFFFFFFu, v, off);
        if (lane >= off) v += u;
    }
    if (lane == 31) wsum[w] = v;
    __syncthreads();
    if (w == 0) {
        int x = wsum[lane];
#pragma unroll
        for (int off = 1; off < 32; off <<= 1) {
            int u = __shfl_up_sync(0xFFFFFFFFu, x, off);
            if (lane >= off) x += u;
        }
        wsum[lane] = x;
    }
    __syncthreads();
    int run = v - s + (w > 0 ? wsum[w - 1] : 0);   // exclusive prefix of this thread's chunk
#pragma unroll
    for (int i = 0; i < CH; i++) {
        int idx = base + i;
        if (idx < NN) { g_rowptr[idx] = run; run += local[i]; }
    }
    if (t == T - 1) g_rowptr[NN] = run;
    // fused disqrt
    for (int n = t; n < NN; n += T) {
        float x = (float)(g_deg[n] + 1);
        float r = rsqrtf(x);
        r = r * (1.5f - 0.5f * x * r * r);
        g_disqrt[n] = r;
    }
}

__global__ void scatter_kernel(const int* __restrict__ ei) {
    int e = blockIdx.x * blockDim.x + threadIdx.x;
    if (e < EE) {
        int d = ei[EE + e];
        int pos = g_rowptr[d] + atomicAdd(&g_cursor[d], 1);
        g_col[pos] = ei[e];
    }
}

__global__ void sort_kernel() {
    int n = blockIdx.x * blockDim.x + threadIdx.x;
    if (n >= NN) return;
    int beg = g_rowptr[n], end = g_rowptr[n + 1];
    for (int i = beg + 1; i < end; i++) {
        int key = g_col[i];
        int j = i - 1;
        while (j >= beg && g_col[j] > key) { g_col[j + 1] = g_col[j]; j--; }
        g_col[j + 1] = key;
    }
}

// ---------------- bf16 split kernels ----------------
__global__ void split_x_kernel(const float* __restrict__ in, __nv_bfloat16* __restrict__ outp) {
    int r = blockIdx.x;
    int t = threadIdx.x;
    float v = in[(size_t)r * DD + t];
    __nv_bfloat16 hi = __float2bfloat16(v);
    __nv_bfloat16 lo = __float2bfloat16(v - __bfloat162float(hi));
    size_t base = (size_t)r * KTOT;
    outp[base + t] = hi;
    outp[base + DD + t] = hi;
    outp[base + 2 * DD + t] = lo;
}

__global__ void split_w_kernel(const float* __restrict__ w, __nv_bfloat16* __restrict__ outp) {
    int n = blockIdx.x;   // output col
    int k = threadIdx.x;  // input dim
    float v = w[(size_t)k * DD + n];
    __nv_bfloat16 hi = __float2bfloat16(v);
    __nv_bfloat16 lo = __float2bfloat16(v - __bfloat162float(hi));
    size_t base = (size_t)n * KTOT;
    outp[base + k] = hi;
    outp[base + DD + k] = lo;
    outp[base + 2 * DD + k] = hi;
}

// ---------------- row L2 normalize + bf16 split ----------------
__global__ void norm_split_kernel(const float* __restrict__ in,
                                  __nv_bfloat16* __restrict__ outp,
                                  int hi2_off, int lo_off, int accum_s) {
    int r = blockIdx.x;
    int t = threadIdx.x;
    float v = in[(size_t)r * DD + t];
    __shared__ float sh[DD];
    sh[t] = v * v;
    __syncthreads();
    for (int off = 128; off > 0; off >>= 1) {
        if (t < off) sh[t] += sh[t + off];
        __syncthreads();
    }
    float nrm = sqrtf(sh[0]);
    float val = v / fmaxf(nrm, 1e-12f);
    __nv_bfloat16 hi = __float2bfloat16(val);
    __nv_bfloat16 lo = __float2bfloat16(val - __bfloat162float(hi));
    size_t base = (size_t)r * KTOT;
    outp[base + t] = hi;
    outp[base + hi2_off + t] = hi;
    outp[base + lo_off + t] = lo;
    if (accum_s) atomicAdd(&g_s[t], val);
}

// ---------------- shared BKK=64 HMMA tile geometry -------------------
#define BKK 64
#define LDK 72            // 144B row stride: 8-row ldmatrix phase covers all 32 banks
#define KITERS (KTOT / BKK)   // 12
#define BUF_B (128 * LDK * 2) // 18432 per matrix per stage
#define HMMA_SMEM (4 * BUF_B) // 73728: 2 stages x (A,B)

#define HMMA_LOAD(dstA, dstB, k0) do {                                             \
        _Pragma("unroll")                                                          \
        for (int q = 0; q < 4; q++) {                                              \
            int chunk = tid + q * 256;                                             \
            int row = chunk >> 3;                                                  \
            int cs = chunk & 7;                                                    \
            uint32_t off = (uint32_t)(row * (LDK * 2) + cs * 16);                  \
            cp_async16((dstA) + off, &Abf[(size_t)(bm + row) * KTOT + (k0) + cs * 8]); \
            cp_async16((dstB) + off, &Bbf[(size_t)(bn + row) * KTOT + (k0) + cs * 8]); \
        }                                                                          \
    } while (0)

#define HMMA_MAINLOOP()                                                            \
    HMMA_LOAD(sA0, sB0, 0);                                                        \
    cp_commit();                                                                   \
    for (int kb = 0; kb < KITERS; kb++) {                                          \
        cp_wait0();                                                                \
        __syncthreads();                                                           \
        if (kb + 1 < KITERS) {                                                     \
            uint32_t dA = ((kb + 1) & 1) ? sA1 : sA0;                              \
            uint32_t dB = ((kb + 1) & 1) ? sB1 : sB0;                              \
            HMMA_LOAD(dA, dB, (kb + 1) * BKK);                                     \
            cp_commit();                                                           \
        }                                                                          \
        uint32_t aBase = (kb & 1) ? sA1 : sA0;                                     \
        uint32_t bBase = (kb & 1) ? sB1 : sB0;                                     \
        _Pragma("unroll")                                                          \
        for (int ks = 0; ks < BKK; ks += 16) {                                     \
            uint32_t afr[2][4];                                                    \
            _Pragma("unroll")                                                      \
            for (int mt = 0; mt < 2; mt++) {                                       \
                int r = wm + mt * 16 + (lane & 15);                                \
                int c = ks + 8 * (lane >> 4);                                      \
                ldm_x4(afr[mt][0], afr[mt][1], afr[mt][2], afr[mt][3],             \
                       aBase + (uint32_t)(r * LDK + c) * 2);                       \
            }                                                                      \
            uint32_t bfr[8][2];                                                    \
            _Pragma("unroll")                                                      \
            for (int bt = 0; bt < 4; bt++) {                                       \
                int r = wn + bt * 16 + ((lane >> 4) & 1) * 8 + (lane & 7);         \
                int c = ks + ((lane >> 3) & 1) * 8;                                \
                ldm_x4(bfr[bt * 2][0], bfr[bt * 2][1],                             \
                       bfr[bt * 2 + 1][0], bfr[bt * 2 + 1][1],                     \
                       bBase + (uint32_t)(r * LDK + c) * 2);                       \
            }                                                                      \
            _Pragma("unroll")                                                      \
            for (int mt = 0; mt < 2; mt++)                                         \
                _Pragma("unroll")                                                  \
                for (int nt = 0; nt < 8; nt++)                                     \
                    mma16816(acc[mt][nt], afr[mt], bfr[nt]);                       \
        }                                                                          \
        __syncthreads();                                                           \
    }

// ---------------- bf16 HMMA sim GEMM + fused per-class max -------------------
__global__ __launch_bounds__(256) void sim_hmma_kernel(const __nv_bfloat16* __restrict__ Abf,
                                                       const __nv_bfloat16* __restrict__ Bbf,
                                                       unsigned long long* __restrict__ pack) {
    extern __shared__ __align__(16) char smem_raw[];

    const int tid = threadIdx.x;
    const int wid = tid >> 5;
    const int lane = tid & 31;
    const int bm = blockIdx.y * 128;
    const int bn = blockIdx.x * 128;

    const int wm = (wid & 3) * 32;   // warp m offset
    const int wn = (wid >> 2) * 64;  // warp n offset

    const uint32_t sA0 = smem_to_u32(smem_raw);
    const uint32_t sA1 = sA0 + BUF_B;
    const uint32_t sB0 = sA0 + 2 * BUF_B;
    const uint32_t sB1 = sA0 + 3 * BUF_B;

    float acc[2][8][4];
#pragma unroll
    for (int mt = 0; mt < 2; mt++)
#pragma unroll
        for (int nt = 0; nt < 8; nt++)
#pragma unroll
            for (int e = 0; e < 4; e++) acc[mt][nt][e] = 0.0f;

    HMMA_MAINLOOP();

    // -------- fused epilogue: per-class (groups of PP cols) max + argmax --------
    {
        float* sst = (float*)smem_raw;   // 64 x 132 floats = 33792B staging (fits)
        const int lwm = wm & 63;
        int c_lo = bn / PP;
        int c_hi = (bn + 127) / PP;
        if (c_hi > CC - 1) c_hi = CC - 1;
        const int r = tid >> 2;          // 0..63
        const int cstep0 = tid & 3;
#pragma unroll
        for (int half = 0; half < 2; half++) {
            __syncthreads();
            if ((wm < 64) == (half == 0)) {
#pragma unroll
                for (int mt = 0; mt < 2; mt++) {
                    int r0 = lwm + mt * 16 + (lane >> 2);
#pragma unroll
                    for (int nt = 0; nt < 8; nt++) {
                        int col = wn + nt * 8 + 2 * (lane & 3);
                        sst[r0 * 132 + col] = acc[mt][nt][0];
                        sst[r0 * 132 + col + 1] = acc[mt][nt][1];
                        sst[(r0 + 8) * 132 + col] = acc[mt][nt][2];
                        sst[(r0 + 8) * 132 + col + 1] = acc[mt][nt][3];
                    }
                }
            }
            __syncthreads();
            for (int c = c_lo + cstep0; c <= c_hi; c += 4) {
                int col0 = c * PP - bn;
                int lo = col0 > 0 ? col0 : 0;
                int hi = col0 + PP < 128 ? col0 + PP : 128;
                float best = -3.402823466e+38f;
                int bj = 0;
                for (int x = lo; x < hi; x++) {
                    float v = sst[r * 132 + x];
                    if (v > best) { best = v; bj = x - col0; }
                }
                unsigned long long pk =
                    ((unsigned long long)f2sortable(best) << 32) | (unsigned int)(15 - bj);
                unsigned long long* dst = &pack[(size_t)(bm + half * 64 + r) * CC + c];
                if (col0 >= 0 && col0 + PP <= 128) *dst = pk;   // interior: exclusive writer
                else atomicMax(dst, pk);                         // straddles tile boundary
            }
        }
    }
}

// ---------------- GCN HMMA GEMM (BKK=64, same proven mainloop): C[MPAD, DD] ------
__global__ __launch_bounds__(256) void gcn_hmma_kernel(const __nv_bfloat16* __restrict__ Abf,
                                                       const __nv_bfloat16* __restrict__ Bbf,
                                                       float* __restrict__ Cout) {
    extern __shared__ __align__(16) char smem_raw[];

    const int tid = threadIdx.x;
    const int wid = tid >> 5;
    const int lane = tid & 31;
    const int bm = blockIdx.y * 128;
    const int bn = blockIdx.x * 128;

    const int wm = (wid & 3) * 32;
    const int wn = (wid >> 2) * 64;

    const uint32_t sA0 = smem_to_u32(smem_raw);
    const uint32_t sA1 = sA0 + BUF_B;
    const uint32_t sB0 = sA0 + 2 * BUF_B;
    const uint32_t sB1 = sA0 + 3 * BUF_B;

    float acc[2][8][4];
#pragma unroll
    for (int mt = 0; mt < 2; mt++)
#pragma unroll
        for (int nt = 0; nt < 8; nt++)
#pragma unroll
            for (int e = 0; e < 4; e++) acc[mt][nt][e] = 0.0f;

    HMMA_MAINLOOP();

#pragma unroll
    for (int mt = 0; mt < 2; mt++) {
        int row0 = bm + wm + mt * 16 + (lane >> 2);
#pragma unroll
        for (int nt = 0; nt < 8; nt++) {
            int col = bn + wn + nt * 8 + 2 * (lane & 3);
            *(float2*)&Cout[(size_t)row0 * DD + col] =
                make_float2(acc[mt][nt][0], acc[mt][nt][1]);
            *(float2*)&Cout[(size_t)(row0 + 8) * DD + col] =
                make_float2(acc[mt][nt][2], acc[mt][nt][3]);
        }
    }
}

// ---------------- GCN aggregation + bias + relu ----------------
__global__ void agg_kernel(const float* __restrict__ xw,
                           float* __restrict__ outp,
                           const float* __restrict__ bias) {
    int n = blockIdx.x;
    int d = threadIdx.x;
    float dn = g_disqrt[n];
    float acc = dn * dn * xw[(size_t)n * DD + d];
    int beg = g_rowptr[n], end = g_rowptr[n + 1];
    for (int j = beg; j < end; j++) {
        int s = g_col[j];
        acc += dn * g_disqrt[s] * xw[(size_t)s * DD + d];
    }
    outp[(size_t)n * DD + d] = fmaxf(acc + bias[d], 0.0f);
}

// ---------------- per-row CE + usage scatter (consumes packed) ----------------
__global__ void ce_kernel(const unsigned long long* __restrict__ pack,
                          float* __restrict__ out,
                          const int* __restrict__ labels,
                          float* __restrict__ usage_pos,
                          float* __restrict__ usage_neg) {
    int b = blockIdx.x;
    const unsigned long long* prow = pack + (size_t)b * CC;
    float* orow = out + (size_t)b * CC;
    int t = threadIdx.x;
    __shared__ float smax[256];
    __shared__ int simax[256];
    float bm = -1e30f;
    int bi = 0x7fffffff;
    for (int c = t; c < CC; c += 256) {
        unsigned long long pk = prow[c];
        float v = 0.5f * (1.0f + sortable2f((unsigned int)(pk >> 32)));
        orow[c] = v;
        if (v > bm) { bm = v; bi = c; }
    }
    smax[t] = bm; simax[t] = bi;
    __syncthreads();
    for (int off = 128; off > 0; off >>= 1) {
        if (t < off) {
            float v2 = smax[t + off];
            int i2 = simax[t + off];
            if (v2 > smax[t] || (v2 == smax[t] && i2 < simax[t])) {
                smax[t] = v2; simax[t] = i2;
            }
        }
        __syncthreads();
    }
    float rowmax = smax[0];
    int pred = simax[0];
    __shared__ float ssum[256];
    float s = 0.0f;
    for (int c = t; c < CC; c += 256) s += expf(orow[c] - rowmax);
    ssum[t] = s;
    __syncthreads();
    for (int off = 128; off > 0; off >>= 1) {
        if (t < off) ssum[t] += ssum[t + off];
        __syncthreads();
    }
    if (t == 0) {
        int lab = labels[b];
        float x_lab = orow[lab];
        float lse = rowmax + logf(ssum[0]);
        if ((x_lab - rowmax) > MARGIN_F) {
            atomicAdd(&g_ce_sum, lse - x_lab);
            atomicAdd(&g_cnt, 1);
        }
        int jl = 15 - (int)(unsigned int)(prow[lab] & 0xFFFFFFFFull);
        atomicAdd(&usage_pos[lab * PP + jl], 1.0f);
        if (pred != lab) {
            int jp = 15 - (int)(unsigned int)(prow[pred] & 0xFFFFFFFFull);
            atomicAdd(&usage_neg[pred * PP + jp], 1.0f);
        }
    }
}

// ---------------- finalize loss ----------------
__global__ void finalize_kernel(float* __restrict__ out_loss) {
    __shared__ float sh[DD];
    int t = threadIdx.x;
    float v = g_s[t];
    sh[t] = v * v;
    __syncthreads();
    for (int off = 128; off > 0; off >>= 1) {
        if (t < off) sh[t] += sh[t + off];
        __syncthreads();
    }
    if (t == 0) {
        float disp = -sh[0] / ((float)NN * (float)NN);
        int cnt = g_cnt;
        float loss = (cnt == 0) ? 0.0f
                                : (g_ce_sum / (float)(cnt > 1 ? cnt : 1) + LW_F * disp);
        out_loss[0] = loss;
    }
}

// ---------------- launch ----------------
extern "C" void kernel_launch(void* const* d_in, const int* in_sizes, int n_in,
                              void* d_out, int out_size) {
    const float* hidden = (const float*)d_in[0];
    const int* labels = (const int*)d_in[1];
    const int* edge_index = (const int*)d_in[2];
    const float* node_features = (const float*)d_in[3];
    const float* w1 = (const float*)d_in[4];
    const float* b1 = (const float*)d_in[5];
    const float* w2 = (const float*)d_in[6];
    const float* b2 = (const float*)d_in[7];
    float* out = (float*)d_out;

    float* out_loss = out + (size_t)BB * CC;
    float* out_pos = out_loss + 1;
    float* out_neg = out_pos + NN;

    float *p_bufA = 0, *p_bufB = 0;
    __nv_bfloat16 *p_xs = 0, *p_ws = 0, *p_Abf = 0, *p_Bbf = 0;
    unsigned long long* p_pack = 0;
    cudaGetSymbolAddress((void**)&p_bufA, g_bufA);
    cudaGetSymbolAddress((void**)&p_bufB, g_bufB);
    cudaGetSymbolAddress((void**)&p_xs,   g_xs);
    cudaGetSymbolAddress((void**)&p_ws,   g_ws);
    cudaGetSymbolAddress((void**)&p_Abf,  g_Abf);
    cudaGetSymbolAddress((void**)&p_Bbf,  g_Bbf);
    cudaGetSymbolAddress((void**)&p_pack, g_pack);

    cudaFuncSetAttribute(sim_hmma_kernel, cudaFuncAttributeMaxDynamicSharedMemorySize, HMMA_SMEM);
    cudaFuncSetAttribute(gcn_hmma_kernel, cudaFuncAttributeMaxDynamicSharedMemorySize, HMMA_SMEM);

    // graph build + boundary pack reset
    init_kernel<<<(BB * CC + 255) / 256, 256>>>(out_loss);
    deg_kernel<<<(EE + 255) / 256, 256>>>(edge_index);
    scan_kernel<<<1, 1024>>>();   // scan + fused disqrt
    scatter_kernel<<<(EE + 255) / 256, 256>>>(edge_index);
    sort_kernel<<<(NN + 255) / 256, 256>>>();

    // GCN layer 1: xw = x @ w1 (bf16-split HMMA), aggregate + bias + relu
    split_x_kernel<<<NN, DD>>>(node_features, p_xs);
    split_w_kernel<<<DD, DD>>>(w1, p_ws);
    {
        dim3 grid(DD / 128, MPAD / 128);
        gcn_hmma_kernel<<<grid, 256, HMMA_SMEM>>>(p_xs, p_ws, p_bufA);
    }
    agg_kernel<<<NN, DD>>>(p_bufA, p_bufB, b1);

    // GCN layer 2
    split_x_kernel<<<NN, DD>>>(p_bufB, p_xs);
    split_w_kernel<<<DD, DD>>>(w2, p_ws);
    {
        dim3 grid(DD / 128, MPAD / 128);
        gcn_hmma_kernel<<<grid, 256, HMMA_SMEM>>>(p_xs, p_ws, p_bufA);
    }
    agg_kernel<<<NN, DD>>>(p_bufA, p_bufB, b2);

    // normalize + bf16 split:
    //   protos (B'): [hi | lo | hi]  -> hi2_off=512, lo_off=256 ; accumulate g_s
    //   hidden (A'): [hi | hi | lo]  -> hi2_off=256, lo_off=512
    norm_split_kernel<<<NN, DD>>>(p_bufB, p_Bbf, 512, 256, 1);
    norm_split_kernel<<<BB, DD>>>(hidden, p_Abf, 256, 512, 0);

    // sim GEMM (BKK=64, dynamic smem) with fused per-class max/argmax -> packed
    {
        dim3 grid(LDN / 128, BB / 128);
        sim_hmma_kernel<<<grid, 256, HMMA_SMEM>>>(p_Abf, p_Bbf, p_pack);
    }

    // CE + usage (decodes packed, writes output scores)
    ce_kernel<<<BB, 256>>>(p_pack, out, labels, out_pos, out_neg);

    // loss
    finalize_kernel<<<1, DD>>>(out_loss);
}

// round 15
// speedup vs baseline: 1.8684x; 1.1606x over previous
#include <cuda_runtime.h>
#include <cuda_bf16.h>
#include <math.h>
#include <stdint.h>

// Problem constants
#define BB 4096
#define CC 1000
#define PP 10
#define DD 256
#define NN 10000     // CC*PP
#define EE 160000
#define MARGIN_F (-0.1f)
#define LW_F (0.1f)

// bf16-split GEMM geometry
#define KTOT 768          // [hi | hi | lo] x [hi | lo | hi]
#define LDN 10112         // N padded to 79*128
#define MPAD 10112        // NN padded to 79*128

// ---------------- scratch (device globals; no runtime allocation) ----------------
__device__ float g_bufA[MPAD * DD];             // GEMM output scratch
__device__ __nv_bfloat16 g_xs[MPAD * KTOT];     // GCN input split (pad rows stay 0)
__device__ __nv_bfloat16 g_ws[DD * KTOT];       // weight split (transposed)
__device__ __nv_bfloat16 g_Abf[BB * KTOT];      // hidden_norm split
__device__ __nv_bfloat16 g_Bbf[LDN * KTOT];     // proto_norm split (pad rows stay 0)
__device__ unsigned long long g_pack[(size_t)BB * CC]; // packed (sortable max, 15-idx)
__device__ float g_disqrt[NN];
__device__ int   g_deg[NN];
__device__ int   g_rowptr[NN + 1];
__device__ int   g_col[EE];
__device__ int   g_cursor[NN];
__device__ float g_s[DD];
__device__ float g_ce_sum;
__device__ int   g_cnt;

// boundary classes: c mod 64 in {12,25,38,51}  (10c mod 128 >= 119 among even residues)
__constant__ int c_btbl[4] = {12, 25, 38, 51};

// ---------------- helpers ----------------
__device__ __forceinline__ uint32_t smem_to_u32(const void* p) {
    uint32_t a;
    asm("{ .reg .u64 t; cvta.to.shared.u64 t, %1; cvt.u32.u64 %0, t; }" : "=r"(a) : "l"(p));
    return a;
}
__device__ __forceinline__ void cp_async16(uint32_t dst, const void* src) {
    asm volatile("cp.async.cg.shared.global [%0], [%1], 16;" :: "r"(dst), "l"(src) : "memory");
}
__device__ __forceinline__ void cp_commit() {
    asm volatile("cp.async.commit_group;" ::: "memory");
}
__device__ __forceinline__ void cp_wait0() {
    asm volatile("cp.async.wait_group 0;" ::: "memory");
}
__device__ __forceinline__ void ldm_x4(uint32_t& r0, uint32_t& r1, uint32_t& r2, uint32_t& r3,
                                       uint32_t addr) {
    asm volatile("ldmatrix.sync.aligned.m8n8.x4.shared.b16 {%0,%1,%2,%3}, [%4];"
                 : "=r"(r0), "=r"(r1), "=r"(r2), "=r"(r3) : "r"(addr));
}
__device__ __forceinline__ void mma16816(float* d, const uint32_t* a, const uint32_t* b) {
    asm volatile(
        "mma.sync.aligned.m16n8k16.row.col.f32.bf16.bf16.f32 "
        "{%0,%1,%2,%3}, {%4,%5,%6,%7}, {%8,%9}, {%0,%1,%2,%3};"
        : "+f"(d[0]), "+f"(d[1]), "+f"(d[2]), "+f"(d[3])
        : "r"(a[0]), "r"(a[1]), "r"(a[2]), "r"(a[3]), "r"(b[0]), "r"(b[1]));
}
__device__ __forceinline__ unsigned int f2sortable(float f) {
    unsigned int b = __float_as_uint(f);
    return (b & 0x80000000u) ? ~b : (b | 0x80000000u);
}
__device__ __forceinline__ float sortable2f(unsigned int e) {
    unsigned int b = (e & 0x80000000u) ? (e ^ 0x80000000u) : ~e;
    return __uint_as_float(b);
}

// ---------------- init ----------------
__global__ void init_kernel(float* out_tail) {
    int i = blockIdx.x * blockDim.x + threadIdx.x;
    if (i < NN) { g_deg[i] = 0; g_cursor[i] = 0; }
    if (i < DD) g_s[i] = 0.0f;
    if (i == 0) { g_ce_sum = 0.0f; g_cnt = 0; }
    if (i < 1 + 2 * NN) out_tail[i] = 0.0f;
    // compact boundary pack reset: i in [0, BB*64)
    if (i < BB * 64) {
        int b = i >> 6;
        int j = i & 63;
        int c = (j >> 2) * 64 + c_btbl[j & 3];
        if (c < CC) g_pack[(size_t)b * CC + c] = 0ull;
    }
}

// ---------------- degree ----------------
__global__ void deg_kernel(const int* __restrict__ ei) {
    int e = blockIdx.x * blockDim.x + threadIdx.x;
    if (e < EE) atomicAdd(&g_deg[ei[EE + e]], 1);
}

// ---------------- exclusive scan (shfl-based) + fused disqrt ----------------
__global__ void scan_kernel() {
    const int T = 1024;
    const int CH = (NN + T - 1) / T;   // 10
    __shared__ int wsum[32];
    int t = threadIdx.x;
    int lane = t & 31, w = t >> 5;
    int base = t * CH;
    int local[CH];
    int s = 0;
#pragma unroll
    for (int i = 0; i < CH; i++) {
        int idx = base + i;
        local[i] = (idx < NN) ? g_deg[idx] : 0;
        s += local[i];
    }
    int v = s;
#pragma unroll
    for (int off = 1; off < 32; off <<= 1) {
        int u = __shfl_up_sync(0xFFFFFFFFu, v, off);
        if (lane >= off) v += u;
    }
    if (lane == 31) wsum[w] = v;
    __syncthreads();
    if (w == 0) {
        int x = wsum[lane];
#pragma unroll
        for (int off = 1; off < 32; off <<= 1) {
            int u = __shfl_up_sync(0xFFFFFFFFu, x, off);
            if (lane >= off) x += u;
        }
        wsum[lane] = x;
    }
    __syncthreads();
    int run = v - s + (w > 0 ? wsum[w - 1] : 0);
#pragma unroll
    for (int i = 0; i < CH; i++) {
        int idx = base + i;
        if (idx < NN) { g_rowptr[idx] = run; run += local[i]; }
    }
    if (t == T - 1) g_rowptr[NN] = run;
    for (int n = t; n < NN; n += T) {
        float x = (float)(g_deg[n] + 1);
        float r = rsqrtf(x);
        r = r * (1.5f - 0.5f * x * r * r);
        g_disqrt[n] = r;
    }
}

__global__ void scatter_kernel(const int* __restrict__ ei) {
    int e = blockIdx.x * blockDim.x + threadIdx.x;
    if (e < EE) {
        int d = ei[EE + e];
        int pos = g_rowptr[d] + atomicAdd(&g_cursor[d], 1);
        g_col[pos] = ei[e];
    }
}

// ---------------- bf16 split kernels ----------------
__global__ void split_x_kernel(const float* __restrict__ in, __nv_bfloat16* __restrict__ outp) {
    int r = blockIdx.x;
    int t = threadIdx.x;
    float v = in[(size_t)r * DD + t];
    __nv_bfloat16 hi = __float2bfloat16(v);
    __nv_bfloat16 lo = __float2bfloat16(v - __bfloat162float(hi));
    size_t base = (size_t)r * KTOT;
    outp[base + t] = hi;
    outp[base + DD + t] = hi;
    outp[base + 2 * DD + t] = lo;
}

__global__ void split_w_kernel(const float* __restrict__ w, __nv_bfloat16* __restrict__ outp) {
    int n = blockIdx.x;   // output col
    int k = threadIdx.x;  // input dim
    float v = w[(size_t)k * DD + n];
    __nv_bfloat16 hi = __float2bfloat16(v);
    __nv_bfloat16 lo = __float2bfloat16(v - __bfloat162float(hi));
    size_t base = (size_t)n * KTOT;
    outp[base + k] = hi;
    outp[base + DD + k] = lo;
    outp[base + 2 * DD + k] = hi;
}

// ---------------- row L2 normalize + bf16 split (hidden -> A': [hi|hi|lo]) --------
__global__ void norm_split_kernel(const float* __restrict__ in,
                                  __nv_bfloat16* __restrict__ outp) {
    int r = blockIdx.x;
    int t = threadIdx.x;
    float v = in[(size_t)r * DD + t];
    __shared__ float sh[DD];
    sh[t] = v * v;
    __syncthreads();
    for (int off = 128; off > 0; off >>= 1) {
        if (t < off) sh[t] += sh[t + off];
        __syncthreads();
    }
    float nrm = sqrtf(sh[0]);
    float val = v / fmaxf(nrm, 1e-12f);
    __nv_bfloat16 hi = __float2bfloat16(val);
    __nv_bfloat16 lo = __float2bfloat16(val - __bfloat162float(hi));
    size_t base = (size_t)r * KTOT;
    outp[base + t] = hi;
    outp[base + DD + t] = hi;
    outp[base + 2 * DD + t] = lo;
}

// ---------------- GCN agg + bias + relu, fused bf16 split ([hi|hi|lo]) ------------
__global__ void agg_split_kernel(const float* __restrict__ xw,
                                 __nv_bfloat16* __restrict__ outp,
                                 const float* __restrict__ bias) {
    int n = blockIdx.x;
    int d = threadIdx.x;
    float dn = g_disqrt[n];
    float acc = dn * dn * xw[(size_t)n * DD + d];
    int beg = g_rowptr[n], end = g_rowptr[n + 1];
    for (int j = beg; j < end; j++) {
        int s = g_col[j];
        acc += dn * g_disqrt[s] * xw[(size_t)s * DD + d];
    }
    float act = fmaxf(acc + bias[d], 0.0f);
    __nv_bfloat16 hi = __float2bfloat16(act);
    __nv_bfloat16 lo = __float2bfloat16(act - __bfloat162float(hi));
    size_t base = (size_t)n * KTOT;
    outp[base + d] = hi;
    outp[base + DD + d] = hi;
    outp[base + 2 * DD + d] = lo;
}

// ---------------- GCN agg + bias + relu + L2 norm + split (protos: [hi|lo|hi]) ----
__global__ void agg_norm_split_kernel(const float* __restrict__ xw,
                                      __nv_bfloat16* __restrict__ outp,
                                      const float* __restrict__ bias) {
    int n = blockIdx.x;
    int d = threadIdx.x;
    float dn = g_disqrt[n];
    float acc = dn * dn * xw[(size_t)n * DD + d];
    int beg = g_rowptr[n], end = g_rowptr[n + 1];
    for (int j = beg; j < end; j++) {
        int s = g_col[j];
        acc += dn * g_disqrt[s] * xw[(size_t)s * DD + d];
    }
    float act = fmaxf(acc + bias[d], 0.0f);
    __shared__ float sh[DD];
    sh[d] = act * act;
    __syncthreads();
    for (int off = 128; off > 0; off >>= 1) {
        if (d < off) sh[d] += sh[d + off];
        __syncthreads();
    }
    float nrm = sqrtf(sh[0]);
    float val = act / fmaxf(nrm, 1e-12f);
    __nv_bfloat16 hi = __float2bfloat16(val);
    __nv_bfloat16 lo = __float2bfloat16(val - __bfloat162float(hi));
    size_t base = (size_t)n * KTOT;
    outp[base + d] = hi;
    outp[base + DD + d] = lo;
    outp[base + 2 * DD + d] = hi;
    atomicAdd(&g_s[d], val);
}

// ---------------- shared BKK=64 HMMA tile geometry -------------------
#define BKK 64
#define LDK 72            // 144B row stride: 8-row ldmatrix phase covers all 32 banks
#define KITERS (KTOT / BKK)   // 12
#define BUF_B (128 * LDK * 2) // 18432 per matrix per stage
#define HMMA_SMEM (4 * BUF_B) // 73728: 2 stages x (A,B)

#define HMMA_LOAD(dstA, dstB, k0) do {                                             \
        _Pragma("unroll")                                                          \
        for (int q = 0; q < 4; q++) {                                              \
            int chunk = tid + q * 256;                                             \
            int row = chunk >> 3;                                                  \
            int cs = chunk & 7;                                                    \
            uint32_t off = (uint32_t)(row * (LDK * 2) + cs * 16);                  \
            cp_async16((dstA) + off, &Abf[(size_t)(bm + row) * KTOT + (k0) + cs * 8]); \
            cp_async16((dstB) + off, &Bbf[(size_t)(bn + row) * KTOT + (k0) + cs * 8]); \
        }                                                                          \
    } while (0)

#define HMMA_MAINLOOP()                                                            \
    HMMA_LOAD(sA0, sB0, 0);                                                        \
    cp_commit();                                                                   \
    for (int kb = 0; kb < KITERS; kb++) {                                          \
        cp_wait0();                                                                \
        __syncthreads();                                                           \
        if (kb + 1 < KITERS) {                                                     \
            uint32_t dA = ((kb + 1) & 1) ? sA1 : sA0;                              \
            uint32_t dB = ((kb + 1) & 1) ? sB1 : sB0;                              \
            HMMA_LOAD(dA, dB, (kb + 1) * BKK);                                     \
            cp_commit();                                                           \
        }                                                                          \
        uint32_t aBase = (kb & 1) ? sA1 : sA0;                                     \
        uint32_t bBase = (kb & 1) ? sB1 : sB0;                                     \
        _Pragma("unroll")                                                          \
        for (int ks = 0; ks < BKK; ks += 16) {                                     \
            uint32_t afr[2][4];                                                    \
            _Pragma("unroll")                                                      \
            for (int mt = 0; mt < 2; mt++) {                                       \
                int r = wm + mt * 16 + (lane & 15);                                \
                int c = ks + 8 * (lane >> 4);                                      \
                ldm_x4(afr[mt][0], afr[mt][1], afr[mt][2], afr[mt][3],             \
                       aBase + (uint32_t)(r * LDK + c) * 2);                       \
            }                                                                      \
            uint32_t bfr[8][2];                                                    \
            _Pragma("unroll")                                                      \
            for (int bt = 0; bt < 4; bt++) {                                       \
                int r = wn + bt * 16 + ((lane >> 4) & 1) * 8 + (lane & 7);         \
                int c = ks + ((lane >> 3) & 1) * 8;                                \
                ldm_x4(bfr[bt * 2][0], bfr[bt * 2][1],                             \
                       bfr[bt * 2 + 1][0], bfr[bt * 2 + 1][1],                     \
                       bBase + (uint32_t)(r * LDK + c) * 2);                       \
            }                                                                      \
            _Pragma("unroll")                                                      \
            for (int mt = 0; mt < 2; mt++)                                         \
                _Pragma("unroll")                                                  \
                for (int nt = 0; nt < 8; nt++)                                     \
                    mma16816(acc[mt][nt], afr[mt], bfr[nt]);                       \
        }                                                                          \
        __syncthreads();                                                           \
    }

// ---------------- bf16 HMMA sim GEMM + fused per-class max -------------------
__global__ __launch_bounds__(256) void sim_hmma_kernel(const __nv_bfloat16* __restrict__ Abf,
                                                       const __nv_bfloat16* __restrict__ Bbf,
                                                       unsigned long long* __restrict__ pack) {
    extern __shared__ __align__(16) char smem_raw[];

    const int tid = threadIdx.x;
    const int wid = tid >> 5;
    const int lane = tid & 31;
    const int bm = blockIdx.y * 128;
    const int bn = blockIdx.x * 128;

    const int wm = (wid & 3) * 32;   // warp m offset
    const int wn = (wid >> 2) * 64;  // warp n offset

    const uint32_t sA0 = smem_to_u32(smem_raw);
    const uint32_t sA1 = sA0 + BUF_B;
    const uint32_t sB0 = sA0 + 2 * BUF_B;
    const uint32_t sB1 = sA0 + 3 * BUF_B;

    float acc[2][8][4];
#pragma unroll
    for (int mt = 0; mt < 2; mt++)
#pragma unroll
        for (int nt = 0; nt < 8; nt++)
#pragma unroll
            for (int e = 0; e < 4; e++) acc[mt][nt][e] = 0.0f;

    HMMA_MAINLOOP();

    // -------- fused epilogue: per-class (groups of PP cols) max + argmax --------
    {
        float* sst = (float*)smem_raw;   // 64 x 132 floats staging
        const int lwm = wm & 63;
        int c_lo = bn / PP;
        int c_hi = (bn + 127) / PP;
        if (c_hi > CC - 1) c_hi = CC - 1;
        const int r = tid >> 2;          // 0..63
        const int cstep0 = tid & 3;
#pragma unroll
        for (int half = 0; half < 2; half++) {
            __syncthreads();
            if ((wm < 64) == (half == 0)) {
#pragma unroll
                for (int mt = 0; mt < 2; mt++) {
                    int r0 = lwm + mt * 16 + (lane >> 2);
#pragma unroll
                    for (int nt = 0; nt < 8; nt++) {
                        int col = wn + nt * 8 + 2 * (lane & 3);
                        sst[r0 * 132 + col] = acc[mt][nt][0];
                        sst[r0 * 132 + col + 1] = acc[mt][nt][1];
                        sst[(r0 + 8) * 132 + col] = acc[mt][nt][2];
                        sst[(r0 + 8) * 132 + col + 1] = acc[mt][nt][3];
                    }
                }
            }
            __syncthreads();
            for (int c = c_lo + cstep0; c <= c_hi; c += 4) {
                int col0 = c * PP - bn;
                int lo = col0 > 0 ? col0 : 0;
                int hi = col0 + PP < 128 ? col0 + PP : 128;
                float best = -3.402823466e+38f;
                int bj = 0;
                for (int x = lo; x < hi; x++) {
                    float v = sst[r * 132 + x];
                    if (v > best) { best = v; bj = x - col0; }
                }
                unsigned long long pk =
                    ((unsigned long long)f2sortable(best) << 32) | (unsigned int)(15 - bj);
                unsigned long long* dst = &pack[(size_t)(bm + half * 64 + r) * CC + c];
                if (col0 >= 0 && col0 + PP <= 128) *dst = pk;   // interior: exclusive writer
                else atomicMax(dst, pk);                         // straddles tile boundary
            }
        }
    }
}

// ---------------- GCN HMMA GEMM (BKK=64 mainloop): C[MPAD, DD] ------
__global__ __launch_bounds__(256) void gcn_hmma_kernel(const __nv_bfloat16* __restrict__ Abf,
                                                       const __nv_bfloat16* __restrict__ Bbf,
                                                       float* __restrict__ Cout) {
    extern __shared__ __align__(16) char smem_raw[];

    const int tid = threadIdx.x;
    const int wid = tid >> 5;
    const int lane = tid & 31;
    const int bm = blockIdx.y * 128;
    const int bn = blockIdx.x * 128;

    const int wm = (wid & 3) * 32;
    const int wn = (wid >> 2) * 64;

    const uint32_t sA0 = smem_to_u32(smem_raw);
    const uint32_t sA1 = sA0 + BUF_B;
    const uint32_t sB0 = sA0 + 2 * BUF_B;
    const uint32_t sB1 = sA0 + 3 * BUF_B;

    float acc[2][8][4];
#pragma unroll
    for (int mt = 0; mt < 2; mt++)
#pragma unroll
        for (int nt = 0; nt < 8; nt++)
#pragma unroll
            for (int e = 0; e < 4; e++) acc[mt][nt][e] = 0.0f;

    HMMA_MAINLOOP();

#pragma unroll
    for (int mt = 0; mt < 2; mt++) {
        int row0 = bm + wm + mt * 16 + (lane >> 2);
#pragma unroll
        for (int nt = 0; nt < 8; nt++) {
            int col = bn + wn + nt * 8 + 2 * (lane & 3);
            *(float2*)&Cout[(size_t)row0 * DD + col] =
                make_float2(acc[mt][nt][0], acc[mt][nt][1]);
            *(float2*)&Cout[(size_t)(row0 + 8) * DD + col] =
                make_float2(acc[mt][nt][2], acc[mt][nt][3]);
        }
    }
}

// ---------------- per-row CE + usage scatter (consumes packed) ----------------
__global__ void ce_kernel(const unsigned long long* __restrict__ pack,
                          float* __restrict__ out,
                          const int* __restrict__ labels,
                          float* __restrict__ usage_pos,
                          float* __restrict__ usage_neg) {
    int b = blockIdx.x;
    const unsigned long long* prow = pack + (size_t)b * CC;
    float* orow = out + (size_t)b * CC;
    int t = threadIdx.x;
    __shared__ float smax[256];
    __shared__ int simax[256];
    float bm = -1e30f;
    int bi = 0x7fffffff;
    for (int c = t; c < CC; c += 256) {
        unsigned long long pk = prow[c];
        float v = 0.5f * (1.0f + sortable2f((unsigned int)(pk >> 32)));
        orow[c] = v;
        if (v > bm) { bm = v; bi = c; }
    }
    smax[t] = bm; simax[t] = bi;
    __syncthreads();
    for (int off = 128; off > 0; off >>= 1) {
        if (t < off) {
            float v2 = smax[t + off];
            int i2 = simax[t + off];
            if (v2 > smax[t] || (v2 == smax[t] && i2 < simax[t])) {
                smax[t] = v2; simax[t] = i2;
            }
        }
        __syncthreads();
    }
    float rowmax = smax[0];
    int pred = simax[0];
    __shared__ float ssum[256];
    float s = 0.0f;
    for (int c = t; c < CC; c += 256) s += expf(orow[c] - rowmax);
    ssum[t] = s;
    __syncthreads();
    for (int off = 128; off > 0; off >>= 1) {
        if (t < off) ssum[t] += ssum[t + off];
        __syncthreads();
    }
    if (t == 0) {
        int lab = labels[b];
        float x_lab = orow[lab];
        float lse = rowmax + logf(ssum[0]);
        if ((x_lab - rowmax) > MARGIN_F) {
            atomicAdd(&g_ce_sum, lse - x_lab);
            atomicAdd(&g_cnt, 1);
        }
        int jl = 15 - (int)(unsigned int)(prow[lab] & 0xFFFFFFFFull);
        atomicAdd(&usage_pos[lab * PP + jl], 1.0f);
        if (pred != lab) {
            int jp = 15 - (int)(unsigned int)(prow[pred] & 0xFFFFFFFFull);
            atomicAdd(&usage_neg[pred * PP + jp], 1.0f);
        }
    }
}

// ---------------- finalize loss ----------------
__global__ void finalize_kernel(float* __restrict__ out_loss) {
    __shared__ float sh[DD];
    int t = threadIdx.x;
    float v = g_s[t];
    sh[t] = v * v;
    __syncthreads();
    for (int off = 128; off > 0; off >>= 1) {
        if (t < off) sh[t] += sh[t + off];
        __syncthreads();
    }
    if (t == 0) {
        float disp = -sh[0] / ((float)NN * (float)NN);
        int cnt = g_cnt;
        float loss = (cnt == 0) ? 0.0f
                                : (g_ce_sum / (float)(cnt > 1 ? cnt : 1) + LW_F * disp);
        out_loss[0] = loss;
    }
}

// ---------------- launch ----------------
extern "C" void kernel_launch(void* const* d_in, const int* in_sizes, int n_in,
                              void* d_out, int out_size) {
    const float* hidden = (const float*)d_in[0];
    const int* labels = (const int*)d_in[1];
    const int* edge_index = (const int*)d_in[2];
    const float* node_features = (const float*)d_in[3];
    const float* w1 = (const float*)d_in[4];
    const float* b1 = (const float*)d_in[5];
    const float* w2 = (const float*)d_in[6];
    const float* b2 = (const float*)d_in[7];
    float* out = (float*)d_out;

    float* out_loss = out + (size_t)BB * CC;
    float* out_pos = out_loss + 1;
    float* out_neg = out_pos + NN;

    float* p_bufA = 0;
    __nv_bfloat16 *p_xs = 0, *p_ws = 0, *p_Abf = 0, *p_Bbf = 0;
    unsigned long long* p_pack = 0;
    cudaGetSymbolAddress((void**)&p_bufA, g_bufA);
    cudaGetSymbolAddress((void**)&p_xs,   g_xs);
    cudaGetSymbolAddress((void**)&p_ws,   g_ws);
    cudaGetSymbolAddress((void**)&p_Abf,  g_Abf);
    cudaGetSymbolAddress((void**)&p_Bbf,  g_Bbf);
    cudaGetSymbolAddress((void**)&p_pack, g_pack);

    cudaFuncSetAttribute(sim_hmma_kernel, cudaFuncAttributeMaxDynamicSharedMemorySize, HMMA_SMEM);
    cudaFuncSetAttribute(gcn_hmma_kernel, cudaFuncAttributeMaxDynamicSharedMemorySize, HMMA_SMEM);

    // graph build + compact boundary pack reset
    init_kernel<<<(BB * 64 + 255) / 256, 256>>>(out_loss);
    deg_kernel<<<(EE + 255) / 256, 256>>>(edge_index);
    scan_kernel<<<1, 1024>>>();   // scan + fused disqrt
    scatter_kernel<<<(EE + 255) / 256, 256>>>(edge_index);

    // GCN layer 1: split x, xw = x @ w1 (HMMA), agg+relu fused with layer-2 split
    split_x_kernel<<<NN, DD>>>(node_features, p_xs);
    split_w_kernel<<<DD, DD>>>(w1, p_ws);
    {
        dim3 grid(DD / 128, MPAD / 128);
        gcn_hmma_kernel<<<grid, 256, HMMA_SMEM>>>(p_xs, p_ws, p_bufA);
    }
    agg_split_kernel<<<NN, DD>>>(p_bufA, p_xs, b1);   // layer-2 input split, in place

    // GCN layer 2: xw2 GEMM, then agg+relu+norm+split (protos) fused
    split_w_kernel<<<DD, DD>>>(w2, p_ws);
    {
        dim3 grid(DD / 128, MPAD / 128);
        gcn_hmma_kernel<<<grid, 256, HMMA_SMEM>>>(p_xs, p_ws, p_bufA);
    }
    agg_norm_split_kernel<<<NN, DD>>>(p_bufA, p_Bbf, b2);  // protos [hi|lo|hi] + g_s

    // hidden normalize + split (A': [hi|hi|lo])
    norm_split_kernel<<<BB, DD>>>(hidden, p_Abf);

    // sim GEMM (BKK=64) with fused per-class max/argmax -> packed
    {
        dim3 grid(LDN / 128, BB / 128);
        sim_hmma_kernel<<<grid, 256, HMMA_SMEM>>>(p_Abf, p_Bbf, p_pack);
    }

    // CE + usage (decodes packed, writes output scores)
    ce_kernel<<<BB, 256>>>(p_pack, out, labels, out_pos, out_neg);

    // loss
    finalize_kernel<<<1, DD>>>(out_loss);
}

// round 16
// speedup vs baseline: 1.9178x; 1.0264x over previous
#include <cuda_runtime.h>
#include <cuda_bf16.h>
#include <math.h>
#include <stdint.h>

// Problem constants
#define BB 4096
#define CC 1000
#define PP 10
#define DD 256
#define NN 10000     // CC*PP
#define EE 160000
#define MARGIN_F (-0.1f)
#define LW_F (0.1f)

// bf16-split GEMM geometry
#define KTOT 768          // [hi | hi | lo] x [hi | lo | hi]
#define LDN 10112         // N padded to 79*128
#define MPAD 10112        // NN padded to 79*128

// ---------------- scratch (device globals; no runtime allocation) ----------------
__device__ float g_bufA[MPAD * DD];             // GEMM output scratch
__device__ __nv_bfloat16 g_xs[MPAD * KTOT];     // GCN input split (pad rows stay 0)
__device__ __nv_bfloat16 g_ws[DD * KTOT];       // weight split (transposed)
__device__ __nv_bfloat16 g_Abf[BB * KTOT];      // hidden_norm split
__device__ __nv_bfloat16 g_Bbf[LDN * KTOT];     // proto_norm split (pad rows stay 0)
__device__ unsigned long long g_pack[(size_t)BB * CC]; // packed (sortable max, 15-idx)
__device__ float g_disqrt[NN];
__device__ int   g_deg[NN];
__device__ int   g_rowptr[NN + 1];
__device__ int   g_col[EE];
__device__ int   g_cursor[NN];
__device__ float g_s[DD];
__device__ float g_ce_sum;
__device__ int   g_cnt;

// boundary classes: c mod 64 in {12,25,38,51}
__constant__ int c_btbl[4] = {12, 25, 38, 51};

// ---------------- helpers ----------------
__device__ __forceinline__ uint32_t smem_to_u32(const void* p) {
    uint32_t a;
    asm("{ .reg .u64 t; cvta.to.shared.u64 t, %1; cvt.u32.u64 %0, t; }" : "=r"(a) : "l"(p));
    return a;
}
__device__ __forceinline__ void cp_async16(uint32_t dst, const void* src) {
    asm volatile("cp.async.cg.shared.global [%0], [%1], 16;" :: "r"(dst), "l"(src) : "memory");
}
__device__ __forceinline__ void cp_commit() {
    asm volatile("cp.async.commit_group;" ::: "memory");
}
__device__ __forceinline__ void cp_wait0() {
    asm volatile("cp.async.wait_group 0;" ::: "memory");
}
__device__ __forceinline__ void ldm_x4(uint32_t& r0, uint32_t& r1, uint32_t& r2, uint32_t& r3,
                                       uint32_t addr) {
    asm volatile("ldmatrix.sync.aligned.m8n8.x4.shared.b16 {%0,%1,%2,%3}, [%4];"
                 : "=r"(r0), "=r"(r1), "=r"(r2), "=r"(r3) : "r"(addr));
}
__device__ __forceinline__ void mma16816(float* d, const uint32_t* a, const uint32_t* b) {
    asm volatile(
        "mma.sync.aligned.m16n8k16.row.col.f32.bf16.bf16.f32 "
        "{%0,%1,%2,%3}, {%4,%5,%6,%7}, {%8,%9}, {%0,%1,%2,%3};"
        : "+f"(d[0]), "+f"(d[1]), "+f"(d[2]), "+f"(d[3])
        : "r"(a[0]), "r"(a[1]), "r"(a[2]), "r"(a[3]), "r"(b[0]), "r"(b[1]));
}
__device__ __forceinline__ unsigned int f2sortable(float f) {
    unsigned int b = __float_as_uint(f);
    return (b & 0x80000000u) ? ~b : (b | 0x80000000u);
}
__device__ __forceinline__ float sortable2f(unsigned int e) {
    unsigned int b = (e & 0x80000000u) ? (e ^ 0x80000000u) : ~e;
    return __uint_as_float(b);
}

// ---------------- init ----------------
__global__ void init_kernel(float* out_tail) {
    int i = blockIdx.x * blockDim.x + threadIdx.x;
    if (i < NN) { g_deg[i] = 0; g_cursor[i] = 0; }
    if (i < DD) g_s[i] = 0.0f;
    if (i == 0) { g_ce_sum = 0.0f; g_cnt = 0; }
    if (i < 1 + 2 * NN) out_tail[i] = 0.0f;
    if (i < BB * 64) {
        int b = i >> 6;
        int j = i & 63;
        int c = (j >> 2) * 64 + c_btbl[j & 3];
        if (c < CC) g_pack[(size_t)b * CC + c] = 0ull;
    }
}

// ---------------- degree ----------------
__global__ void deg_kernel(const int* __restrict__ ei) {
    int e = blockIdx.x * blockDim.x + threadIdx.x;
    if (e < EE) atomicAdd(&g_deg[ei[EE + e]], 1);
}

// ---------------- exclusive scan (shfl-based) + fused disqrt ----------------
__global__ void scan_kernel() {
    const int T = 1024;
    const int CH = (NN + T - 1) / T;   // 10
    __shared__ int wsum[32];
    int t = threadIdx.x;
    int lane = t & 31, w = t >> 5;
    int base = t * CH;
    int local[CH];
    int s = 0;
#pragma unroll
    for (int i = 0; i < CH; i++) {
        int idx = base + i;
        local[i] = (idx < NN) ? g_deg[idx] : 0;
        s += local[i];
    }
    int v = s;
#pragma unroll
    for (int off = 1; off < 32; off <<= 1) {
        int u = __shfl_up_sync(0xFFFFFFFFu, v, off);
        if (lane >= off) v += u;
    }
    if (lane == 31) wsum[w] = v;
    __syncthreads();
    if (w == 0) {
        int x = wsum[lane];
#pragma unroll
        for (int off = 1; off < 32; off <<= 1) {
            int u = __shfl_up_sync(0xFFFFFFFFu, x, off);
            if (lane >= off) x += u;
        }
        wsum[lane] = x;
    }
    __syncthreads();
    int run = v - s + (w > 0 ? wsum[w - 1] : 0);
#pragma unroll
    for (int i = 0; i < CH; i++) {
        int idx = base + i;
        if (idx < NN) { g_rowptr[idx] = run; run += local[i]; }
    }
    if (t == T - 1) g_rowptr[NN] = run;
    for (int n = t; n < NN; n += T) {
        float x = (float)(g_deg[n] + 1);
        float r = rsqrtf(x);
        r = r * (1.5f - 0.5f * x * r * r);
        g_disqrt[n] = r;
    }
}

__global__ void scatter_kernel(const int* __restrict__ ei) {
    int e = blockIdx.x * blockDim.x + threadIdx.x;
    if (e < EE) {
        int d = ei[EE + e];
        int pos = g_rowptr[d] + atomicAdd(&g_cursor[d], 1);
        g_col[pos] = ei[e];
    }
}

// ---------------- bf16 split kernels ----------------
__global__ void split_x_kernel(const float* __restrict__ in, __nv_bfloat16* __restrict__ outp) {
    int r = blockIdx.x;
    int t = threadIdx.x;
    float v = in[(size_t)r * DD + t];
    __nv_bfloat16 hi = __float2bfloat16(v);
    __nv_bfloat16 lo = __float2bfloat16(v - __bfloat162float(hi));
    size_t base = (size_t)r * KTOT;
    outp[base + t] = hi;
    outp[base + DD + t] = hi;
    outp[base + 2 * DD + t] = lo;
}

__global__ void split_w_kernel(const float* __restrict__ w, __nv_bfloat16* __restrict__ outp) {
    int n = blockIdx.x;   // output col
    int k = threadIdx.x;  // input dim
    float v = w[(size_t)k * DD + n];
    __nv_bfloat16 hi = __float2bfloat16(v);
    __nv_bfloat16 lo = __float2bfloat16(v - __bfloat162float(hi));
    size_t base = (size_t)n * KTOT;
    outp[base + k] = hi;
    outp[base + DD + k] = lo;
    outp[base + 2 * DD + k] = hi;
}

// ---------------- row L2 normalize + bf16 split (hidden -> A': [hi|hi|lo]) --------
__global__ void norm_split_kernel(const float* __restrict__ in,
                                  __nv_bfloat16* __restrict__ outp) {
    int r = blockIdx.x;
    int t = threadIdx.x;
    float v = in[(size_t)r * DD + t];
    __shared__ float sh[DD];
    sh[t] = v * v;
    __syncthreads();
    for (int off = 128; off > 0; off >>= 1) {
        if (t < off) sh[t] += sh[t + off];
        __syncthreads();
    }
    float nrm = sqrtf(sh[0]);
    float val = v / fmaxf(nrm, 1e-12f);
    __nv_bfloat16 hi = __float2bfloat16(val);
    __nv_bfloat16 lo = __float2bfloat16(val - __bfloat162float(hi));
    size_t base = (size_t)r * KTOT;
    outp[base + t] = hi;
    outp[base + DD + t] = hi;
    outp[base + 2 * DD + t] = lo;
}

// ---------------- GCN agg + bias + relu, fused bf16 split ([hi|hi|lo]) ------------
__global__ void agg_split_kernel(const float* __restrict__ xw,
                                 __nv_bfloat16* __restrict__ outp,
                                 const float* __restrict__ bias) {
    int n = blockIdx.x;
    int d = threadIdx.x;
    float dn = g_disqrt[n];
    float acc = dn * dn * xw[(size_t)n * DD + d];
    int beg = g_rowptr[n], end = g_rowptr[n + 1];
    for (int j = beg; j < end; j++) {
        int s = g_col[j];
        acc += dn * g_disqrt[s] * xw[(size_t)s * DD + d];
    }
    float act = fmaxf(acc + bias[d], 0.0f);
    __nv_bfloat16 hi = __float2bfloat16(act);
    __nv_bfloat16 lo = __float2bfloat16(act - __bfloat162float(hi));
    size_t base = (size_t)n * KTOT;
    outp[base + d] = hi;
    outp[base + DD + d] = hi;
    outp[base + 2 * DD + d] = lo;
}

// ---------------- GCN agg + bias + relu + L2 norm + split (protos: [hi|lo|hi]) ----
__global__ void agg_norm_split_kernel(const float* __restrict__ xw,
                                      __nv_bfloat16* __restrict__ outp,
                                      const float* __restrict__ bias) {
    int n = blockIdx.x;
    int d = threadIdx.x;
    float dn = g_disqrt[n];
    float acc = dn * dn * xw[(size_t)n * DD + d];
    int beg = g_rowptr[n], end = g_rowptr[n + 1];
    for (int j = beg; j < end; j++) {
        int s = g_col[j];
        acc += dn * g_disqrt[s] * xw[(size_t)s * DD + d];
    }
    float act = fmaxf(acc + bias[d], 0.0f);
    __shared__ float sh[DD];
    sh[d] = act * act;
    __syncthreads();
    for (int off = 128; off > 0; off >>= 1) {
        if (d < off) sh[d] += sh[d + off];
        __syncthreads();
    }
    float nrm = sqrtf(sh[0]);
    float val = act / fmaxf(nrm, 1e-12f);
    __nv_bfloat16 hi = __float2bfloat16(val);
    __nv_bfloat16 lo = __float2bfloat16(val - __bfloat162float(hi));
    size_t base = (size_t)n * KTOT;
    outp[base + d] = hi;
    outp[base + DD + d] = lo;
    outp[base + 2 * DD + d] = hi;
    atomicAdd(&g_s[d], val);
}

// ---------------- shared tile constants -------------------
#define BKK 64
#define LDK 72            // 144B row stride: 8-row ldmatrix phase covers all 32 banks
#define KITERS (KTOT / BKK)   // 12
#define BUF_B (128 * LDK * 2) // 18432: 128-row buffer per stage
#define HMMA_SMEM (4 * BUF_B) // 73728 (sim)
#define BUF_B64 (64 * LDK * 2)                 // 9216: 64-row buffer per stage
#define GCN_SMEM (2 * BUF_B + 2 * BUF_B64)     // 55296 (gcn, N-tile 64)

// ---------------- bf16 HMMA sim GEMM + fused per-class max -------------------
__global__ __launch_bounds__(256) void sim_hmma_kernel(const __nv_bfloat16* __restrict__ Abf,
                                                       const __nv_bfloat16* __restrict__ Bbf,
                                                       unsigned long long* __restrict__ pack) {
    extern __shared__ __align__(16) char smem_raw[];

    const int tid = threadIdx.x;
    const int wid = tid >> 5;
    const int lane = tid & 31;
    const int bm = blockIdx.y * 128;
    const int bn = blockIdx.x * 128;

    const int wm = (wid & 3) * 32;   // warp m offset
    const int wn = (wid >> 2) * 64;  // warp n offset

    const uint32_t sA0 = smem_to_u32(smem_raw);
    const uint32_t sA1 = sA0 + BUF_B;
    const uint32_t sB0 = sA0 + 2 * BUF_B;
    const uint32_t sB1 = sA0 + 3 * BUF_B;

    float acc[2][8][4];
#pragma unroll
    for (int mt = 0; mt < 2; mt++)
#pragma unroll
        for (int nt = 0; nt < 8; nt++)
#pragma unroll
            for (int e = 0; e < 4; e++) acc[mt][nt][e] = 0.0f;

#define SIM_LOAD(dstA, dstB, k0) do {                                              \
        _Pragma("unroll")                                                          \
        for (int q = 0; q < 4; q++) {                                              \
            int chunk = tid + q * 256;                                             \
            int row = chunk >> 3;                                                  \
            int cs = chunk & 7;                                                    \
            uint32_t off = (uint32_t)(row * (LDK * 2) + cs * 16);                  \
            cp_async16((dstA) + off, &Abf[(size_t)(bm + row) * KTOT + (k0) + cs * 8]); \
            cp_async16((dstB) + off, &Bbf[(size_t)(bn + row) * KTOT + (k0) + cs * 8]); \
        }                                                                          \
    } while (0)

    SIM_LOAD(sA0, sB0, 0);
    cp_commit();

    for (int kb = 0; kb < KITERS; kb++) {
        cp_wait0();
        __syncthreads();
        if (kb + 1 < KITERS) {
            uint32_t dA = ((kb + 1) & 1) ? sA1 : sA0;
            uint32_t dB = ((kb + 1) & 1) ? sB1 : sB0;
            SIM_LOAD(dA, dB, (kb + 1) * BKK);
            cp_commit();
        }
        uint32_t aBase = (kb & 1) ? sA1 : sA0;
        uint32_t bBase = (kb & 1) ? sB1 : sB0;
#pragma unroll
        for (int ks = 0; ks < BKK; ks += 16) {
            uint32_t afr[2][4];
#pragma unroll
            for (int mt = 0; mt < 2; mt++) {
                int r = wm + mt * 16 + (lane & 15);
                int c = ks + 8 * (lane >> 4);
                ldm_x4(afr[mt][0], afr[mt][1], afr[mt][2], afr[mt][3],
                       aBase + (uint32_t)(r * LDK + c) * 2);
            }
            uint32_t bfr[8][2];
#pragma unroll
            for (int bt = 0; bt < 4; bt++) {
                int r = wn + bt * 16 + ((lane >> 4) & 1) * 8 + (lane & 7);
                int c = ks + ((lane >> 3) & 1) * 8;
                ldm_x4(bfr[bt * 2][0], bfr[bt * 2][1], bfr[bt * 2 + 1][0], bfr[bt * 2 + 1][1],
                       bBase + (uint32_t)(r * LDK + c) * 2);
            }
#pragma unroll
            for (int mt = 0; mt < 2; mt++)
#pragma unroll
                for (int nt = 0; nt < 8; nt++)
                    mma16816(acc[mt][nt], afr[mt], bfr[nt]);
        }
        __syncthreads();
    }
#undef SIM_LOAD

    // -------- fused epilogue: per-class (groups of PP cols) max + argmax --------
    {
        float* sst = (float*)smem_raw;   // 64 x 132 floats staging
        const int lwm = wm & 63;
        int c_lo = bn / PP;
        int c_hi = (bn + 127) / PP;
        if (c_hi > CC - 1) c_hi = CC - 1;
        const int r = tid >> 2;          // 0..63
        const int cstep0 = tid & 3;
#pragma unroll
        for (int half = 0; half < 2; half++) {
            __syncthreads();
            if ((wm < 64) == (half == 0)) {
#pragma unroll
                for (int mt = 0; mt < 2; mt++) {
                    int r0 = lwm + mt * 16 + (lane >> 2);
#pragma unroll
                    for (int nt = 0; nt < 8; nt++) {
                        int col = wn + nt * 8 + 2 * (lane & 3);
                        sst[r0 * 132 + col] = acc[mt][nt][0];
                        sst[r0 * 132 + col + 1] = acc[mt][nt][1];
                        sst[(r0 + 8) * 132 + col] = acc[mt][nt][2];
                        sst[(r0 + 8) * 132 + col + 1] = acc[mt][nt][3];
                    }
                }
            }
            __syncthreads();
            for (int c = c_lo + cstep0; c <= c_hi; c += 4) {
                int col0 = c * PP - bn;
                int lo = col0 > 0 ? col0 : 0;
                int hi = col0 + PP < 128 ? col0 + PP : 128;
                float best = -3.402823466e+38f;
                int bj = 0;
                for (int x = lo; x < hi; x++) {
                    float v = sst[r * 132 + x];
                    if (v > best) { best = v; bj = x - col0; }
                }
                unsigned long long pk =
                    ((unsigned long long)f2sortable(best) << 32) | (unsigned int)(15 - bj);
                unsigned long long* dst = &pack[(size_t)(bm + half * 64 + r) * CC + c];
                if (col0 >= 0 && col0 + PP <= 128) *dst = pk;   // interior: exclusive writer
                else atomicMax(dst, pk);                         // straddles tile boundary
            }
        }
    }
}

// ---------------- GCN HMMA GEMM (128x64 tile, full-chip grid): C[MPAD, DD] --------
__global__ __launch_bounds__(256) void gcn_hmma_kernel(const __nv_bfloat16* __restrict__ Abf,
                                                       const __nv_bfloat16* __restrict__ Bbf,
                                                       float* __restrict__ Cout) {
    extern __shared__ __align__(16) char smem_raw[];

    const int tid = threadIdx.x;
    const int wid = tid >> 5;
    const int lane = tid & 31;
    const int bm = blockIdx.y * 128;
    const int bn = blockIdx.x * 64;

    const int wm = (wid & 3) * 32;   // 4 warp rows
    const int wn = (wid >> 2) * 32;  // 2 warp cols x 32

    const uint32_t sA0 = smem_to_u32(smem_raw);
    const uint32_t sA1 = sA0 + BUF_B;
    const uint32_t sB0 = sA0 + 2 * BUF_B;
    const uint32_t sB1 = sB0 + BUF_B64;

    float acc[2][4][4];
#pragma unroll
    for (int mt = 0; mt < 2; mt++)
#pragma unroll
        for (int nt = 0; nt < 4; nt++)
#pragma unroll
            for (int e = 0; e < 4; e++) acc[mt][nt][e] = 0.0f;

#define GCN_LOAD(dstA, dstB, k0) do {                                              \
        _Pragma("unroll")                                                          \
        for (int q = 0; q < 4; q++) {                                              \
            int chunk = tid + q * 256;                                             \
            int row = chunk >> 3;                                                  \
            int cs = chunk & 7;                                                    \
            uint32_t off = (uint32_t)(row * (LDK * 2) + cs * 16);                  \
            cp_async16((dstA) + off, &Abf[(size_t)(bm + row) * KTOT + (k0) + cs * 8]); \
        }                                                                          \
        _Pragma("unroll")                                                          \
        for (int q = 0; q < 2; q++) {                                              \
            int chunk = tid + q * 256;                                             \
            int row = chunk >> 3;                                                  \
            int cs = chunk & 7;                                                    \
            uint32_t off = (uint32_t)(row * (LDK * 2) + cs * 16);                  \
            cp_async16((dstB) + off, &Bbf[(size_t)(bn + row) * KTOT + (k0) + cs * 8]); \
        }                                                                          \
    } while (0)

    GCN_LOAD(sA0, sB0, 0);
    cp_commit();

    for (int kb = 0; kb < KITERS; kb++) {
        cp_wait0();
        __syncthreads();
        if (kb + 1 < KITERS) {
            uint32_t dA = ((kb + 1) & 1) ? sA1 : sA0;
            uint32_t dB = ((kb + 1) & 1) ? sB1 : sB0;
            GCN_LOAD(dA, dB, (kb + 1) * BKK);
            cp_commit();
        }
        uint32_t aBase = (kb & 1) ? sA1 : sA0;
        uint32_t bBase = (kb & 1) ? sB1 : sB0;
#pragma unroll
        for (int ks = 0; ks < BKK; ks += 16) {
            uint32_t afr[2][4];
#pragma unroll
            for (int mt = 0; mt < 2; mt++) {
                int r = wm + mt * 16 + (lane & 15);
                int c = ks + 8 * (lane >> 4);
                ldm_x4(afr[mt][0], afr[mt][1], afr[mt][2], afr[mt][3],
                       aBase + (uint32_t)(r * LDK + c) * 2);
            }
            uint32_t bfr[4][2];
#pragma unroll
            for (int bt = 0; bt < 2; bt++) {
                int r = wn + bt * 16 + ((lane >> 4) & 1) * 8 + (lane & 7);
                int c = ks + ((lane >> 3) & 1) * 8;
                ldm_x4(bfr[bt * 2][0], bfr[bt * 2][1], bfr[bt * 2 + 1][0], bfr[bt * 2 + 1][1],
                       bBase + (uint32_t)(r * LDK + c) * 2);
            }
#pragma unroll
            for (int mt = 0; mt < 2; mt++)
#pragma unroll
                for (int nt = 0; nt < 4; nt++)
                    mma16816(acc[mt][nt], afr[mt], bfr[nt]);
        }
        __syncthreads();
    }
#undef GCN_LOAD

#pragma unroll
    for (int mt = 0; mt < 2; mt++) {
        int row0 = bm + wm + mt * 16 + (lane >> 2);
#pragma unroll
        for (int nt = 0; nt < 4; nt++) {
            int col = bn + wn + nt * 8 + 2 * (lane & 3);
            *(float2*)&Cout[(size_t)row0 * DD + col] =
                make_float2(acc[mt][nt][0], acc[mt][nt][1]);
            *(float2*)&Cout[(size_t)(row0 + 8) * DD + col] =
                make_float2(acc[mt][nt][2], acc[mt][nt][3]);
        }
    }
}

// ---------------- per-row CE + usage scatter (consumes packed) ----------------
__global__ void ce_kernel(const unsigned long long* __restrict__ pack,
                          float* __restrict__ out,
                          const int* __restrict__ labels,
                          float* __restrict__ usage_pos,
                          float* __restrict__ usage_neg) {
    int b = blockIdx.x;
    const unsigned long long* prow = pack + (size_t)b * CC;
    float* orow = out + (size_t)b * CC;
    int t = threadIdx.x;
    __shared__ float smax[256];
    __shared__ int simax[256];
    float bm = -1e30f;
    int bi = 0x7fffffff;
    for (int c = t; c < CC; c += 256) {
        unsigned long long pk = prow[c];
        float v = 0.5f * (1.0f + sortable2f((unsigned int)(pk >> 32)));
        orow[c] = v;
        if (v > bm) { bm = v; bi = c; }
    }
    smax[t] = bm; simax[t] = bi;
    __syncthreads();
    for (int off = 128; off > 0; off >>= 1) {
        if (t < off) {
            float v2 = smax[t + off];
            int i2 = simax[t + off];
            if (v2 > smax[t] || (v2 == smax[t] && i2 < simax[t])) {
                smax[t] = v2; simax[t] = i2;
            }
        }
        __syncthreads();
    }
    float rowmax = smax[0];
    int pred = simax[0];
    __shared__ float ssum[256];
    float s = 0.0f;
    for (int c = t; c < CC; c += 256) s += expf(orow[c] - rowmax);
    ssum[t] = s;
    __syncthreads();
    for (int off = 128; off > 0; off >>= 1) {
        if (t < off) ssum[t] += ssum[t + off];
        __syncthreads();
    }
    if (t == 0) {
        int lab = labels[b];
        float x_lab = orow[lab];
        float lse = rowmax + logf(ssum[0]);
        if ((x_lab - rowmax) > MARGIN_F) {
            atomicAdd(&g_ce_sum, lse - x_lab);
            atomicAdd(&g_cnt, 1);
        }
        int jl = 15 - (int)(unsigned int)(prow[lab] & 0xFFFFFFFFull);
        atomicAdd(&usage_pos[lab * PP + jl], 1.0f);
        if (pred != lab) {
            int jp = 15 - (int)(unsigned int)(prow[pred] & 0xFFFFFFFFull);
            atomicAdd(&usage_neg[pred * PP + jp], 1.0f);
        }
    }
}

// ---------------- finalize loss ----------------
__global__ void finalize_kernel(float* __restrict__ out_loss) {
    __shared__ float sh[DD];
    int t = threadIdx.x;
    float v = g_s[t];
    sh[t] = v * v;
    __syncthreads();
    for (int off = 128; off > 0; off >>= 1) {
        if (t < off) sh[t] += sh[t + off];
        __syncthreads();
    }
    if (t == 0) {
        float disp = -sh[0] / ((float)NN * (float)NN);
        int cnt = g_cnt;
        float loss = (cnt == 0) ? 0.0f
                                : (g_ce_sum / (float)(cnt > 1 ? cnt : 1) + LW_F * disp);
        out_loss[0] = loss;
    }
}

// ---------------- launch ----------------
extern "C" void kernel_launch(void* const* d_in, const int* in_sizes, int n_in,
                              void* d_out, int out_size) {
    const float* hidden = (const float*)d_in[0];
    const int* labels = (const int*)d_in[1];
    const int* edge_index = (const int*)d_in[2];
    const float* node_features = (const float*)d_in[3];
    const float* w1 = (const float*)d_in[4];
    const float* b1 = (const float*)d_in[5];
    const float* w2 = (const float*)d_in[6];
    const float* b2 = (const float*)d_in[7];
    float* out = (float*)d_out;

    float* out_loss = out + (size_t)BB * CC;
    float* out_pos = out_loss + 1;
    float* out_neg = out_pos + NN;

    float* p_bufA = 0;
    __nv_bfloat16 *p_xs = 0, *p_ws = 0, *p_Abf = 0, *p_Bbf = 0;
    unsigned long long* p_pack = 0;
    cudaGetSymbolAddress((void**)&p_bufA, g_bufA);
    cudaGetSymbolAddress((void**)&p_xs,   g_xs);
    cudaGetSymbolAddress((void**)&p_ws,   g_ws);
    cudaGetSymbolAddress((void**)&p_Abf,  g_Abf);
    cudaGetSymbolAddress((void**)&p_Bbf,  g_Bbf);
    cudaGetSymbolAddress((void**)&p_pack, g_pack);

    cudaFuncSetAttribute(sim_hmma_kernel, cudaFuncAttributeMaxDynamicSharedMemorySize, HMMA_SMEM);
    cudaFuncSetAttribute(gcn_hmma_kernel, cudaFuncAttributeMaxDynamicSharedMemorySize, GCN_SMEM);

    // graph build + compact boundary pack reset
    init_kernel<<<(BB * 64 + 255) / 256, 256>>>(out_loss);
    deg_kernel<<<(EE + 255) / 256, 256>>>(edge_index);
    scan_kernel<<<1, 1024>>>();   // scan + fused disqrt
    scatter_kernel<<<(EE + 255) / 256, 256>>>(edge_index);

    // GCN layer 1: split x, xw = x @ w1 (HMMA), agg+relu fused with layer-2 split
    split_x_kernel<<<NN, DD>>>(node_features, p_xs);
    split_w_kernel<<<DD, DD>>>(w1, p_ws);
    {
        dim3 grid(DD / 64, MPAD / 128);
        gcn_hmma_kernel<<<grid, 256, GCN_SMEM>>>(p_xs, p_ws, p_bufA);
    }
    agg_split_kernel<<<NN, DD>>>(p_bufA, p_xs, b1);   // layer-2 input split, in place

    // GCN layer 2: xw2 GEMM, then agg+relu+norm+split (protos) fused
    split_w_kernel<<<DD, DD>>>(w2, p_ws);
    {
        dim3 grid(DD / 64, MPAD / 128);
        gcn_hmma_kernel<<<grid, 256, GCN_SMEM>>>(p_xs, p_ws, p_bufA);
    }
    agg_norm_split_kernel<<<NN, DD>>>(p_bufA, p_Bbf, b2);  // protos [hi|lo|hi] + g_s

    // hidden normalize + split (A': [hi|hi|lo])
    norm_split_kernel<<<BB, DD>>>(hidden, p_Abf);

    // sim GEMM (BKK=64) with fused per-class max/argmax -> packed
    {
        dim3 grid(LDN / 128, BB / 128);
        sim_hmma_kernel<<<grid, 256, HMMA_SMEM>>>(p_Abf, p_Bbf, p_pack);
    }

    // CE + usage (decodes packed, writes output scores)
    ce_kernel<<<BB, 256>>>(p_pack, out, labels, out_pos, out_neg);

    // loss
    finalize_kernel<<<1, DD>>>(out_loss);
}

// round 17
// speedup vs baseline: 1.9809x; 1.0329x over previous
#include <cuda_runtime.h>
#include <cuda_bf16.h>
#include <math.h>
#include <stdint.h>

// Problem constants
#define BB 4096
#define CC 1000
#define PP 10
#define DD 256
#define NN 10000     // CC*PP
#define EE 160000
#define MARGIN_F (-0.1f)
#define LW_F (0.1f)

// bf16-split GEMM geometry
#define KTOT 768          // [hi | hi | lo] x [hi | lo | hi]
#define LDN 10112         // N padded to 79*128
#define MPAD 10112        // NN padded to 79*128

// ---------------- scratch (device globals; no runtime allocation) ----------------
__device__ float g_bufA[MPAD * DD];             // GEMM output scratch
__device__ __nv_bfloat16 g_xs[MPAD * KTOT];     // GCN input split (pad rows stay 0)
__device__ __nv_bfloat16 g_ws[DD * KTOT];       // w1 split (transposed)
__device__ __nv_bfloat16 g_ws2[DD * KTOT];      // w2 split (transposed)
__device__ __nv_bfloat16 g_Abf[BB * KTOT];      // hidden_norm split
__device__ __nv_bfloat16 g_Bbf[LDN * KTOT];     // proto_norm split (pad rows stay 0)
__device__ unsigned long long g_pack[(size_t)BB * CC]; // packed (sortable max, 15-idx)
__device__ float g_disqrt[NN];
__device__ int   g_deg[NN];
__device__ int   g_rowptr[NN + 1];
__device__ int   g_col[EE];
__device__ int   g_cursor[NN];
__device__ float g_s[DD];
__device__ float g_ce_sum;
__device__ int   g_cnt;

// boundary classes: c mod 64 in {12,25,38,51}
__constant__ int c_btbl[4] = {12, 25, 38, 51};

// ---------------- helpers ----------------
__device__ __forceinline__ uint32_t smem_to_u32(const void* p) {
    uint32_t a;
    asm("{ .reg .u64 t; cvta.to.shared.u64 t, %1; cvt.u32.u64 %0, t; }" : "=r"(a) : "l"(p));
    return a;
}
__device__ __forceinline__ void cp_async16(uint32_t dst, const void* src) {
    asm volatile("cp.async.cg.shared.global [%0], [%1], 16;" :: "r"(dst), "l"(src) : "memory");
}
__device__ __forceinline__ void cp_commit() {
    asm volatile("cp.async.commit_group;" ::: "memory");
}
__device__ __forceinline__ void cp_wait0() {
    asm volatile("cp.async.wait_group 0;" ::: "memory");
}
__device__ __forceinline__ void ldm_x4(uint32_t& r0, uint32_t& r1, uint32_t& r2, uint32_t& r3,
                                       uint32_t addr) {
    asm volatile("ldmatrix.sync.aligned.m8n8.x4.shared.b16 {%0,%1,%2,%3}, [%4];"
                 : "=r"(r0), "=r"(r1), "=r"(r2), "=r"(r3) : "r"(addr));
}
__device__ __forceinline__ void mma16816(float* d, const uint32_t* a, const uint32_t* b) {
    asm volatile(
        "mma.sync.aligned.m16n8k16.row.col.f32.bf16.bf16.f32 "
        "{%0,%1,%2,%3}, {%4,%5,%6,%7}, {%8,%9}, {%0,%1,%2,%3};"
        : "+f"(d[0]), "+f"(d[1]), "+f"(d[2]), "+f"(d[3])
        : "r"(a[0]), "r"(a[1]), "r"(a[2]), "r"(a[3]), "r"(b[0]), "r"(b[1]));
}
__device__ __forceinline__ unsigned int f2sortable(float f) {
    unsigned int b = __float_as_uint(f);
    return (b & 0x80000000u) ? ~b : (b | 0x80000000u);
}
__device__ __forceinline__ float sortable2f(unsigned int e) {
    unsigned int b = (e & 0x80000000u) ? (e ^ 0x80000000u) : ~e;
    return __uint_as_float(b);
}

// ---------------- init ----------------
__global__ void init_kernel(float* out_tail) {
    int i = blockIdx.x * blockDim.x + threadIdx.x;
    if (i < NN) { g_deg[i] = 0; g_cursor[i] = 0; }
    if (i < DD) g_s[i] = 0.0f;
    if (i == 0) { g_ce_sum = 0.0f; g_cnt = 0; }
    if (i < 1 + 2 * NN) out_tail[i] = 0.0f;
    if (i < BB * 64) {
        int b = i >> 6;
        int j = i & 63;
        int c = (j >> 2) * 64 + c_btbl[j & 3];
        if (c < CC) g_pack[(size_t)b * CC + c] = 0ull;
    }
}

// ---------------- degree ----------------
__global__ void deg_kernel(const int* __restrict__ ei) {
    int e = blockIdx.x * blockDim.x + threadIdx.x;
    if (e < EE) atomicAdd(&g_deg[ei[EE + e]], 1);
}

// ---------------- exclusive scan (shfl-based) + fused disqrt ----------------
__global__ void scan_kernel() {
    const int T = 1024;
    const int CH = (NN + T - 1) / T;   // 10
    __shared__ int wsum[32];
    int t = threadIdx.x;
    int lane = t & 31, w = t >> 5;
    int base = t * CH;
    int local[CH];
    int s = 0;
#pragma unroll
    for (int i = 0; i < CH; i++) {
        int idx = base + i;
        local[i] = (idx < NN) ? g_deg[idx] : 0;
        s += local[i];
    }
    int v = s;
#pragma unroll
    for (int off = 1; off < 32; off <<= 1) {
        int u = __shfl_up_sync(0xFFFFFFFFu, v, off);
        if (lane >= off) v += u;
    }
    if (lane == 31) wsum[w] = v;
    __syncthreads();
    if (w == 0) {
        int x = wsum[lane];
#pragma unroll
        for (int off = 1; off < 32; off <<= 1) {
            int u = __shfl_up_sync(0xFFFFFFFFu, x, off);
            if (lane >= off) x += u;
        }
        wsum[lane] = x;
    }
    __syncthreads();
    int run = v - s + (w > 0 ? wsum[w - 1] : 0);
#pragma unroll
    for (int i = 0; i < CH; i++) {
        int idx = base + i;
        if (idx < NN) { g_rowptr[idx] = run; run += local[i]; }
    }
    if (t == T - 1) g_rowptr[NN] = run;
    for (int n = t; n < NN; n += T) {
        float x = (float)(g_deg[n] + 1);
        float r = rsqrtf(x);
        r = r * (1.5f - 0.5f * x * r * r);
        g_disqrt[n] = r;
    }
}

__global__ void scatter_kernel(const int* __restrict__ ei) {
    int e = blockIdx.x * blockDim.x + threadIdx.x;
    if (e < EE) {
        int d = ei[EE + e];
        int pos = g_rowptr[d] + atomicAdd(&g_cursor[d], 1);
        g_col[pos] = ei[e];
    }
}

// ---------------- bf16 split kernels ----------------
__global__ void split_x_kernel(const float* __restrict__ in, __nv_bfloat16* __restrict__ outp) {
    int r = blockIdx.x;
    int t = threadIdx.x;
    float v = in[(size_t)r * DD + t];
    __nv_bfloat16 hi = __float2bfloat16(v);
    __nv_bfloat16 lo = __float2bfloat16(v - __bfloat162float(hi));
    size_t base = (size_t)r * KTOT;
    outp[base + t] = hi;
    outp[base + DD + t] = hi;
    outp[base + 2 * DD + t] = lo;
}

__global__ void split_w_kernel(const float* __restrict__ w, __nv_bfloat16* __restrict__ outp) {
    int n = blockIdx.x;   // output col
    int k = threadIdx.x;  // input dim
    float v = w[(size_t)k * DD + n];
    __nv_bfloat16 hi = __float2bfloat16(v);
    __nv_bfloat16 lo = __float2bfloat16(v - __bfloat162float(hi));
    size_t base = (size_t)n * KTOT;
    outp[base + k] = hi;
    outp[base + DD + k] = lo;
    outp[base + 2 * DD + k] = hi;
}

// ---------------- row L2 normalize + bf16 split (hidden -> A': [hi|hi|lo]) --------
__global__ void norm_split_kernel(const float* __restrict__ in,
                                  __nv_bfloat16* __restrict__ outp) {
    int r = blockIdx.x;
    int t = threadIdx.x;
    float v = in[(size_t)r * DD + t];
    __shared__ float sh[DD];
    sh[t] = v * v;
    __syncthreads();
    for (int off = 128; off > 0; off >>= 1) {
        if (t < off) sh[t] += sh[t + off];
        __syncthreads();
    }
    float nrm = sqrtf(sh[0]);
    float val = v / fmaxf(nrm, 1e-12f);
    __nv_bfloat16 hi = __float2bfloat16(val);
    __nv_bfloat16 lo = __float2bfloat16(val - __bfloat162float(hi));
    size_t base = (size_t)r * KTOT;
    outp[base + t] = hi;
    outp[base + DD + t] = hi;
    outp[base + 2 * DD + t] = lo;
}

// ---------------- GCN agg + bias + relu, fused bf16 split ([hi|hi|lo]) ------------
__global__ void agg_split_kernel(const float* __restrict__ xw,
                                 __nv_bfloat16* __restrict__ outp,
                                 const float* __restrict__ bias) {
    int n = blockIdx.x;
    int d = threadIdx.x;
    float dn = g_disqrt[n];
    float acc = dn * dn * xw[(size_t)n * DD + d];
    int beg = g_rowptr[n], end = g_rowptr[n + 1];
    for (int j = beg; j < end; j++) {
        int s = g_col[j];
        acc += dn * g_disqrt[s] * xw[(size_t)s * DD + d];
    }
    float act = fmaxf(acc + bias[d], 0.0f);
    __nv_bfloat16 hi = __float2bfloat16(act);
    __nv_bfloat16 lo = __float2bfloat16(act - __bfloat162float(hi));
    size_t base = (size_t)n * KTOT;
    outp[base + d] = hi;
    outp[base + DD + d] = hi;
    outp[base + 2 * DD + d] = lo;
}

// ---------------- GCN agg + bias + relu + L2 norm + split (protos: [hi|lo|hi]) ----
__global__ void agg_norm_split_kernel(const float* __restrict__ xw,
                                      __nv_bfloat16* __restrict__ outp,
                                      const float* __restrict__ bias) {
    int n = blockIdx.x;
    int d = threadIdx.x;
    float dn = g_disqrt[n];
    float acc = dn * dn * xw[(size_t)n * DD + d];
    int beg = g_rowptr[n], end = g_rowptr[n + 1];
    for (int j = beg; j < end; j++) {
        int s = g_col[j];
        acc += dn * g_disqrt[s] * xw[(size_t)s * DD + d];
    }
    float act = fmaxf(acc + bias[d], 0.0f);
    __shared__ float sh[DD];
    sh[d] = act * act;
    __syncthreads();
    for (int off = 128; off > 0; off >>= 1) {
        if (d < off) sh[d] += sh[d + off];
        __syncthreads();
    }
    float nrm = sqrtf(sh[0]);
    float val = act / fmaxf(nrm, 1e-12f);
    __nv_bfloat16 hi = __float2bfloat16(val);
    __nv_bfloat16 lo = __float2bfloat16(val - __bfloat162float(hi));
    size_t base = (size_t)n * KTOT;
    outp[base + d] = hi;
    outp[base + DD + d] = lo;
    outp[base + 2 * DD + d] = hi;
    atomicAdd(&g_s[d], val);
}

// ---------------- shared tile constants -------------------
#define BKK 64
#define LDK 72            // 144B row stride: 8-row ldmatrix phase covers all 32 banks
#define KITERS (KTOT / BKK)   // 12
#define BUF_B (128 * LDK * 2) // 18432: 128-row buffer per stage
#define HMMA_SMEM (4 * BUF_B) // 73728 (sim)
#define BUF_B64 (64 * LDK * 2)                 // 9216: 64-row buffer per stage
#define GCN_SMEM (2 * BUF_B + 2 * BUF_B64)     // 55296 (gcn, N-tile 64)

// ---------------- bf16 HMMA sim GEMM + fused per-class max -------------------
__global__ __launch_bounds__(256) void sim_hmma_kernel(const __nv_bfloat16* __restrict__ Abf,
                                                       const __nv_bfloat16* __restrict__ Bbf,
                                                       unsigned long long* __restrict__ pack) {
    extern __shared__ __align__(16) char smem_raw[];

    const int tid = threadIdx.x;
    const int wid = tid >> 5;
    const int lane = tid & 31;
    const int bm = blockIdx.y * 128;
    const int bn = blockIdx.x * 128;

    const int wm = (wid & 3) * 32;   // warp m offset
    const int wn = (wid >> 2) * 64;  // warp n offset

    const uint32_t sA0 = smem_to_u32(smem_raw);
    const uint32_t sA1 = sA0 + BUF_B;
    const uint32_t sB0 = sA0 + 2 * BUF_B;
    const uint32_t sB1 = sA0 + 3 * BUF_B;

    float acc[2][8][4];
#pragma unroll
    for (int mt = 0; mt < 2; mt++)
#pragma unroll
        for (int nt = 0; nt < 8; nt++)
#pragma unroll
            for (int e = 0; e < 4; e++) acc[mt][nt][e] = 0.0f;

#define SIM_LOAD(dstA, dstB, k0) do {                                              \
        _Pragma("unroll")                                                          \
        for (int q = 0; q < 4; q++) {                                              \
            int chunk = tid + q * 256;                                             \
            int row = chunk >> 3;                                                  \
            int cs = chunk & 7;                                                    \
            uint32_t off = (uint32_t)(row * (LDK * 2) + cs * 16);                  \
            cp_async16((dstA) + off, &Abf[(size_t)(bm + row) * KTOT + (k0) + cs * 8]); \
            cp_async16((dstB) + off, &Bbf[(size_t)(bn + row) * KTOT + (k0) + cs * 8]); \
        }                                                                          \
    } while (0)

    SIM_LOAD(sA0, sB0, 0);
    cp_commit();

    for (int kb = 0; kb < KITERS; kb++) {
        cp_wait0();
        __syncthreads();
        if (kb + 1 < KITERS) {
            uint32_t dA = ((kb + 1) & 1) ? sA1 : sA0;
            uint32_t dB = ((kb + 1) & 1) ? sB1 : sB0;
            SIM_LOAD(dA, dB, (kb + 1) * BKK);
            cp_commit();
        }
        uint32_t aBase = (kb & 1) ? sA1 : sA0;
        uint32_t bBase = (kb & 1) ? sB1 : sB0;
#pragma unroll
        for (int ks = 0; ks < BKK; ks += 16) {
            uint32_t afr[2][4];
#pragma unroll
            for (int mt = 0; mt < 2; mt++) {
                int r = wm + mt * 16 + (lane & 15);
                int c = ks + 8 * (lane >> 4);
                ldm_x4(afr[mt][0], afr[mt][1], afr[mt][2], afr[mt][3],
                       aBase + (uint32_t)(r * LDK + c) * 2);
            }
            uint32_t bfr[8][2];
#pragma unroll
            for (int bt = 0; bt < 4; bt++) {
                int r = wn + bt * 16 + ((lane >> 4) & 1) * 8 + (lane & 7);
                int c = ks + ((lane >> 3) & 1) * 8;
                ldm_x4(bfr[bt * 2][0], bfr[bt * 2][1], bfr[bt * 2 + 1][0], bfr[bt * 2 + 1][1],
                       bBase + (uint32_t)(r * LDK + c) * 2);
            }
#pragma unroll
            for (int mt = 0; mt < 2; mt++)
#pragma unroll
                for (int nt = 0; nt < 8; nt++)
                    mma16816(acc[mt][nt], afr[mt], bfr[nt]);
        }
        __syncthreads();
    }
#undef SIM_LOAD

    // -------- fused epilogue: per-class (groups of PP cols) max + argmax --------
    {
        float* sst = (float*)smem_raw;   // 64 x 132 floats staging
        const int lwm = wm & 63;
        int c_lo = bn / PP;
        int c_hi = (bn + 127) / PP;
        if (c_hi > CC - 1) c_hi = CC - 1;
        const int r = tid >> 2;          // 0..63
        const int cstep0 = tid & 3;
#pragma unroll
        for (int half = 0; half < 2; half++) {
            __syncthreads();
            if ((wm < 64) == (half == 0)) {
#pragma unroll
                for (int mt = 0; mt < 2; mt++) {
                    int r0 = lwm + mt * 16 + (lane >> 2);
#pragma unroll
                    for (int nt = 0; nt < 8; nt++) {
                        int col = wn + nt * 8 + 2 * (lane & 3);
                        sst[r0 * 132 + col] = acc[mt][nt][0];
                        sst[r0 * 132 + col + 1] = acc[mt][nt][1];
                        sst[(r0 + 8) * 132 + col] = acc[mt][nt][2];
                        sst[(r0 + 8) * 132 + col + 1] = acc[mt][nt][3];
                    }
                }
            }
            __syncthreads();
            for (int c = c_lo + cstep0; c <= c_hi; c += 4) {
                int col0 = c * PP - bn;
                int lo = col0 > 0 ? col0 : 0;
                int hi = col0 + PP < 128 ? col0 + PP : 128;
                float best = -3.402823466e+38f;
                int bj = 0;
                for (int x = lo; x < hi; x++) {
                    float v = sst[r * 132 + x];
                    if (v > best) { best = v; bj = x - col0; }
                }
                unsigned long long pk =
                    ((unsigned long long)f2sortable(best) << 32) | (unsigned int)(15 - bj);
                unsigned long long* dst = &pack[(size_t)(bm + half * 64 + r) * CC + c];
                if (col0 >= 0 && col0 + PP <= 128) *dst = pk;   // interior: exclusive writer
                else atomicMax(dst, pk);                         // straddles tile boundary
            }
        }
    }
}

// ---------------- GCN HMMA GEMM (128x64 tile, full-chip grid): C[MPAD, DD] --------
__global__ __launch_bounds__(256) void gcn_hmma_kernel(const __nv_bfloat16* __restrict__ Abf,
                                                       const __nv_bfloat16* __restrict__ Bbf,
                                                       float* __restrict__ Cout) {
    extern __shared__ __align__(16) char smem_raw[];

    const int tid = threadIdx.x;
    const int wid = tid >> 5;
    const int lane = tid & 31;
    const int bm = blockIdx.y * 128;
    const int bn = blockIdx.x * 64;

    const int wm = (wid & 3) * 32;   // 4 warp rows
    const int wn = (wid >> 2) * 32;  // 2 warp cols x 32

    const uint32_t sA0 = smem_to_u32(smem_raw);
    const uint32_t sA1 = sA0 + BUF_B;
    const uint32_t sB0 = sA0 + 2 * BUF_B;
    const uint32_t sB1 = sB0 + BUF_B64;

    float acc[2][4][4];
#pragma unroll
    for (int mt = 0; mt < 2; mt++)
#pragma unroll
        for (int nt = 0; nt < 4; nt++)
#pragma unroll
            for (int e = 0; e < 4; e++) acc[mt][nt][e] = 0.0f;

#define GCN_LOAD(dstA, dstB, k0) do {                                              \
        _Pragma("unroll")                                                          \
        for (int q = 0; q < 4; q++) {                                              \
            int chunk = tid + q * 256;                                             \
            int row = chunk >> 3;                                                  \
            int cs = chunk & 7;                                                    \
            uint32_t off = (uint32_t)(row * (LDK * 2) + cs * 16);                  \
            cp_async16((dstA) + off, &Abf[(size_t)(bm + row) * KTOT + (k0) + cs * 8]); \
        }                                                                          \
        _Pragma("unroll")                                                          \
        for (int q = 0; q < 2; q++) {                                              \
            int chunk = tid + q * 256;                                             \
            int row = chunk >> 3;                                                  \
            int cs = chunk & 7;                                                    \
            uint32_t off = (uint32_t)(row * (LDK * 2) + cs * 16);                  \
            cp_async16((dstB) + off, &Bbf[(size_t)(bn + row) * KTOT + (k0) + cs * 8]); \
        }                                                                          \
    } while (0)

    GCN_LOAD(sA0, sB0, 0);
    cp_commit();

    for (int kb = 0; kb < KITERS; kb++) {
        cp_wait0();
        __syncthreads();
        if (kb + 1 < KITERS) {
            uint32_t dA = ((kb + 1) & 1) ? sA1 : sA0;
            uint32_t dB = ((kb + 1) & 1) ? sB1 : sB0;
            GCN_LOAD(dA, dB, (kb + 1) * BKK);
            cp_commit();
        }
        uint32_t aBase = (kb & 1) ? sA1 : sA0;
        uint32_t bBase = (kb & 1) ? sB1 : sB0;
#pragma unroll
        for (int ks = 0; ks < BKK; ks += 16) {
            uint32_t afr[2][4];
#pragma unroll
            for (int mt = 0; mt < 2; mt++) {
                int r = wm + mt * 16 + (lane & 15);
                int c = ks + 8 * (lane >> 4);
                ldm_x4(afr[mt][0], afr[mt][1], afr[mt][2], afr[mt][3],
                       aBase + (uint32_t)(r * LDK + c) * 2);
            }
            uint32_t bfr[4][2];
#pragma unroll
            for (int bt = 0; bt < 2; bt++) {
                int r = wn + bt * 16 + ((lane >> 4) & 1) * 8 + (lane & 7);
                int c = ks + ((lane >> 3) & 1) * 8;
                ldm_x4(bfr[bt * 2][0], bfr[bt * 2][1], bfr[bt * 2 + 1][0], bfr[bt * 2 + 1][1],
                       bBase + (uint32_t)(r * LDK + c) * 2);
            }
#pragma unroll
            for (int mt = 0; mt < 2; mt++)
#pragma unroll
                for (int nt = 0; nt < 4; nt++)
                    mma16816(acc[mt][nt], afr[mt], bfr[nt]);
        }
        __syncthreads();
    }
#undef GCN_LOAD

#pragma unroll
    for (int mt = 0; mt < 2; mt++) {
        int row0 = bm + wm + mt * 16 + (lane >> 2);
#pragma unroll
        for (int nt = 0; nt < 4; nt++) {
            int col = bn + wn + nt * 8 + 2 * (lane & 3);
            *(float2*)&Cout[(size_t)row0 * DD + col] =
                make_float2(acc[mt][nt][0], acc[mt][nt][1]);
            *(float2*)&Cout[(size_t)(row0 + 8) * DD + col] =
                make_float2(acc[mt][nt][2], acc[mt][nt][3]);
        }
    }
}

// ---------------- per-row CE + usage scatter (consumes packed) ----------------
__global__ void ce_kernel(const unsigned long long* __restrict__ pack,
                          float* __restrict__ out,
                          const int* __restrict__ labels,
                          float* __restrict__ usage_pos,
                          float* __restrict__ usage_neg) {
    int b = blockIdx.x;
    const unsigned long long* prow = pack + (size_t)b * CC;
    float* orow = out + (size_t)b * CC;
    int t = threadIdx.x;
    __shared__ float smax[256];
    __shared__ int simax[256];
    float bm = -1e30f;
    int bi = 0x7fffffff;
    for (int c = t; c < CC; c += 256) {
        unsigned long long pk = prow[c];
        float v = 0.5f * (1.0f + sortable2f((unsigned int)(pk >> 32)));
        orow[c] = v;
        if (v > bm) { bm = v; bi = c; }
    }
    smax[t] = bm; simax[t] = bi;
    __syncthreads();
    for (int off = 128; off > 0; off >>= 1) {
        if (t < off) {
            float v2 = smax[t + off];
            int i2 = simax[t + off];
            if (v2 > smax[t] || (v2 == smax[t] && i2 < simax[t])) {
                smax[t] = v2; simax[t] = i2;
            }
        }
        __syncthreads();
    }
    float rowmax = smax[0];
    int pred = simax[0];
    __shared__ float ssum[256];
    float s = 0.0f;
    for (int c = t; c < CC; c += 256) s += expf(orow[c] - rowmax);
    ssum[t] = s;
    __syncthreads();
    for (int off = 128; off > 0; off >>= 1) {
        if (t < off) ssum[t] += ssum[t + off];
        __syncthreads();
    }
    if (t == 0) {
        int lab = labels[b];
        float x_lab = orow[lab];
        float lse = rowmax + logf(ssum[0]);
        if ((x_lab - rowmax) > MARGIN_F) {
            atomicAdd(&g_ce_sum, lse - x_lab);
            atomicAdd(&g_cnt, 1);
        }
        int jl = 15 - (int)(unsigned int)(prow[lab] & 0xFFFFFFFFull);
        atomicAdd(&usage_pos[lab * PP + jl], 1.0f);
        if (pred != lab) {
            int jp = 15 - (int)(unsigned int)(prow[pred] & 0xFFFFFFFFull);
            atomicAdd(&usage_neg[pred * PP + jp], 1.0f);
        }
    }
}

// ---------------- finalize loss ----------------
__global__ void finalize_kernel(float* __restrict__ out_loss) {
    __shared__ float sh[DD];
    int t = threadIdx.x;
    float v = g_s[t];
    sh[t] = v * v;
    __syncthreads();
    for (int off = 128; off > 0; off >>= 1) {
        if (t < off) sh[t] += sh[t + off];
        __syncthreads();
    }
    if (t == 0) {
        float disp = -sh[0] / ((float)NN * (float)NN);
        int cnt = g_cnt;
        float loss = (cnt == 0) ? 0.0f
                                : (g_ce_sum / (float)(cnt > 1 ? cnt : 1) + LW_F * disp);
        out_loss[0] = loss;
    }
}

// ---------------- launch ----------------
extern "C" void kernel_launch(void* const* d_in, const int* in_sizes, int n_in,
                              void* d_out, int out_size) {
    const float* hidden = (const float*)d_in[0];
    const int* labels = (const int*)d_in[1];
    const int* edge_index = (const int*)d_in[2];
    const float* node_features = (const float*)d_in[3];
    const float* w1 = (const float*)d_in[4];
    const float* b1 = (const float*)d_in[5];
    const float* w2 = (const float*)d_in[6];
    const float* b2 = (const float*)d_in[7];
    float* out = (float*)d_out;

    float* out_loss = out + (size_t)BB * CC;
    float* out_pos = out_loss + 1;
    float* out_neg = out_pos + NN;

    float* p_bufA = 0;
    __nv_bfloat16 *p_xs = 0, *p_ws = 0, *p_ws2 = 0, *p_Abf = 0, *p_Bbf = 0;
    unsigned long long* p_pack = 0;
    cudaGetSymbolAddress((void**)&p_bufA, g_bufA);
    cudaGetSymbolAddress((void**)&p_xs,   g_xs);
    cudaGetSymbolAddress((void**)&p_ws,   g_ws);
    cudaGetSymbolAddress((void**)&p_ws2,  g_ws2);
    cudaGetSymbolAddress((void**)&p_Abf,  g_Abf);
    cudaGetSymbolAddress((void**)&p_Bbf,  g_Bbf);
    cudaGetSymbolAddress((void**)&p_pack, g_pack);

    cudaFuncSetAttribute(sim_hmma_kernel, cudaFuncAttributeMaxDynamicSharedMemorySize, HMMA_SMEM);
    cudaFuncSetAttribute(gcn_hmma_kernel, cudaFuncAttributeMaxDynamicSharedMemorySize, GCN_SMEM);

    // side stream + fork/join events (driver objects only; no device allocation;
    // created fresh each call -> deterministic; capture ends after return so they
    // are intentionally not destroyed here)
    cudaStream_t s1;
    cudaStreamCreateWithFlags(&s1, cudaStreamNonBlocking);
    cudaEvent_t eFork, eJoin;
    cudaEventCreateWithFlags(&eFork, cudaEventDisableTiming);
    cudaEventCreateWithFlags(&eJoin, cudaEventDisableTiming);

    // fork: s1 branches off the (captured) main stream
    cudaEventRecord(eFork, 0);
    cudaStreamWaitEvent(s1, eFork, 0);

    // ---- side chain (independent of adjacency build) ----
    split_x_kernel<<<NN, DD, 0, s1>>>(node_features, p_xs);
    split_w_kernel<<<DD, DD, 0, s1>>>(w1, p_ws);
    {
        dim3 grid(DD / 64, MPAD / 128);
        gcn_hmma_kernel<<<grid, 256, GCN_SMEM, s1>>>(p_xs, p_ws, p_bufA);
    }
    split_w_kernel<<<DD, DD, 0, s1>>>(w2, p_ws2);
    norm_split_kernel<<<BB, DD, 0, s1>>>(hidden, p_Abf);
    cudaEventRecord(eJoin, s1);

    // ---- main chain: graph build + compact boundary pack reset ----
    init_kernel<<<(BB * 64 + 255) / 256, 256>>>(out_loss);
    deg_kernel<<<(EE + 255) / 256, 256>>>(edge_index);
    scan_kernel<<<1, 1024>>>();   // scan + fused disqrt
    scatter_kernel<<<(EE + 255) / 256, 256>>>(edge_index);

    // join: everything below needs both chains
    cudaStreamWaitEvent(0, eJoin, 0);

    // GCN layer 1 aggregation (+ layer-2 input split, in place)
    agg_split_kernel<<<NN, DD>>>(p_bufA, p_xs, b1);

    // GCN layer 2: xw2 GEMM, then agg+relu+norm+split (protos) fused
    {
        dim3 grid(DD / 64, MPAD / 128);
        gcn_hmma_kernel<<<grid, 256, GCN_SMEM>>>(p_xs, p_ws2, p_bufA);
    }
    agg_norm_split_kernel<<<NN, DD>>>(p_bufA, p_Bbf, b2);  // protos [hi|lo|hi] + g_s

    // sim GEMM (BKK=64) with fused per-class max/argmax -> packed
    {
        dim3 grid(LDN / 128, BB / 128);
        sim_hmma_kernel<<<grid, 256, HMMA_SMEM>>>(p_Abf, p_Bbf, p_pack);
    }

    // CE + usage (decodes packed, writes output scores)
    ce_kernel<<<BB, 256>>>(p_pack, out, labels, out_pos, out_neg);

    // loss
    finalize_kernel<<<1, DD>>>(out_loss);
}